// round 12
// baseline (speedup 1.0000x reference)
#include <cuda_runtime.h>
#include <cstdint>

// ----------------------------------------------------------------------------
// Problem constants
// ----------------------------------------------------------------------------
constexpr int B_  = 8;
constexpr int N_  = 1024;
constexpr int D_  = 256;
constexpr int H_  = 8;
constexpr int DK_ = 32;
constexpr int FF_ = 1024;
constexpr int L_  = 4;
constexpr int ROWS = B_ * N_;          // 8192 token rows

// ----------------------------------------------------------------------------
// Scratch (device globals: no allocation allowed)
// ----------------------------------------------------------------------------
__device__ float g_Q  [ROWS * D_];
__device__ float g_ATT[ROWS * D_];
__device__ float g_X  [ROWS * D_];
__device__ float g_Hb [ROWS * FF_];
// Attention staging buffers in mma-fragment-tiled layout.
__device__ __align__(16) float g_Kaug[64 * 8 * 5120];
__device__ __align__(16) float g_Vaug[64 * 8 * 4096];

// ----------------------------------------------------------------------------
// Helpers
// ----------------------------------------------------------------------------
__device__ __forceinline__ uint32_t smem_u32(const void* p) {
    return (uint32_t)__cvta_generic_to_shared(p);
}
__device__ __forceinline__ void cp16(uint32_t s, const void* g) {
    asm volatile("cp.async.cg.shared.global [%0], [%1], 16;" :: "r"(s), "l"(g));
}
__device__ __forceinline__ void cp_commit() {
    asm volatile("cp.async.commit_group;" ::: "memory");
}
template <int NN>
__device__ __forceinline__ void cp_wait() {
    asm volatile("cp.async.wait_group %0;" :: "n"(NN) : "memory");
}
__device__ __forceinline__ void mma_tf32(float* c, const uint32_t* a, const uint32_t* b) {
    asm volatile(
        "mma.sync.aligned.m16n8k8.row.col.f32.tf32.tf32.f32 "
        "{%0,%1,%2,%3},{%4,%5,%6,%7},{%8,%9},{%0,%1,%2,%3};"
        : "+f"(c[0]), "+f"(c[1]), "+f"(c[2]), "+f"(c[3])
        : "r"(a[0]), "r"(a[1]), "r"(a[2]), "r"(a[3]), "r"(b[0]), "r"(b[1]));
}

// ----------------------------------------------------------------------------
// tf32 MMA GEMM core (128x128 tile): 3-stage cp.async pipeline.
// ----------------------------------------------------------------------------
constexpr int A_TILE_U32 = 128 * 32;
constexpr int B_TILE_U32 = 32 * 136;
constexpr int STAGE_U32  = A_TILE_U32 + B_TILE_U32;            // 8448
constexpr int GEMM_SMEM  = 3 * STAGE_U32 * 4;                  // 101376 bytes

__device__ __forceinline__ void gemm_accum(const float* __restrict__ A,
                                           const float* __restrict__ Bw,
                                           int Nn, int Kk,
                                           float acc[2][8][4])
{
    extern __shared__ uint32_t sm[];

    const int tid  = threadIdx.x;
    const int lane = tid & 31;
    const int warp = tid >> 5;
    const int gid  = lane >> 2;
    const int tig  = lane & 3;
    const int wm   = warp & 3;
    const int wn   = warp >> 2;

    const int rowBase = blockIdx.y * 128;
    const int colBase = blockIdx.x * 128;

    int aR[4], aS[4], bR[4], bS[4], aC4[4], bC4[4];
#pragma unroll
    for (int i = 0; i < 4; i++) {
        int idx = tid + i * 256;
        int r  = idx >> 3;
        int c4 = (idx & 7) << 2;
        aR[i] = r; aS[i] = r * 32 + (c4 ^ ((r & 7) << 2)); aC4[i] = c4;
        int rb  = idx >> 5;
        int cb4 = (idx & 31) << 2;
        bR[i] = rb; bS[i] = rb * 136 + cb4; bC4[i] = cb4;
    }

    auto issue = [&](int t, int buf) {
        const int k0 = t * 32;
        uint32_t* As = sm + buf * STAGE_U32;
        uint32_t* Bs = As + A_TILE_U32;
#pragma unroll
        for (int i = 0; i < 4; i++)
            cp16(smem_u32(&As[aS[i]]),
                 &A[(size_t)(rowBase + aR[i]) * Kk + k0 + aC4[i]]);
#pragma unroll
        for (int i = 0; i < 4; i++)
            cp16(smem_u32(&Bs[bS[i]]),
                 &Bw[(size_t)(k0 + bR[i]) * Nn + colBase + bC4[i]]);
        cp_commit();
    };

#pragma unroll
    for (int mt = 0; mt < 2; mt++)
#pragma unroll
        for (int nt = 0; nt < 8; nt++)
#pragma unroll
            for (int j = 0; j < 4; j++) acc[mt][nt][j] = 0.0f;

    const int T = Kk >> 5;
    issue(0, 0);
    issue(1, 1);

    int buf = 0;
    for (int t = 0; t < T; t++) {
        if (t + 1 < T) cp_wait<1>(); else cp_wait<0>();
        __syncthreads();

        const uint32_t* Ab = sm + buf * STAGE_U32;
        const uint32_t* Bb = Ab + A_TILE_U32;

#pragma unroll
        for (int kk = 0; kk < 32; kk += 8) {
            uint32_t a[2][4];
#pragma unroll
            for (int mt = 0; mt < 2; mt++) {
                const int m  = wm * 32 + mt * 16 + gid;
                const int sw = (m & 7) << 2;
                const int b0 = m * 32;
                const int b1 = b0 + 8 * 32;
                a[mt][0] = Ab[b0 + (kk ^ sw) + tig];
                a[mt][1] = Ab[b1 + (kk ^ sw) + tig];
                a[mt][2] = Ab[b0 + ((kk + 4) ^ sw) + tig];
                a[mt][3] = Ab[b1 + ((kk + 4) ^ sw) + tig];
            }
            uint32_t b[8][2];
#pragma unroll
            for (int nt = 0; nt < 8; nt++) {
                const int n = wn * 64 + nt * 8 + gid;
                b[nt][0] = Bb[(kk + tig) * 136 + n];
                b[nt][1] = Bb[(kk + tig + 4) * 136 + n];
            }
#pragma unroll
            for (int mt = 0; mt < 2; mt++)
#pragma unroll
                for (int nt = 0; nt < 8; nt++)
                    mma_tf32(acc[mt][nt], a[mt], b[nt]);
        }

        if (t + 2 < T) {
            int nbuf = buf + 2; if (nbuf >= 3) nbuf -= 3;
            issue(t + 2, nbuf);
        }
        if (++buf == 3) buf = 0;
    }
}

// ----------------------------------------------------------------------------
// QKV kernel. z=0: Q plain. z=1: K -> Kaug fragment-tiled. z=2: V -> Vaug.
// ----------------------------------------------------------------------------
__global__ __launch_bounds__(256, 2)
void qkv_kernel(const float* __restrict__ A,
                const float* __restrict__ Wq, const float* __restrict__ Wk,
                const float* __restrict__ Wv,
                const float* __restrict__ bq, const float* __restrict__ bk,
                const float* __restrict__ bv,
                float* __restrict__ Qo, float* __restrict__ Kaug,
                float* __restrict__ Vaug)
{
    const float* Bw; const float* bias;
    if (blockIdx.z == 0)      { Bw = Wq; bias = bq; }
    else if (blockIdx.z == 1) { Bw = Wk; bias = bk; }
    else                      { Bw = Wv; bias = bv; }

    float acc[2][8][4];
    gemm_accum(A, Bw, D_, D_, acc);

    const int lane = threadIdx.x & 31;
    const int warp = threadIdx.x >> 5;
    const int gid  = lane >> 2;
    const int tig  = lane & 3;
    const int wm   = warp & 3;
    const int wn   = warp >> 2;
    const int rowBase = blockIdx.y * 128;
    const int colBase = blockIdx.x * 128;

    if (blockIdx.z == 0) {
#pragma unroll
        for (int mt = 0; mt < 2; mt++) {
            const int row0 = rowBase + wm * 32 + mt * 16 + gid;
            const int row1 = row0 + 8;
#pragma unroll
            for (int nt = 0; nt < 8; nt++) {
                const int col = colBase + wn * 64 + nt * 8 + 2 * tig;
                float2 bb = *reinterpret_cast<const float2*>(&bias[col]);
                *reinterpret_cast<float2*>(&Qo[(size_t)row0 * D_ + col]) =
                    make_float2(acc[mt][nt][0] + bb.x, acc[mt][nt][1] + bb.y);
                *reinterpret_cast<float2*>(&Qo[(size_t)row1 * D_ + col]) =
                    make_float2(acc[mt][nt][2] + bb.x, acc[mt][nt][3] + bb.y);
            }
        }
    } else if (blockIdx.z == 1) {
#pragma unroll
        for (int mt = 0; mt < 2; mt++) {
            const int row0 = rowBase + wm * 32 + mt * 16 + gid;
            const int b    = row0 >> 10;
            const int n0   = row0 & 1023;
            const int kt   = n0 >> 7;
            const int key0 = n0 & 127;
            const int key1 = key0 + 8;
#pragma unroll
            for (int nt = 0; nt < 8; nt++) {
                const int col = colBase + wn * 64 + nt * 8 + 2 * tig;
                const int h   = col >> 5;
                const int kk0 = col & 31;
                float2 bb = *reinterpret_cast<const float2*>(&bias[col]);
                const size_t base = (size_t)((b * 8 + h) * 8 + kt) * 5120;
#pragma unroll
                for (int e = 0; e < 4; e++) {
                    const int kk  = kk0 + (e & 1);
                    const int key = (e < 2) ? key0 : key1;
                    const float v = acc[mt][nt][e] + ((e & 1) ? bb.y : bb.x);
                    Kaug[base + (size_t)(((kk >> 2) * 16 + (key >> 3)) * 32
                                         + (kk & 3) * 8 + (key & 7))] = v;
                }
            }
        }
    } else {
#pragma unroll
        for (int mt = 0; mt < 2; mt++) {
            const int row0 = rowBase + wm * 32 + mt * 16 + gid;
            const int b    = row0 >> 10;
            const int n0   = row0 & 1023;
            const int kt   = n0 >> 7;
            const int key0 = n0 & 127;
            const int key1 = key0 + 8;
#pragma unroll
            for (int nt = 0; nt < 8; nt++) {
                const int col = colBase + wn * 64 + nt * 8 + 2 * tig;
                const int h   = col >> 5;
                const int dk0 = col & 31;
                float2 bb = *reinterpret_cast<const float2*>(&bias[col]);
                const size_t base = (size_t)((b * 8 + h) * 8 + kt) * 4096;
#pragma unroll
                for (int e = 0; e < 4; e++) {
                    const int dk  = dk0 + (e & 1);
                    const int key = (e < 2) ? key0 : key1;
                    const float v = acc[mt][nt][e] + ((e & 1) ? bb.y : bb.x);
                    Vaug[base + (size_t)(((key >> 2) * 4 + (dk >> 3)) * 32
                                         + (key & 3) * 8 + (dk & 7))] = v;
                }
            }
        }
    }
}

// ff1: plain 128x128-tile GEMM with ReLU.
__global__ __launch_bounds__(256, 2)
void ff1_kernel(const float* __restrict__ A, const float* __restrict__ Bw,
                const float* __restrict__ bias, float* __restrict__ C)
{
    float acc[2][8][4];
    gemm_accum(A, Bw, FF_, D_, acc);

    const int lane = threadIdx.x & 31;
    const int warp = threadIdx.x >> 5;
    const int gid  = lane >> 2;
    const int tig  = lane & 3;
    const int wm   = warp & 3;
    const int wn   = warp >> 2;
    const int rowBase = blockIdx.y * 128;
    const int colBase = blockIdx.x * 128;

#pragma unroll
    for (int mt = 0; mt < 2; mt++) {
        const int row0 = rowBase + wm * 32 + mt * 16 + gid;
        const int row1 = row0 + 8;
#pragma unroll
        for (int nt = 0; nt < 8; nt++) {
            const int col = colBase + wn * 64 + nt * 8 + 2 * tig;
            float2 bb = *reinterpret_cast<const float2*>(&bias[col]);
            float v0 = fmaxf(acc[mt][nt][0] + bb.x, 0.0f);
            float v1 = fmaxf(acc[mt][nt][1] + bb.y, 0.0f);
            float v2 = fmaxf(acc[mt][nt][2] + bb.x, 0.0f);
            float v3 = fmaxf(acc[mt][nt][3] + bb.y, 0.0f);
            *reinterpret_cast<float2*>(&C[(size_t)row0 * FF_ + col]) = make_float2(v0, v1);
            *reinterpret_cast<float2*>(&C[(size_t)row1 * FF_ + col]) = make_float2(v2, v3);
        }
    }
}

// ----------------------------------------------------------------------------
// Fused ff2 + residual + LayerNorm.
// CTA tile: 32 rows x 256 cols (full model row), K=1024, grid 256, occ 2.
// 256 threads / 8 warps; warp w owns all 32 rows x cols [w*32, w*32+32).
// 3-stage cp.async pipeline; smem/stage = 37888 B, total 113664 B.
// ----------------------------------------------------------------------------
constexpr int A2_TILE_U32 = 32 * 32;                            // 1024
constexpr int B2_TILE_U32 = 32 * 264;                           // 8448
constexpr int STAGE2_U32  = A2_TILE_U32 + B2_TILE_U32;          // 9472
constexpr int FF2_SMEM    = 3 * STAGE2_U32 * 4;                 // 113664 bytes

__global__ __launch_bounds__(256, 2)
void ff2_ln_kernel(const float* __restrict__ Hb,
                   const float* __restrict__ W2,
                   const float* __restrict__ b2,
                   const float* __restrict__ X,
                   const float* __restrict__ g,
                   const float* __restrict__ be,
                   float* __restrict__ out)
{
    extern __shared__ uint32_t sm[];

    const int tid  = threadIdx.x;
    const int lane = tid & 31;
    const int wn   = tid >> 5;            // warp 0..7 = column group
    const int gid  = lane >> 2;
    const int tig  = lane & 3;

    const int rowBase = blockIdx.x * 32;

    // staging: A = 1 float4 per 8 threads... A tile = 32 rows x 8 float4 = 256
    // float4 -> 1 per thread. B tile = 32 k-rows x 64 float4 = 2048 -> 8/thread.
    const int aR  = tid >> 3;             // 0..31
    const int aC4 = (tid & 7) << 2;
    const int aS  = aR * 32 + (aC4 ^ ((aR & 7) << 2));

    int bR[8], bS[8], bC4[8];
#pragma unroll
    for (int i = 0; i < 8; i++) {
        int idx = tid + i * 256;
        int rb  = idx >> 6;               // 0..31
        int cb4 = (idx & 63) << 2;        // 0..252
        bR[i] = rb; bS[i] = rb * 264 + cb4; bC4[i] = cb4;
    }

    auto issue = [&](int t, int buf) {
        const int k0 = t * 32;
        uint32_t* As = sm + buf * STAGE2_U32;
        uint32_t* Bs = As + A2_TILE_U32;
        cp16(smem_u32(&As[aS]),
             &Hb[(size_t)(rowBase + aR) * FF_ + k0 + aC4]);
#pragma unroll
        for (int i = 0; i < 8; i++)
            cp16(smem_u32(&Bs[bS[i]]),
                 &W2[(size_t)(k0 + bR[i]) * D_ + bC4[i]]);
        cp_commit();
    };

    float acc[2][4][4];
#pragma unroll
    for (int mt = 0; mt < 2; mt++)
#pragma unroll
        for (int nt = 0; nt < 4; nt++)
#pragma unroll
            for (int j = 0; j < 4; j++) acc[mt][nt][j] = 0.0f;

    const int T = FF_ >> 5;               // 32
    issue(0, 0);
    issue(1, 1);

    int buf = 0;
    for (int t = 0; t < T; t++) {
        if (t + 1 < T) cp_wait<1>(); else cp_wait<0>();
        __syncthreads();

        const uint32_t* Ab = sm + buf * STAGE2_U32;
        const uint32_t* Bb = Ab + A2_TILE_U32;

#pragma unroll
        for (int kk = 0; kk < 32; kk += 8) {
            uint32_t a[2][4];
#pragma unroll
            for (int mt = 0; mt < 2; mt++) {
                const int m  = mt * 16 + gid;           // rows m, m+8
                const int sw = (m & 7) << 2;
                const int b0 = m * 32;
                const int b1 = b0 + 8 * 32;
                a[mt][0] = Ab[b0 + (kk ^ sw) + tig];
                a[mt][1] = Ab[b1 + (kk ^ sw) + tig];
                a[mt][2] = Ab[b0 + ((kk + 4) ^ sw) + tig];
                a[mt][3] = Ab[b1 + ((kk + 4) ^ sw) + tig];
            }
            uint32_t b[4][2];
#pragma unroll
            for (int nt = 0; nt < 4; nt++) {
                const int n = wn * 32 + nt * 8 + gid;
                b[nt][0] = Bb[(kk + tig) * 264 + n];
                b[nt][1] = Bb[(kk + tig + 4) * 264 + n];
            }
#pragma unroll
            for (int mt = 0; mt < 2; mt++)
#pragma unroll
                for (int nt = 0; nt < 4; nt++)
                    mma_tf32(acc[mt][nt], a[mt], b[nt]);
        }

        if (t + 2 < T) {
            int nbuf = buf + 2; if (nbuf >= 3) nbuf -= 3;
            issue(t + 2, nbuf);
        }
        if (++buf == 3) buf = 0;
    }

    // ---- epilogue: bias + residual, per-row mean/var, LN ----
    __syncthreads();
    float* red = reinterpret_cast<float*>(sm);   // [32 rows][16]: sum/sq per warp

#pragma unroll
    for (int mt = 0; mt < 2; mt++) {
        const int rloc0 = mt * 16 + gid;
        const int rloc1 = rloc0 + 8;
        float s0 = 0.0f, q0 = 0.0f, s1 = 0.0f, q1 = 0.0f;
#pragma unroll
        for (int nt = 0; nt < 4; nt++) {
            const int col = wn * 32 + nt * 8 + 2 * tig;
            float2 bb = *reinterpret_cast<const float2*>(&b2[col]);
            float2 x0 = *reinterpret_cast<const float2*>(
                &X[(size_t)(rowBase + rloc0) * D_ + col]);
            float2 x1 = *reinterpret_cast<const float2*>(
                &X[(size_t)(rowBase + rloc1) * D_ + col]);
            float v0 = acc[mt][nt][0] + bb.x + x0.x;
            float v1 = acc[mt][nt][1] + bb.y + x0.y;
            float v2 = acc[mt][nt][2] + bb.x + x1.x;
            float v3 = acc[mt][nt][3] + bb.y + x1.y;
            acc[mt][nt][0] = v0; acc[mt][nt][1] = v1;
            acc[mt][nt][2] = v2; acc[mt][nt][3] = v3;
            s0 += v0 + v1; q0 = fmaf(v0, v0, fmaf(v1, v1, q0));
            s1 += v2 + v3; q1 = fmaf(v2, v2, fmaf(v3, v3, q1));
        }
        s0 += __shfl_xor_sync(0xffffffffu, s0, 1);
        s0 += __shfl_xor_sync(0xffffffffu, s0, 2);
        q0 += __shfl_xor_sync(0xffffffffu, q0, 1);
        q0 += __shfl_xor_sync(0xffffffffu, q0, 2);
        s1 += __shfl_xor_sync(0xffffffffu, s1, 1);
        s1 += __shfl_xor_sync(0xffffffffu, s1, 2);
        q1 += __shfl_xor_sync(0xffffffffu, q1, 1);
        q1 += __shfl_xor_sync(0xffffffffu, q1, 2);
        if (tig == 0) {
            red[rloc0 * 16 + wn * 2 + 0] = s0;
            red[rloc0 * 16 + wn * 2 + 1] = q0;
            red[rloc1 * 16 + wn * 2 + 0] = s1;
            red[rloc1 * 16 + wn * 2 + 1] = q1;
        }
    }
    __syncthreads();

#pragma unroll
    for (int mt = 0; mt < 2; mt++) {
#pragma unroll
        for (int rr = 0; rr < 2; rr++) {
            const int rloc = mt * 16 + gid + rr * 8;
            const float* rp = &red[rloc * 16];
            float sum = 0.0f, sq = 0.0f;
#pragma unroll
            for (int wq = 0; wq < 8; wq++) {
                sum += rp[wq * 2 + 0];
                sq  += rp[wq * 2 + 1];
            }
            const float mean = sum * (1.0f / 256.0f);
            const float var  = sq * (1.0f / 256.0f) - mean * mean;
            const float rs   = rsqrtf(var + 1e-5f);
            const int row = rowBase + rloc;
#pragma unroll
            for (int nt = 0; nt < 4; nt++) {
                const int col = wn * 32 + nt * 8 + 2 * tig;
                float2 gv = *reinterpret_cast<const float2*>(&g[col]);
                float2 ev = *reinterpret_cast<const float2*>(&be[col]);
                const float a0 = acc[mt][nt][rr * 2 + 0];
                const float a1 = acc[mt][nt][rr * 2 + 1];
                *reinterpret_cast<float2*>(&out[(size_t)row * D_ + col]) =
                    make_float2((a0 - mean) * rs * gv.x + ev.x,
                                (a1 - mean) * rs * gv.y + ev.y);
            }
        }
    }
}

// ----------------------------------------------------------------------------
// One-time fill of Kaug coords rows (kk 32..39): layer-invariant.
// ----------------------------------------------------------------------------
__global__ __launch_bounds__(256)
void fill_kcoords_kernel(const float* __restrict__ coords,
                         float* __restrict__ Kaug)
{
    const int t  = blockIdx.x;
    const int kt = t & 7;
    const int b  = (t >> 3) >> 3;
    const size_t base = (size_t)t * 5120 + 128 * 32;
#pragma unroll
    for (int j = 0; j < 4; j++) {
        const int e   = threadIdx.x + j * 256;
        const int rel = e >> 5;
        const int ln  = e & 31;
        const int kk  = 32 + (rel >> 4) * 4 + (ln >> 3);
        const int key = (rel & 15) * 8 + (ln & 7);
        float v = 0.0f;
        if (kk < 35)
            v = coords[(size_t)(b * N_ + kt * 128 + key) * 3 + (kk - 32)];
        Kaug[base + e] = v;
    }
}

// ----------------------------------------------------------------------------
// tf32 MMA flash attention. 2 CTAs/SM.
// ----------------------------------------------------------------------------
constexpr int KT_FLOATS   = 5120;
constexpr int VT_FLOATS   = 4096;
constexpr int TILE_FLOATS = KT_FLOATS + VT_FLOATS;
constexpr int ATTN_SMEM   = 2 * TILE_FLOATS * 4;

__global__ __launch_bounds__(256, 2)
void attn_mma_kernel(const float* __restrict__ Q,
                     const float* __restrict__ Kaug,
                     const float* __restrict__ Vaug,
                     const float* __restrict__ coords,
                     const float* __restrict__ alpha,
                     int layer,
                     float* __restrict__ Out)
{
    extern __shared__ float smf[];

    const int tid  = threadIdx.x;
    const int lane = tid & 31;
    const int w    = tid >> 5;
    const int gid  = lane >> 2;
    const int tig  = lane & 3;

    const int bh = blockIdx.x;
    const int b  = bh >> 3;
    const int h  = bh & 7;
    const int q0 = blockIdx.y * 128;

    const float scale  = 0.17677669529663687f;
    const float alphav = alpha[layer];

    uint32_t qf[5][4];
    {
        const int row0 = b * N_ + q0 + w * 16 + gid;
#pragma unroll
        for (int ks = 0; ks < 5; ks++) {
#pragma unroll
            for (int r = 0; r < 4; r++) {
                const int row = row0 + (r & 1) * 8;
                const int kk  = ks * 8 + tig + ((r >> 1) << 2);
                float v;
                if (kk < 32)      v = Q[(size_t)row * D_ + h * DK_ + kk] * scale;
                else if (kk < 35) v = alphav * coords[(size_t)row * 3 + (kk - 32)];
                else              v = 0.0f;
                qf[ks][r] = __float_as_uint(v);
            }
        }
    }

    auto issue = [&](int t, int buf) {
        const float* srcK = Kaug + (size_t)(bh * 8 + t) * KT_FLOATS;
        float* dstK = smf + buf * TILE_FLOATS;
#pragma unroll
        for (int j = 0; j < 5; j++) {
            const int i16 = tid + j * 256;
            cp16(smem_u32(dstK + i16 * 4), srcK + i16 * 4);
        }
        const float* srcV = Vaug + (size_t)(bh * 8 + t) * VT_FLOATS;
        float* dstV = smf + buf * TILE_FLOATS + KT_FLOATS;
#pragma unroll
        for (int j = 0; j < 4; j++) {
            const int i16 = tid + j * 256;
            cp16(smem_u32(dstV + i16 * 4), srcV + i16 * 4);
        }
        cp_commit();
    };

    float O[4][4];
#pragma unroll
    for (int i = 0; i < 4; i++)
#pragma unroll
        for (int j = 0; j < 4; j++) O[i][j] = 0.0f;
    float m0 = -1e30f, m1 = -1e30f, l0 = 0.0f, l1 = 0.0f;

    const int klane = tig * 8 + gid;
    const int src0  = (gid << 2) + (tig >> 1);
    const int src1  = src0 + 2;

    issue(0, 0);

    for (int t = 0; t < 8; t++) {
        if (t < 7) { issue(t + 1, (t + 1) & 1); cp_wait<1>(); }
        else       { cp_wait<0>(); }
        __syncthreads();

        const uint32_t* Kb = reinterpret_cast<const uint32_t*>(smf + (t & 1) * TILE_FLOATS);
        const uint32_t* Vb = Kb + KT_FLOATS;

        float s[16][4];
#pragma unroll
        for (int nt = 0; nt < 16; nt++)
#pragma unroll
            for (int j = 0; j < 4; j++) s[nt][j] = 0.0f;

#pragma unroll
        for (int ks = 0; ks < 5; ks++) {
#pragma unroll
            for (int nt = 0; nt < 16; nt++) {
                uint32_t bfr[2];
                bfr[0] = Kb[(32 * ks + nt) * 32 + klane];
                bfr[1] = Kb[(32 * ks + 16 + nt) * 32 + klane];
                mma_tf32(s[nt], qf[ks], bfr);
            }
        }

        float mx0 = -1e30f, mx1 = -1e30f;
#pragma unroll
        for (int nt = 0; nt < 16; nt++) {
            mx0 = fmaxf(mx0, fmaxf(s[nt][0], s[nt][1]));
            mx1 = fmaxf(mx1, fmaxf(s[nt][2], s[nt][3]));
        }
        mx0 = fmaxf(mx0, __shfl_xor_sync(0xffffffffu, mx0, 1));
        mx0 = fmaxf(mx0, __shfl_xor_sync(0xffffffffu, mx0, 2));
        mx1 = fmaxf(mx1, __shfl_xor_sync(0xffffffffu, mx1, 1));
        mx1 = fmaxf(mx1, __shfl_xor_sync(0xffffffffu, mx1, 2));

        const float mn0 = fmaxf(m0, mx0);
        const float mn1 = fmaxf(m1, mx1);
        const float c0  = __expf(m0 - mn0);
        const float c1  = __expf(m1 - mn1);
        m0 = mn0; m1 = mn1;

        float rs0 = 0.0f, rs1 = 0.0f;
#pragma unroll
        for (int nt = 0; nt < 16; nt++) {
            s[nt][0] = __expf(s[nt][0] - mn0);
            s[nt][1] = __expf(s[nt][1] - mn0);
            s[nt][2] = __expf(s[nt][2] - mn1);
            s[nt][3] = __expf(s[nt][3] - mn1);
            rs0 += s[nt][0] + s[nt][1];
            rs1 += s[nt][2] + s[nt][3];
        }
        rs0 += __shfl_xor_sync(0xffffffffu, rs0, 1);
        rs0 += __shfl_xor_sync(0xffffffffu, rs0, 2);
        rs1 += __shfl_xor_sync(0xffffffffu, rs1, 1);
        rs1 += __shfl_xor_sync(0xffffffffu, rs1, 2);
        l0 = l0 * c0 + rs0;
        l1 = l1 * c1 + rs1;

#pragma unroll
        for (int nt2 = 0; nt2 < 4; nt2++) {
            O[nt2][0] *= c0; O[nt2][1] *= c0;
            O[nt2][2] *= c1; O[nt2][3] *= c1;
        }

#pragma unroll
        for (int ks = 0; ks < 16; ks++) {
            uint32_t a[4];
            {
                float v0 = __shfl_sync(0xffffffffu, s[ks][0], src0);
                float v1 = __shfl_sync(0xffffffffu, s[ks][1], src0);
                float v2 = __shfl_sync(0xffffffffu, s[ks][2], src0);
                float v3 = __shfl_sync(0xffffffffu, s[ks][3], src0);
                float u0 = __shfl_sync(0xffffffffu, s[ks][0], src1);
                float u1 = __shfl_sync(0xffffffffu, s[ks][1], src1);
                float u2 = __shfl_sync(0xffffffffu, s[ks][2], src1);
                float u3 = __shfl_sync(0xffffffffu, s[ks][3], src1);
                const bool odd = (tig & 1);
                a[0] = __float_as_uint(odd ? v1 : v0);
                a[1] = __float_as_uint(odd ? v3 : v2);
                a[2] = __float_as_uint(odd ? u1 : u0);
                a[3] = __float_as_uint(odd ? u3 : u2);
            }
#pragma unroll
            for (int nt2 = 0; nt2 < 4; nt2++) {
                uint32_t bfr[2];
                bfr[0] = Vb[(8 * ks + nt2) * 32 + klane];
                bfr[1] = Vb[(8 * ks + 4 + nt2) * 32 + klane];
                mma_tf32(O[nt2], a, bfr);
            }
        }
        __syncthreads();
    }

    const float inv0 = 1.0f / l0;
    const float inv1 = 1.0f / l1;
    const int row0 = b * N_ + q0 + w * 16 + gid;
    const int row1 = row0 + 8;
#pragma unroll
    for (int nt2 = 0; nt2 < 4; nt2++) {
        const int col = h * DK_ + nt2 * 8 + 2 * tig;
        *reinterpret_cast<float2*>(&Out[(size_t)row0 * D_ + col]) =
            make_float2(O[nt2][0] * inv0, O[nt2][1] * inv0);
        *reinterpret_cast<float2*>(&Out[(size_t)row1 * D_ + col]) =
            make_float2(O[nt2][2] * inv1, O[nt2][3] * inv1);
    }
}

// ----------------------------------------------------------------------------
// Fused residual add + LayerNorm (LN1). TWO rows per warp (proven config).
// Block 256 = 8 warps = 16 rows; grid = ROWS/16.
// ----------------------------------------------------------------------------
__global__ __launch_bounds__(256, 6)
void add_ln_kernel(const float* __restrict__ x,
                   const float* __restrict__ delta,
                   const float* __restrict__ g,
                   const float* __restrict__ be,
                   float* __restrict__ out)
{
    const int warp = threadIdx.x >> 5;
    const int lane = threadIdx.x & 31;
    const int rowA = blockIdx.x * 16 + warp * 2;
    const int rowB = rowA + 1;
    const int col0 = lane * 8;

    const float4* xa = reinterpret_cast<const float4*>(&x[(size_t)rowA * D_ + col0]);
    const float4* da = reinterpret_cast<const float4*>(&delta[(size_t)rowA * D_ + col0]);
    const float4* xb = reinterpret_cast<const float4*>(&x[(size_t)rowB * D_ + col0]);
    const float4* db = reinterpret_cast<const float4*>(&delta[(size_t)rowB * D_ + col0]);

    float4 xa0 = xa[0], xa1 = xa[1], xb0 = xb[0], xb1 = xb[1];
    float4 da0 = da[0], da1 = da[1], db0 = db[0], db1 = db[1];

    float ra[8], rb[8];
    ra[0] = xa0.x + da0.x; ra[1] = xa0.y + da0.y; ra[2] = xa0.z + da0.z; ra[3] = xa0.w + da0.w;
    ra[4] = xa1.x + da1.x; ra[5] = xa1.y + da1.y; ra[6] = xa1.z + da1.z; ra[7] = xa1.w + da1.w;
    rb[0] = xb0.x + db0.x; rb[1] = xb0.y + db0.y; rb[2] = xb0.z + db0.z; rb[3] = xb0.w + db0.w;
    rb[4] = xb1.x + db1.x; rb[5] = xb1.y + db1.y; rb[6] = xb1.z + db1.z; rb[7] = xb1.w + db1.w;

    float sa = 0.0f, sb = 0.0f;
#pragma unroll
    for (int j = 0; j < 8; j++) { sa += ra[j]; sb += rb[j]; }
#pragma unroll
    for (int off = 16; off > 0; off >>= 1) {
        sa += __shfl_xor_sync(0xffffffffu, sa, off);
        sb += __shfl_xor_sync(0xffffffffu, sb, off);
    }
    const float meanA = sa * (1.0f / 256.0f);
    const float meanB = sb * (1.0f / 256.0f);

    float va = 0.0f, vb = 0.0f;
#pragma unroll
    for (int j = 0; j < 8; j++) {
        float ta = ra[j] - meanA; va = fmaf(ta, ta, va);
        float tb = rb[j] - meanB; vb = fmaf(tb, tb, vb);
    }
#pragma unroll
    for (int off = 16; off > 0; off >>= 1) {
        va += __shfl_xor_sync(0xffffffffu, va, off);
        vb += __shfl_xor_sync(0xffffffffu, vb, off);
    }
    const float rsA = rsqrtf(va * (1.0f / 256.0f) + 1e-5f);
    const float rsB = rsqrtf(vb * (1.0f / 256.0f) + 1e-5f);

    const float4* gg = reinterpret_cast<const float4*>(&g[col0]);
    const float4* bb = reinterpret_cast<const float4*>(&be[col0]);
    float4 g0 = gg[0], g1 = gg[1], e0 = bb[0], e1 = bb[1];
    const float gv[8] = {g0.x, g0.y, g0.z, g0.w, g1.x, g1.y, g1.z, g1.w};
    const float ev[8] = {e0.x, e0.y, e0.z, e0.w, e1.x, e1.y, e1.z, e1.w};

    float oa[8], ob[8];
#pragma unroll
    for (int j = 0; j < 8; j++) {
        oa[j] = (ra[j] - meanA) * rsA * gv[j] + ev[j];
        ob[j] = (rb[j] - meanB) * rsB * gv[j] + ev[j];
    }

    float4* outA = reinterpret_cast<float4*>(&out[(size_t)rowA * D_ + col0]);
    float4* outB = reinterpret_cast<float4*>(&out[(size_t)rowB * D_ + col0]);
    outA[0] = make_float4(oa[0], oa[1], oa[2], oa[3]);
    outA[1] = make_float4(oa[4], oa[5], oa[6], oa[7]);
    outB[0] = make_float4(ob[0], ob[1], ob[2], ob[3]);
    outB[1] = make_float4(ob[4], ob[5], ob[6], ob[7]);
}

// ----------------------------------------------------------------------------
// Host driver
// ----------------------------------------------------------------------------
extern "C" void kernel_launch(void* const* d_in, const int* in_sizes, int n_in,
                              void* d_out, int out_size)
{
    const float* x      = (const float*)d_in[0];
    const float* coords = (const float*)d_in[1];
    const float* Wq     = (const float*)d_in[2];
    const float* bq     = (const float*)d_in[3];
    const float* Wk     = (const float*)d_in[4];
    const float* bk     = (const float*)d_in[5];
    const float* Wv     = (const float*)d_in[6];
    const float* bv     = (const float*)d_in[7];
    const float* alpha  = (const float*)d_in[8];
    const float* W1     = (const float*)d_in[9];
    const float* b1     = (const float*)d_in[10];
    const float* W2     = (const float*)d_in[11];
    const float* b2     = (const float*)d_in[12];
    const float* g1     = (const float*)d_in[13];
    const float* be1    = (const float*)d_in[14];
    const float* g2     = (const float*)d_in[15];
    const float* be2    = (const float*)d_in[16];
    float* out = (float*)d_out;

    float *Qp, *Ap, *Xp, *Hp, *KAp, *VAp;
    cudaGetSymbolAddress((void**)&Qp,  g_Q);
    cudaGetSymbolAddress((void**)&Ap,  g_ATT);
    cudaGetSymbolAddress((void**)&Xp,  g_X);
    cudaGetSymbolAddress((void**)&Hp,  g_Hb);
    cudaGetSymbolAddress((void**)&KAp, g_Kaug);
    cudaGetSymbolAddress((void**)&VAp, g_Vaug);

    cudaFuncSetAttribute(qkv_kernel,
                         cudaFuncAttributeMaxDynamicSharedMemorySize, GEMM_SMEM);
    cudaFuncSetAttribute(ff1_kernel,
                         cudaFuncAttributeMaxDynamicSharedMemorySize, GEMM_SMEM);
    cudaFuncSetAttribute(ff2_ln_kernel,
                         cudaFuncAttributeMaxDynamicSharedMemorySize, FF2_SMEM);
    cudaFuncSetAttribute(attn_mma_kernel,
                         cudaFuncAttributeMaxDynamicSharedMemorySize, ATTN_SMEM);

    const dim3 gQKV(D_ / 128, ROWS / 128, 3);
    const dim3 gFF1(FF_ / 128, ROWS / 128);
    const dim3 gAttn(B_ * H_, N_ / 128);

    fill_kcoords_kernel<<<512, 256>>>(coords, KAp);

    const float* cur = x;
    for (int i = 0; i < L_; i++) {
        qkv_kernel<<<gQKV, 256, GEMM_SMEM>>>(
            cur,
            Wq + (size_t)i * D_ * D_, Wk + (size_t)i * D_ * D_, Wv + (size_t)i * D_ * D_,
            bq + i * D_, bk + i * D_, bv + i * D_,
            Qp, KAp, VAp);

        attn_mma_kernel<<<gAttn, 256, ATTN_SMEM>>>(Qp, KAp, VAp, coords, alpha, i, Ap);

        add_ln_kernel<<<ROWS / 16, 256>>>(cur, Ap, g1 + i * D_, be1 + i * D_, Xp);

        ff1_kernel<<<gFF1, 256, GEMM_SMEM>>>(Xp, W1 + (size_t)i * D_ * FF_,
                                             b1 + i * FF_, Hp);

        float* xo = (i == L_ - 1) ? out : Xp;
        ff2_ln_kernel<<<ROWS / 32, 256, FF2_SMEM>>>(
            Hp, W2 + (size_t)i * FF_ * D_, b2 + i * D_,
            Xp, g2 + i * D_, be2 + i * D_, xo);

        cur = Xp;
    }
}

// round 14
// speedup vs baseline: 1.2241x; 1.2241x over previous
#include <cuda_runtime.h>
#include <cuda_fp16.h>
#include <cstdint>

// ----------------------------------------------------------------------------
// Problem constants
// ----------------------------------------------------------------------------
constexpr int B_  = 8;
constexpr int N_  = 1024;
constexpr int D_  = 256;
constexpr int H_  = 8;
constexpr int DK_ = 32;
constexpr int FF_ = 1024;
constexpr int L_  = 4;
constexpr int ROWS = B_ * N_;          // 8192 token rows

// ----------------------------------------------------------------------------
// Scratch (device globals: no allocation allowed)
// ----------------------------------------------------------------------------
__device__ float g_Q  [ROWS * D_];
__device__ float g_ATT[ROWS * D_];
__device__ float g_X  [ROWS * D_];
// fp16 packed activations (u32 = half2 along k)
__device__ __align__(16) uint32_t g_Xh [ROWS * D_ / 2];      // [row][kpair(128)]
__device__ __align__(16) uint32_t g_Hbh[ROWS * FF_ / 2];     // [row][kpair(512)]
// fp16 packed weights: [K/2][N] per layer
__device__ __align__(16) uint32_t g_Wqh[L_ * (D_ / 2) * D_];
__device__ __align__(16) uint32_t g_Wkh[L_ * (D_ / 2) * D_];
__device__ __align__(16) uint32_t g_Wvh[L_ * (D_ / 2) * D_];
__device__ __align__(16) uint32_t g_W1h[L_ * (D_ / 2) * FF_];
__device__ __align__(16) uint32_t g_W2h[L_ * (FF_ / 2) * D_];
// Attention staging buffers in mma-fragment-tiled layout (fp32, unchanged).
__device__ __align__(16) float g_Kaug[64 * 8 * 5120];
__device__ __align__(16) float g_Vaug[64 * 8 * 4096];

// ----------------------------------------------------------------------------
// Helpers
// ----------------------------------------------------------------------------
__device__ __forceinline__ uint32_t smem_u32(const void* p) {
    return (uint32_t)__cvta_generic_to_shared(p);
}
__device__ __forceinline__ void cp16(uint32_t s, const void* g) {
    asm volatile("cp.async.cg.shared.global [%0], [%1], 16;" :: "r"(s), "l"(g));
}
__device__ __forceinline__ void cp_commit() {
    asm volatile("cp.async.commit_group;" ::: "memory");
}
template <int NN>
__device__ __forceinline__ void cp_wait() {
    asm volatile("cp.async.wait_group %0;" :: "n"(NN) : "memory");
}
__device__ __forceinline__ void mma_tf32(float* c, const uint32_t* a, const uint32_t* b) {
    asm volatile(
        "mma.sync.aligned.m16n8k8.row.col.f32.tf32.tf32.f32 "
        "{%0,%1,%2,%3},{%4,%5,%6,%7},{%8,%9},{%0,%1,%2,%3};"
        : "+f"(c[0]), "+f"(c[1]), "+f"(c[2]), "+f"(c[3])
        : "r"(a[0]), "r"(a[1]), "r"(a[2]), "r"(a[3]), "r"(b[0]), "r"(b[1]));
}
__device__ __forceinline__ void mma_f16(float* c, const uint32_t* a, const uint32_t* b) {
    asm volatile(
        "mma.sync.aligned.m16n8k16.row.col.f32.f16.f16.f32 "
        "{%0,%1,%2,%3},{%4,%5,%6,%7},{%8,%9},{%0,%1,%2,%3};"
        : "+f"(c[0]), "+f"(c[1]), "+f"(c[2]), "+f"(c[3])
        : "r"(a[0]), "r"(a[1]), "r"(a[2]), "r"(a[3]), "r"(b[0]), "r"(b[1]));
}
__device__ __forceinline__ uint32_t packh2(float a, float b) {
    __half2 h = __floats2half2_rn(a, b);
    return *reinterpret_cast<uint32_t*>(&h);
}

// ----------------------------------------------------------------------------
// fp16 MMA GEMM core (128x128 tile): 3-stage cp.async pipeline.
// A: packed activations [row][Kpairs], B: packed weights [Kpairs][Nn].
// Per k-tile: 64 k-elements = 32 kpairs. Smem byte-layout identical to the
// proven tf32 version; only the mma instruction and T change.
// ----------------------------------------------------------------------------
constexpr int A_TILE_U32 = 128 * 32;
constexpr int B_TILE_U32 = 32 * 136;
constexpr int STAGE_U32  = A_TILE_U32 + B_TILE_U32;            // 8448
constexpr int GEMM_SMEM  = 3 * STAGE_U32 * 4;                  // 101376 bytes

__device__ __forceinline__ void gemm_accum_f16(const uint32_t* __restrict__ A,
                                               const uint32_t* __restrict__ Bw,
                                               int Nn, int Kpairs,
                                               float acc[2][8][4])
{
    extern __shared__ uint32_t sm[];

    const int tid  = threadIdx.x;
    const int lane = tid & 31;
    const int warp = tid >> 5;
    const int gid  = lane >> 2;
    const int tig  = lane & 3;
    const int wm   = warp & 3;
    const int wn   = warp >> 2;

    const int rowBase = blockIdx.y * 128;
    const int colBase = blockIdx.x * 128;

    int aR[4], aS[4], bR[4], bS[4], aC4[4], bC4[4];
#pragma unroll
    for (int i = 0; i < 4; i++) {
        int idx = tid + i * 256;
        int r  = idx >> 3;
        int c4 = (idx & 7) << 2;
        aR[i] = r; aS[i] = r * 32 + (c4 ^ ((r & 7) << 2)); aC4[i] = c4;
        int rb  = idx >> 5;
        int cb4 = (idx & 31) << 2;
        bR[i] = rb; bS[i] = rb * 136 + cb4; bC4[i] = cb4;
    }

    auto issue = [&](int t, int buf) {
        const int k0 = t * 32;                 // kpair units
        uint32_t* As = sm + buf * STAGE_U32;
        uint32_t* Bs = As + A_TILE_U32;
#pragma unroll
        for (int i = 0; i < 4; i++)
            cp16(smem_u32(&As[aS[i]]),
                 &A[(size_t)(rowBase + aR[i]) * Kpairs + k0 + aC4[i]]);
#pragma unroll
        for (int i = 0; i < 4; i++)
            cp16(smem_u32(&Bs[bS[i]]),
                 &Bw[(size_t)(k0 + bR[i]) * Nn + colBase + bC4[i]]);
        cp_commit();
    };

#pragma unroll
    for (int mt = 0; mt < 2; mt++)
#pragma unroll
        for (int nt = 0; nt < 8; nt++)
#pragma unroll
            for (int j = 0; j < 4; j++) acc[mt][nt][j] = 0.0f;

    const int T = Kpairs >> 5;
    issue(0, 0);
    issue(1, 1);

    int buf = 0;
    for (int t = 0; t < T; t++) {
        if (t + 1 < T) cp_wait<1>(); else cp_wait<0>();
        __syncthreads();

        const uint32_t* Ab = sm + buf * STAGE_U32;
        const uint32_t* Bb = Ab + A_TILE_U32;

#pragma unroll
        for (int kk = 0; kk < 32; kk += 8) {   // kpair units; 8 kpairs = k16
            uint32_t a[2][4];
#pragma unroll
            for (int mt = 0; mt < 2; mt++) {
                const int m  = wm * 32 + mt * 16 + gid;
                const int sw = (m & 7) << 2;
                const int b0 = m * 32;
                const int b1 = b0 + 8 * 32;
                a[mt][0] = Ab[b0 + (kk ^ sw) + tig];
                a[mt][1] = Ab[b1 + (kk ^ sw) + tig];
                a[mt][2] = Ab[b0 + ((kk + 4) ^ sw) + tig];
                a[mt][3] = Ab[b1 + ((kk + 4) ^ sw) + tig];
            }
            uint32_t b[8][2];
#pragma unroll
            for (int nt = 0; nt < 8; nt++) {
                const int n = wn * 64 + nt * 8 + gid;
                b[nt][0] = Bb[(kk + tig) * 136 + n];
                b[nt][1] = Bb[(kk + tig + 4) * 136 + n];
            }
#pragma unroll
            for (int mt = 0; mt < 2; mt++)
#pragma unroll
                for (int nt = 0; nt < 8; nt++)
                    mma_f16(acc[mt][nt], a[mt], b[nt]);
        }

        if (t + 2 < T) {
            int nbuf = buf + 2; if (nbuf >= 3) nbuf -= 3;
            issue(t + 2, nbuf);
        }
        if (++buf == 3) buf = 0;
    }
}

// ----------------------------------------------------------------------------
// QKV kernel (fp16). z=0: Q plain fp32. z=1: K -> Kaug. z=2: V -> Vaug.
// ----------------------------------------------------------------------------
__global__ __launch_bounds__(256, 2)
void qkv_kernel(const uint32_t* __restrict__ Ah,
                const uint32_t* __restrict__ Wqh, const uint32_t* __restrict__ Wkh,
                const uint32_t* __restrict__ Wvh,
                const float* __restrict__ bq, const float* __restrict__ bk,
                const float* __restrict__ bv,
                float* __restrict__ Qo, float* __restrict__ Kaug,
                float* __restrict__ Vaug)
{
    const uint32_t* Bw; const float* bias;
    if (blockIdx.z == 0)      { Bw = Wqh; bias = bq; }
    else if (blockIdx.z == 1) { Bw = Wkh; bias = bk; }
    else                      { Bw = Wvh; bias = bv; }

    float acc[2][8][4];
    gemm_accum_f16(Ah, Bw, D_, D_ / 2, acc);

    const int lane = threadIdx.x & 31;
    const int warp = threadIdx.x >> 5;
    const int gid  = lane >> 2;
    const int tig  = lane & 3;
    const int wm   = warp & 3;
    const int wn   = warp >> 2;
    const int rowBase = blockIdx.y * 128;
    const int colBase = blockIdx.x * 128;

    if (blockIdx.z == 0) {
#pragma unroll
        for (int mt = 0; mt < 2; mt++) {
            const int row0 = rowBase + wm * 32 + mt * 16 + gid;
            const int row1 = row0 + 8;
#pragma unroll
            for (int nt = 0; nt < 8; nt++) {
                const int col = colBase + wn * 64 + nt * 8 + 2 * tig;
                float2 bb = *reinterpret_cast<const float2*>(&bias[col]);
                *reinterpret_cast<float2*>(&Qo[(size_t)row0 * D_ + col]) =
                    make_float2(acc[mt][nt][0] + bb.x, acc[mt][nt][1] + bb.y);
                *reinterpret_cast<float2*>(&Qo[(size_t)row1 * D_ + col]) =
                    make_float2(acc[mt][nt][2] + bb.x, acc[mt][nt][3] + bb.y);
            }
        }
    } else if (blockIdx.z == 1) {
#pragma unroll
        for (int mt = 0; mt < 2; mt++) {
            const int row0 = rowBase + wm * 32 + mt * 16 + gid;
            const int b    = row0 >> 10;
            const int n0   = row0 & 1023;
            const int kt   = n0 >> 7;
            const int key0 = n0 & 127;
            const int key1 = key0 + 8;
#pragma unroll
            for (int nt = 0; nt < 8; nt++) {
                const int col = colBase + wn * 64 + nt * 8 + 2 * tig;
                const int h   = col >> 5;
                const int kk0 = col & 31;
                float2 bb = *reinterpret_cast<const float2*>(&bias[col]);
                const size_t base = (size_t)((b * 8 + h) * 8 + kt) * 5120;
#pragma unroll
                for (int e = 0; e < 4; e++) {
                    const int kk  = kk0 + (e & 1);
                    const int key = (e < 2) ? key0 : key1;
                    const float v = acc[mt][nt][e] + ((e & 1) ? bb.y : bb.x);
                    Kaug[base + (size_t)(((kk >> 2) * 16 + (key >> 3)) * 32
                                         + (kk & 3) * 8 + (key & 7))] = v;
                }
            }
        }
    } else {
#pragma unroll
        for (int mt = 0; mt < 2; mt++) {
            const int row0 = rowBase + wm * 32 + mt * 16 + gid;
            const int b    = row0 >> 10;
            const int n0   = row0 & 1023;
            const int kt   = n0 >> 7;
            const int key0 = n0 & 127;
            const int key1 = key0 + 8;
#pragma unroll
            for (int nt = 0; nt < 8; nt++) {
                const int col = colBase + wn * 64 + nt * 8 + 2 * tig;
                const int h   = col >> 5;
                const int dk0 = col & 31;
                float2 bb = *reinterpret_cast<const float2*>(&bias[col]);
                const size_t base = (size_t)((b * 8 + h) * 8 + kt) * 4096;
#pragma unroll
                for (int e = 0; e < 4; e++) {
                    const int dk  = dk0 + (e & 1);
                    const int key = (e < 2) ? key0 : key1;
                    const float v = acc[mt][nt][e] + ((e & 1) ? bb.y : bb.x);
                    Vaug[base + (size_t)(((key >> 2) * 4 + (dk >> 3)) * 32
                                         + (key & 3) * 8 + (dk & 7))] = v;
                }
            }
        }
    }
}

// ff1 (fp16): H = relu(X @ W1 + b1), output packed fp16 only.
__global__ __launch_bounds__(256, 2)
void ff1_kernel(const uint32_t* __restrict__ Ah, const uint32_t* __restrict__ Bw,
                const float* __restrict__ bias, uint32_t* __restrict__ Ch)
{
    float acc[2][8][4];
    gemm_accum_f16(Ah, Bw, FF_, D_ / 2, acc);

    const int lane = threadIdx.x & 31;
    const int warp = threadIdx.x >> 5;
    const int gid  = lane >> 2;
    const int tig  = lane & 3;
    const int wm   = warp & 3;
    const int wn   = warp >> 2;
    const int rowBase = blockIdx.y * 128;
    const int colBase = blockIdx.x * 128;

#pragma unroll
    for (int mt = 0; mt < 2; mt++) {
        const int row0 = rowBase + wm * 32 + mt * 16 + gid;
        const int row1 = row0 + 8;
#pragma unroll
        for (int nt = 0; nt < 8; nt++) {
            const int col = colBase + wn * 64 + nt * 8 + 2 * tig;
            float2 bb = *reinterpret_cast<const float2*>(&bias[col]);
            float v0 = fmaxf(acc[mt][nt][0] + bb.x, 0.0f);
            float v1 = fmaxf(acc[mt][nt][1] + bb.y, 0.0f);
            float v2 = fmaxf(acc[mt][nt][2] + bb.x, 0.0f);
            float v3 = fmaxf(acc[mt][nt][3] + bb.y, 0.0f);
            Ch[(size_t)row0 * (FF_ / 2) + (col >> 1)] = packh2(v0, v1);
            Ch[(size_t)row1 * (FF_ / 2) + (col >> 1)] = packh2(v2, v3);
        }
    }
}

// ----------------------------------------------------------------------------
// Fused ff2 + residual + LayerNorm (fp16 mma, fp32 epilogue).
// CTA tile 64 rows x 256 cols, K = 1024 (512 kpairs), grid 128, 256 threads.
// ----------------------------------------------------------------------------
constexpr int A2_TILE_U32 = 64 * 32;                            // 2048
constexpr int B2_TILE_U32 = 32 * 264;                           // 8448
constexpr int STAGE2_U32  = A2_TILE_U32 + B2_TILE_U32;          // 10496
constexpr int FF2_SMEM    = 3 * STAGE2_U32 * 4;                 // 125952 bytes

__global__ __launch_bounds__(256, 1)
void ff2_ln_kernel(const uint32_t* __restrict__ Hbh,
                   const uint32_t* __restrict__ W2h,
                   const float* __restrict__ b2,
                   const float* __restrict__ X,
                   const float* __restrict__ g,
                   const float* __restrict__ be,
                   float* __restrict__ out,
                   uint32_t* __restrict__ outh)
{
    extern __shared__ uint32_t sm[];

    const int tid  = threadIdx.x;
    const int lane = tid & 31;
    const int warp = tid >> 5;
    const int gid  = lane >> 2;
    const int tig  = lane & 3;
    const int wm   = warp & 1;
    const int wn   = warp >> 1;

    const int rowBase = blockIdx.x * 64;
    constexpr int KP = FF_ / 2;            // 512 kpairs

    int aR[2], aS[2], aC4[2];
#pragma unroll
    for (int i = 0; i < 2; i++) {
        int idx = tid + i * 256;
        int r  = idx >> 3;
        int c4 = (idx & 7) << 2;
        aR[i] = r; aS[i] = r * 32 + (c4 ^ ((r & 7) << 2)); aC4[i] = c4;
    }
    int bR[8], bS[8], bC4[8];
#pragma unroll
    for (int i = 0; i < 8; i++) {
        int idx = tid + i * 256;
        int rb  = idx >> 6;
        int cb4 = (idx & 63) << 2;
        bR[i] = rb; bS[i] = rb * 264 + cb4; bC4[i] = cb4;
    }

    auto issue = [&](int t, int buf) {
        const int k0 = t * 32;             // kpair units
        uint32_t* As = sm + buf * STAGE2_U32;
        uint32_t* Bs = As + A2_TILE_U32;
#pragma unroll
        for (int i = 0; i < 2; i++)
            cp16(smem_u32(&As[aS[i]]),
                 &Hbh[(size_t)(rowBase + aR[i]) * KP + k0 + aC4[i]]);
#pragma unroll
        for (int i = 0; i < 8; i++)
            cp16(smem_u32(&Bs[bS[i]]),
                 &W2h[(size_t)(k0 + bR[i]) * D_ + bC4[i]]);
        cp_commit();
    };

    float acc[2][8][4];
#pragma unroll
    for (int mt = 0; mt < 2; mt++)
#pragma unroll
        for (int nt = 0; nt < 8; nt++)
#pragma unroll
            for (int j = 0; j < 4; j++) acc[mt][nt][j] = 0.0f;

    const int T = KP >> 5;                 // 16
    issue(0, 0);
    issue(1, 1);

    int buf = 0;
    for (int t = 0; t < T; t++) {
        if (t + 1 < T) cp_wait<1>(); else cp_wait<0>();
        __syncthreads();

        const uint32_t* Ab = sm + buf * STAGE2_U32;
        const uint32_t* Bb = Ab + A2_TILE_U32;

#pragma unroll
        for (int kk = 0; kk < 32; kk += 8) {
            uint32_t a[2][4];
#pragma unroll
            for (int mt = 0; mt < 2; mt++) {
                const int m  = wm * 32 + mt * 16 + gid;
                const int sw = (m & 7) << 2;
                const int b0 = m * 32;
                const int b1 = b0 + 8 * 32;
                a[mt][0] = Ab[b0 + (kk ^ sw) + tig];
                a[mt][1] = Ab[b1 + (kk ^ sw) + tig];
                a[mt][2] = Ab[b0 + ((kk + 4) ^ sw) + tig];
                a[mt][3] = Ab[b1 + ((kk + 4) ^ sw) + tig];
            }
            uint32_t b[8][2];
#pragma unroll
            for (int nt = 0; nt < 8; nt++) {
                const int n = wn * 64 + nt * 8 + gid;
                b[nt][0] = Bb[(kk + tig) * 264 + n];
                b[nt][1] = Bb[(kk + tig + 4) * 264 + n];
            }
#pragma unroll
            for (int mt = 0; mt < 2; mt++)
#pragma unroll
                for (int nt = 0; nt < 8; nt++)
                    mma_f16(acc[mt][nt], a[mt], b[nt]);
        }

        if (t + 2 < T) {
            int nbuf = buf + 2; if (nbuf >= 3) nbuf -= 3;
            issue(t + 2, nbuf);
        }
        if (++buf == 3) buf = 0;
    }

    // ---- epilogue: bias + residual, per-row mean/var, LN, fp32 + fp16 out ----
    __syncthreads();
    float* red = reinterpret_cast<float*>(sm);

#pragma unroll
    for (int mt = 0; mt < 2; mt++) {
        const int rloc0 = wm * 32 + mt * 16 + gid;
        const int rloc1 = rloc0 + 8;
        float s0 = 0.0f, q0 = 0.0f, s1 = 0.0f, q1 = 0.0f;
#pragma unroll
        for (int nt = 0; nt < 8; nt++) {
            const int col = wn * 64 + nt * 8 + 2 * tig;
            float2 bb = *reinterpret_cast<const float2*>(&b2[col]);
            float2 x0 = *reinterpret_cast<const float2*>(
                &X[(size_t)(rowBase + rloc0) * D_ + col]);
            float2 x1 = *reinterpret_cast<const float2*>(
                &X[(size_t)(rowBase + rloc1) * D_ + col]);
            float v0 = acc[mt][nt][0] + bb.x + x0.x;
            float v1 = acc[mt][nt][1] + bb.y + x0.y;
            float v2 = acc[mt][nt][2] + bb.x + x1.x;
            float v3 = acc[mt][nt][3] + bb.y + x1.y;
            acc[mt][nt][0] = v0; acc[mt][nt][1] = v1;
            acc[mt][nt][2] = v2; acc[mt][nt][3] = v3;
            s0 += v0 + v1; q0 = fmaf(v0, v0, fmaf(v1, v1, q0));
            s1 += v2 + v3; q1 = fmaf(v2, v2, fmaf(v3, v3, q1));
        }
        s0 += __shfl_xor_sync(0xffffffffu, s0, 1);
        s0 += __shfl_xor_sync(0xffffffffu, s0, 2);
        q0 += __shfl_xor_sync(0xffffffffu, q0, 1);
        q0 += __shfl_xor_sync(0xffffffffu, q0, 2);
        s1 += __shfl_xor_sync(0xffffffffu, s1, 1);
        s1 += __shfl_xor_sync(0xffffffffu, s1, 2);
        q1 += __shfl_xor_sync(0xffffffffu, q1, 1);
        q1 += __shfl_xor_sync(0xffffffffu, q1, 2);
        if (tig == 0) {
            red[rloc0 * 8 + wn * 2 + 0] = s0;
            red[rloc0 * 8 + wn * 2 + 1] = q0;
            red[rloc1 * 8 + wn * 2 + 0] = s1;
            red[rloc1 * 8 + wn * 2 + 1] = q1;
        }
    }
    __syncthreads();

#pragma unroll
    for (int mt = 0; mt < 2; mt++) {
#pragma unroll
        for (int rr = 0; rr < 2; rr++) {
            const int rloc = wm * 32 + mt * 16 + gid + rr * 8;
            const float* rp = &red[rloc * 8];
            const float sum = rp[0] + rp[2] + rp[4] + rp[6];
            const float sq  = rp[1] + rp[3] + rp[5] + rp[7];
            const float mean = sum * (1.0f / 256.0f);
            const float var  = sq * (1.0f / 256.0f) - mean * mean;
            const float rs   = rsqrtf(var + 1e-5f);
            const int row = rowBase + rloc;
#pragma unroll
            for (int nt = 0; nt < 8; nt++) {
                const int col = wn * 64 + nt * 8 + 2 * tig;
                float2 gv = *reinterpret_cast<const float2*>(&g[col]);
                float2 ev = *reinterpret_cast<const float2*>(&be[col]);
                const float a0 = acc[mt][nt][rr * 2 + 0];
                const float a1 = acc[mt][nt][rr * 2 + 1];
                const float o0 = (a0 - mean) * rs * gv.x + ev.x;
                const float o1 = (a1 - mean) * rs * gv.y + ev.y;
                *reinterpret_cast<float2*>(&out[(size_t)row * D_ + col]) =
                    make_float2(o0, o1);
                outh[(size_t)row * (D_ / 2) + (col >> 1)] = packh2(o0, o1);
            }
        }
    }
}

// ----------------------------------------------------------------------------
// One-time prep: pack weights [K][N] fp32 -> [K/2][N] half2. Grid*256 == total.
// ----------------------------------------------------------------------------
__global__ __launch_bounds__(256)
void pack_w_kernel(const float* __restrict__ W, uint32_t* __restrict__ out, int Nn)
{
    const int idx = blockIdx.x * 256 + threadIdx.x;
    const int kp  = idx / Nn;
    const int n   = idx - kp * Nn;
    out[idx] = packh2(W[(size_t)(2 * kp) * Nn + n],
                      W[(size_t)(2 * kp + 1) * Nn + n]);
}

// One-time: convert x to packed fp16. Grid*256 == ROWS*D/2.
__global__ __launch_bounds__(256)
void conv_x_kernel(const float* __restrict__ x, uint32_t* __restrict__ Xh)
{
    const int idx = blockIdx.x * 256 + threadIdx.x;
    float2 v = reinterpret_cast<const float2*>(x)[idx];
    Xh[idx] = packh2(v.x, v.y);
}

// ----------------------------------------------------------------------------
// One-time fill of Kaug coords rows (kk 32..39): layer-invariant.
// ----------------------------------------------------------------------------
__global__ __launch_bounds__(256)
void fill_kcoords_kernel(const float* __restrict__ coords,
                         float* __restrict__ Kaug)
{
    const int t  = blockIdx.x;
    const int kt = t & 7;
    const int b  = (t >> 3) >> 3;
    const size_t base = (size_t)t * 5120 + 128 * 32;
#pragma unroll
    for (int j = 0; j < 4; j++) {
        const int e   = threadIdx.x + j * 256;
        const int rel = e >> 5;
        const int ln  = e & 31;
        const int kk  = 32 + (rel >> 4) * 4 + (ln >> 3);
        const int key = (rel & 15) * 8 + (ln & 7);
        float v = 0.0f;
        if (kk < 35)
            v = coords[(size_t)(b * N_ + kt * 128 + key) * 3 + (kk - 32)];
        Kaug[base + e] = v;
    }
}

// ----------------------------------------------------------------------------
// tf32 MMA flash attention. 2 CTAs/SM. (unchanged)
// ----------------------------------------------------------------------------
constexpr int KT_FLOATS   = 5120;
constexpr int VT_FLOATS   = 4096;
constexpr int TILE_FLOATS = KT_FLOATS + VT_FLOATS;
constexpr int ATTN_SMEM   = 2 * TILE_FLOATS * 4;

__global__ __launch_bounds__(256, 2)
void attn_mma_kernel(const float* __restrict__ Q,
                     const float* __restrict__ Kaug,
                     const float* __restrict__ Vaug,
                     const float* __restrict__ coords,
                     const float* __restrict__ alpha,
                     int layer,
                     float* __restrict__ Out)
{
    extern __shared__ float smf[];

    const int tid  = threadIdx.x;
    const int lane = tid & 31;
    const int w    = tid >> 5;
    const int gid  = lane >> 2;
    const int tig  = lane & 3;

    const int bh = blockIdx.x;
    const int b  = bh >> 3;
    const int h  = bh & 7;
    const int q0 = blockIdx.y * 128;

    const float scale  = 0.17677669529663687f;
    const float alphav = alpha[layer];

    uint32_t qf[5][4];
    {
        const int row0 = b * N_ + q0 + w * 16 + gid;
#pragma unroll
        for (int ks = 0; ks < 5; ks++) {
#pragma unroll
            for (int r = 0; r < 4; r++) {
                const int row = row0 + (r & 1) * 8;
                const int kk  = ks * 8 + tig + ((r >> 1) << 2);
                float v;
                if (kk < 32)      v = Q[(size_t)row * D_ + h * DK_ + kk] * scale;
                else if (kk < 35) v = alphav * coords[(size_t)row * 3 + (kk - 32)];
                else              v = 0.0f;
                qf[ks][r] = __float_as_uint(v);
            }
        }
    }

    auto issue = [&](int t, int buf) {
        const float* srcK = Kaug + (size_t)(bh * 8 + t) * KT_FLOATS;
        float* dstK = smf + buf * TILE_FLOATS;
#pragma unroll
        for (int j = 0; j < 5; j++) {
            const int i16 = tid + j * 256;
            cp16(smem_u32(dstK + i16 * 4), srcK + i16 * 4);
        }
        const float* srcV = Vaug + (size_t)(bh * 8 + t) * VT_FLOATS;
        float* dstV = smf + buf * TILE_FLOATS + KT_FLOATS;
#pragma unroll
        for (int j = 0; j < 4; j++) {
            const int i16 = tid + j * 256;
            cp16(smem_u32(dstV + i16 * 4), srcV + i16 * 4);
        }
        cp_commit();
    };

    float O[4][4];
#pragma unroll
    for (int i = 0; i < 4; i++)
#pragma unroll
        for (int j = 0; j < 4; j++) O[i][j] = 0.0f;
    float m0 = -1e30f, m1 = -1e30f, l0 = 0.0f, l1 = 0.0f;

    const int klane = tig * 8 + gid;
    const int src0  = (gid << 2) + (tig >> 1);
    const int src1  = src0 + 2;

    issue(0, 0);

    for (int t = 0; t < 8; t++) {
        if (t < 7) { issue(t + 1, (t + 1) & 1); cp_wait<1>(); }
        else       { cp_wait<0>(); }
        __syncthreads();

        const uint32_t* Kb = reinterpret_cast<const uint32_t*>(smf + (t & 1) * TILE_FLOATS);
        const uint32_t* Vb = Kb + KT_FLOATS;

        float s[16][4];
#pragma unroll
        for (int nt = 0; nt < 16; nt++)
#pragma unroll
            for (int j = 0; j < 4; j++) s[nt][j] = 0.0f;

#pragma unroll
        for (int ks = 0; ks < 5; ks++) {
#pragma unroll
            for (int nt = 0; nt < 16; nt++) {
                uint32_t bfr[2];
                bfr[0] = Kb[(32 * ks + nt) * 32 + klane];
                bfr[1] = Kb[(32 * ks + 16 + nt) * 32 + klane];
                mma_tf32(s[nt], qf[ks], bfr);
            }
        }

        float mx0 = -1e30f, mx1 = -1e30f;
#pragma unroll
        for (int nt = 0; nt < 16; nt++) {
            mx0 = fmaxf(mx0, fmaxf(s[nt][0], s[nt][1]));
            mx1 = fmaxf(mx1, fmaxf(s[nt][2], s[nt][3]));
        }
        mx0 = fmaxf(mx0, __shfl_xor_sync(0xffffffffu, mx0, 1));
        mx0 = fmaxf(mx0, __shfl_xor_sync(0xffffffffu, mx0, 2));
        mx1 = fmaxf(mx1, __shfl_xor_sync(0xffffffffu, mx1, 1));
        mx1 = fmaxf(mx1, __shfl_xor_sync(0xffffffffu, mx1, 2));

        const float mn0 = fmaxf(m0, mx0);
        const float mn1 = fmaxf(m1, mx1);
        const float c0  = __expf(m0 - mn0);
        const float c1  = __expf(m1 - mn1);
        m0 = mn0; m1 = mn1;

        float rs0 = 0.0f, rs1 = 0.0f;
#pragma unroll
        for (int nt = 0; nt < 16; nt++) {
            s[nt][0] = __expf(s[nt][0] - mn0);
            s[nt][1] = __expf(s[nt][1] - mn0);
            s[nt][2] = __expf(s[nt][2] - mn1);
            s[nt][3] = __expf(s[nt][3] - mn1);
            rs0 += s[nt][0] + s[nt][1];
            rs1 += s[nt][2] + s[nt][3];
        }
        rs0 += __shfl_xor_sync(0xffffffffu, rs0, 1);
        rs0 += __shfl_xor_sync(0xffffffffu, rs0, 2);
        rs1 += __shfl_xor_sync(0xffffffffu, rs1, 1);
        rs1 += __shfl_xor_sync(0xffffffffu, rs1, 2);
        l0 = l0 * c0 + rs0;
        l1 = l1 * c1 + rs1;

#pragma unroll
        for (int nt2 = 0; nt2 < 4; nt2++) {
            O[nt2][0] *= c0; O[nt2][1] *= c0;
            O[nt2][2] *= c1; O[nt2][3] *= c1;
        }

#pragma unroll
        for (int ks = 0; ks < 16; ks++) {
            uint32_t a[4];
            {
                float v0 = __shfl_sync(0xffffffffu, s[ks][0], src0);
                float v1 = __shfl_sync(0xffffffffu, s[ks][1], src0);
                float v2 = __shfl_sync(0xffffffffu, s[ks][2], src0);
                float v3 = __shfl_sync(0xffffffffu, s[ks][3], src0);
                float u0 = __shfl_sync(0xffffffffu, s[ks][0], src1);
                float u1 = __shfl_sync(0xffffffffu, s[ks][1], src1);
                float u2 = __shfl_sync(0xffffffffu, s[ks][2], src1);
                float u3 = __shfl_sync(0xffffffffu, s[ks][3], src1);
                const bool odd = (tig & 1);
                a[0] = __float_as_uint(odd ? v1 : v0);
                a[1] = __float_as_uint(odd ? v3 : v2);
                a[2] = __float_as_uint(odd ? u1 : u0);
                a[3] = __float_as_uint(odd ? u3 : u2);
            }
#pragma unroll
            for (int nt2 = 0; nt2 < 4; nt2++) {
                uint32_t bfr[2];
                bfr[0] = Vb[(8 * ks + nt2) * 32 + klane];
                bfr[1] = Vb[(8 * ks + 4 + nt2) * 32 + klane];
                mma_tf32(O[nt2], a, bfr);
            }
        }
        __syncthreads();
    }

    const float inv0 = 1.0f / l0;
    const float inv1 = 1.0f / l1;
    const int row0 = b * N_ + q0 + w * 16 + gid;
    const int row1 = row0 + 8;
#pragma unroll
    for (int nt2 = 0; nt2 < 4; nt2++) {
        const int col = h * DK_ + nt2 * 8 + 2 * tig;
        *reinterpret_cast<float2*>(&Out[(size_t)row0 * D_ + col]) =
            make_float2(O[nt2][0] * inv0, O[nt2][1] * inv0);
        *reinterpret_cast<float2*>(&Out[(size_t)row1 * D_ + col]) =
            make_float2(O[nt2][2] * inv1, O[nt2][3] * inv1);
    }
}

// ----------------------------------------------------------------------------
// Fused residual add + LayerNorm (LN1). Two rows per warp; emits fp32 + fp16.
// ----------------------------------------------------------------------------
__global__ __launch_bounds__(256, 6)
void add_ln_kernel(const float* __restrict__ x,
                   const float* __restrict__ delta,
                   const float* __restrict__ g,
                   const float* __restrict__ be,
                   float* __restrict__ out,
                   uint32_t* __restrict__ outh)
{
    const int warp = threadIdx.x >> 5;
    const int lane = threadIdx.x & 31;
    const int rowA = blockIdx.x * 16 + warp * 2;
    const int rowB = rowA + 1;
    const int col0 = lane * 8;

    const float4* xa = reinterpret_cast<const float4*>(&x[(size_t)rowA * D_ + col0]);
    const float4* da = reinterpret_cast<const float4*>(&delta[(size_t)rowA * D_ + col0]);
    const float4* xb = reinterpret_cast<const float4*>(&x[(size_t)rowB * D_ + col0]);
    const float4* db = reinterpret_cast<const float4*>(&delta[(size_t)rowB * D_ + col0]);

    float4 xa0 = xa[0], xa1 = xa[1], xb0 = xb[0], xb1 = xb[1];
    float4 da0 = da[0], da1 = da[1], db0 = db[0], db1 = db[1];

    float ra[8], rb[8];
    ra[0] = xa0.x + da0.x; ra[1] = xa0.y + da0.y; ra[2] = xa0.z + da0.z; ra[3] = xa0.w + da0.w;
    ra[4] = xa1.x + da1.x; ra[5] = xa1.y + da1.y; ra[6] = xa1.z + da1.z; ra[7] = xa1.w + da1.w;
    rb[0] = xb0.x + db0.x; rb[1] = xb0.y + db0.y; rb[2] = xb0.z + db0.z; rb[3] = xb0.w + db0.w;
    rb[4] = xb1.x + db1.x; rb[5] = xb1.y + db1.y; rb[6] = xb1.z + db1.z; rb[7] = xb1.w + db1.w;

    float sa = 0.0f, sb = 0.0f;
#pragma unroll
    for (int j = 0; j < 8; j++) { sa += ra[j]; sb += rb[j]; }
#pragma unroll
    for (int off = 16; off > 0; off >>= 1) {
        sa += __shfl_xor_sync(0xffffffffu, sa, off);
        sb += __shfl_xor_sync(0xffffffffu, sb, off);
    }
    const float meanA = sa * (1.0f / 256.0f);
    const float meanB = sb * (1.0f / 256.0f);

    float va = 0.0f, vb = 0.0f;
#pragma unroll
    for (int j = 0; j < 8; j++) {
        float ta = ra[j] - meanA; va = fmaf(ta, ta, va);
        float tb = rb[j] - meanB; vb = fmaf(tb, tb, vb);
    }
#pragma unroll
    for (int off = 16; off > 0; off >>= 1) {
        va += __shfl_xor_sync(0xffffffffu, va, off);
        vb += __shfl_xor_sync(0xffffffffu, vb, off);
    }
    const float rsA = rsqrtf(va * (1.0f / 256.0f) + 1e-5f);
    const float rsB = rsqrtf(vb * (1.0f / 256.0f) + 1e-5f);

    const float4* gg = reinterpret_cast<const float4*>(&g[col0]);
    const float4* bb = reinterpret_cast<const float4*>(&be[col0]);
    float4 g0 = gg[0], g1 = gg[1], e0 = bb[0], e1 = bb[1];
    const float gv[8] = {g0.x, g0.y, g0.z, g0.w, g1.x, g1.y, g1.z, g1.w};
    const float ev[8] = {e0.x, e0.y, e0.z, e0.w, e1.x, e1.y, e1.z, e1.w};

    float oa[8], ob[8];
#pragma unroll
    for (int j = 0; j < 8; j++) {
        oa[j] = (ra[j] - meanA) * rsA * gv[j] + ev[j];
        ob[j] = (rb[j] - meanB) * rsB * gv[j] + ev[j];
    }

    float4* outA = reinterpret_cast<float4*>(&out[(size_t)rowA * D_ + col0]);
    float4* outB = reinterpret_cast<float4*>(&out[(size_t)rowB * D_ + col0]);
    outA[0] = make_float4(oa[0], oa[1], oa[2], oa[3]);
    outA[1] = make_float4(oa[4], oa[5], oa[6], oa[7]);
    outB[0] = make_float4(ob[0], ob[1], ob[2], ob[3]);
    outB[1] = make_float4(ob[4], ob[5], ob[6], ob[7]);

    uint4 pa, pb;
    pa.x = packh2(oa[0], oa[1]); pa.y = packh2(oa[2], oa[3]);
    pa.z = packh2(oa[4], oa[5]); pa.w = packh2(oa[6], oa[7]);
    pb.x = packh2(ob[0], ob[1]); pb.y = packh2(ob[2], ob[3]);
    pb.z = packh2(ob[4], ob[5]); pb.w = packh2(ob[6], ob[7]);
    *reinterpret_cast<uint4*>(&outh[(size_t)rowA * (D_ / 2) + lane * 4]) = pa;
    *reinterpret_cast<uint4*>(&outh[(size_t)rowB * (D_ / 2) + lane * 4]) = pb;
}

// ----------------------------------------------------------------------------
// Host driver
// ----------------------------------------------------------------------------
extern "C" void kernel_launch(void* const* d_in, const int* in_sizes, int n_in,
                              void* d_out, int out_size)
{
    const float* x      = (const float*)d_in[0];
    const float* coords = (const float*)d_in[1];
    const float* Wq     = (const float*)d_in[2];
    const float* bq     = (const float*)d_in[3];
    const float* Wk     = (const float*)d_in[4];
    const float* bk     = (const float*)d_in[5];
    const float* Wv     = (const float*)d_in[6];
    const float* bv     = (const float*)d_in[7];
    const float* alpha  = (const float*)d_in[8];
    const float* W1     = (const float*)d_in[9];
    const float* b1     = (const float*)d_in[10];
    const float* W2     = (const float*)d_in[11];
    const float* b2     = (const float*)d_in[12];
    const float* g1     = (const float*)d_in[13];
    const float* be1    = (const float*)d_in[14];
    const float* g2     = (const float*)d_in[15];
    const float* be2    = (const float*)d_in[16];
    float* out = (float*)d_out;

    float *Qp, *Ap, *Xp, *KAp, *VAp;
    uint32_t *Xhp, *Hbhp, *Wqhp, *Wkhp, *Wvhp, *W1hp, *W2hp;
    cudaGetSymbolAddress((void**)&Qp,   g_Q);
    cudaGetSymbolAddress((void**)&Ap,   g_ATT);
    cudaGetSymbolAddress((void**)&Xp,   g_X);
    cudaGetSymbolAddress((void**)&KAp,  g_Kaug);
    cudaGetSymbolAddress((void**)&VAp,  g_Vaug);
    cudaGetSymbolAddress((void**)&Xhp,  g_Xh);
    cudaGetSymbolAddress((void**)&Hbhp, g_Hbh);
    cudaGetSymbolAddress((void**)&Wqhp, g_Wqh);
    cudaGetSymbolAddress((void**)&Wkhp, g_Wkh);
    cudaGetSymbolAddress((void**)&Wvhp, g_Wvh);
    cudaGetSymbolAddress((void**)&W1hp, g_W1h);
    cudaGetSymbolAddress((void**)&W2hp, g_W2h);

    cudaFuncSetAttribute(qkv_kernel,
                         cudaFuncAttributeMaxDynamicSharedMemorySize, GEMM_SMEM);
    cudaFuncSetAttribute(ff1_kernel,
                         cudaFuncAttributeMaxDynamicSharedMemorySize, GEMM_SMEM);
    cudaFuncSetAttribute(ff2_ln_kernel,
                         cudaFuncAttributeMaxDynamicSharedMemorySize, FF2_SMEM);
    cudaFuncSetAttribute(attn_mma_kernel,
                         cudaFuncAttributeMaxDynamicSharedMemorySize, ATTN_SMEM);

    const dim3 gQKV(D_ / 128, ROWS / 128, 3);
    const dim3 gFF1(FF_ / 128, ROWS / 128);
    const dim3 gAttn(B_ * H_, N_ / 128);

    // one-time prep (per launch; deterministic)
    fill_kcoords_kernel<<<512, 256>>>(coords, KAp);
    conv_x_kernel<<<ROWS * D_ / 2 / 256, 256>>>(x, Xhp);
    pack_w_kernel<<<L_ * (D_ / 2) * D_ / 256, 256>>>(Wq, Wqhp, D_);
    pack_w_kernel<<<L_ * (D_ / 2) * D_ / 256, 256>>>(Wk, Wkhp, D_);
    pack_w_kernel<<<L_ * (D_ / 2) * D_ / 256, 256>>>(Wv, Wvhp, D_);
    pack_w_kernel<<<L_ * (D_ / 2) * FF_ / 256, 256>>>(W1, W1hp, FF_);
    pack_w_kernel<<<L_ * (FF_ / 2) * D_ / 256, 256>>>(W2, W2hp, D_);

    const float* cur = x;          // fp32 residual source
    const uint32_t* curh = Xhp;    // fp16 GEMM operand
    for (int i = 0; i < L_; i++) {
        qkv_kernel<<<gQKV, 256, GEMM_SMEM>>>(
            curh,
            Wqhp + (size_t)i * (D_ / 2) * D_,
            Wkhp + (size_t)i * (D_ / 2) * D_,
            Wvhp + (size_t)i * (D_ / 2) * D_,
            bq + i * D_, bk + i * D_, bv + i * D_,
            Qp, KAp, VAp);

        attn_mma_kernel<<<gAttn, 256, ATTN_SMEM>>>(Qp, KAp, VAp, coords, alpha, i, Ap);

        add_ln_kernel<<<ROWS / 16, 256>>>(cur, Ap, g1 + i * D_, be1 + i * D_,
                                          Xp, Xhp);

        ff1_kernel<<<gFF1, 256, GEMM_SMEM>>>(
            Xhp, W1hp + (size_t)i * (D_ / 2) * FF_, b1 + i * FF_, Hbhp);

        float* xo = (i == L_ - 1) ? out : Xp;
        ff2_ln_kernel<<<ROWS / 64, 256, FF2_SMEM>>>(
            Hbhp, W2hp + (size_t)i * (FF_ / 2) * D_, b2 + i * D_,
            Xp, g2 + i * D_, be2 + i * D_, xo, Xhp);

        cur = Xp;
        curh = Xhp;
    }
}

// round 15
// speedup vs baseline: 1.5977x; 1.3053x over previous
#include <cuda_runtime.h>
#include <cuda_fp16.h>
#include <cstdint>

// ----------------------------------------------------------------------------
// Problem constants
// ----------------------------------------------------------------------------
constexpr int B_  = 8;
constexpr int N_  = 1024;
constexpr int D_  = 256;
constexpr int H_  = 8;
constexpr int DK_ = 32;
constexpr int FF_ = 1024;
constexpr int L_  = 4;
constexpr int ROWS = B_ * N_;          // 8192 token rows

// ----------------------------------------------------------------------------
// Scratch (device globals: no allocation allowed)
// ----------------------------------------------------------------------------
__device__ float g_Q  [ROWS * D_];
__device__ float g_ATT[ROWS * D_];
__device__ float g_X  [ROWS * D_];
// fp16 packed activations (u32 = half2 along k)
__device__ __align__(16) uint32_t g_Xh [ROWS * D_ / 2];
__device__ __align__(16) uint32_t g_Hbh[ROWS * FF_ / 2];
// fp16 packed weights: [K/2][N] per layer
__device__ __align__(16) uint32_t g_Wqh[L_ * (D_ / 2) * D_];
__device__ __align__(16) uint32_t g_Wkh[L_ * (D_ / 2) * D_];
__device__ __align__(16) uint32_t g_Wvh[L_ * (D_ / 2) * D_];
__device__ __align__(16) uint32_t g_W1h[L_ * (D_ / 2) * FF_];
__device__ __align__(16) uint32_t g_W2h[L_ * (FF_ / 2) * D_];
// Attention fp16 staging (padded row layouts, flat-copyable):
// K' per (bh,kt): 24 kpairs x 136 keys(pad) u32 = 3264
// V  per (bh,kt): 64 keypairs x 40 dk(pad) u32 = 2560
constexpr int KT_U32 = 24 * 136;       // 3264
constexpr int VT_U32 = 64 * 40;        // 2560
__device__ __align__(16) uint32_t g_Khaug[64 * 8 * KT_U32];
__device__ __align__(16) uint32_t g_Vhaug[64 * 8 * VT_U32];

// ----------------------------------------------------------------------------
// Helpers
// ----------------------------------------------------------------------------
__device__ __forceinline__ uint32_t smem_u32(const void* p) {
    return (uint32_t)__cvta_generic_to_shared(p);
}
__device__ __forceinline__ void cp16(uint32_t s, const void* g) {
    asm volatile("cp.async.cg.shared.global [%0], [%1], 16;" :: "r"(s), "l"(g));
}
__device__ __forceinline__ void cp_commit() {
    asm volatile("cp.async.commit_group;" ::: "memory");
}
template <int NN>
__device__ __forceinline__ void cp_wait() {
    asm volatile("cp.async.wait_group %0;" :: "n"(NN) : "memory");
}
__device__ __forceinline__ void mma_f16(float* c, const uint32_t* a, const uint32_t* b) {
    asm volatile(
        "mma.sync.aligned.m16n8k16.row.col.f32.f16.f16.f32 "
        "{%0,%1,%2,%3},{%4,%5,%6,%7},{%8,%9},{%0,%1,%2,%3};"
        : "+f"(c[0]), "+f"(c[1]), "+f"(c[2]), "+f"(c[3])
        : "r"(a[0]), "r"(a[1]), "r"(a[2]), "r"(a[3]), "r"(b[0]), "r"(b[1]));
}
__device__ __forceinline__ uint32_t packh2(float a, float b) {
    __half2 h = __floats2half2_rn(a, b);
    return *reinterpret_cast<uint32_t*>(&h);
}

// ----------------------------------------------------------------------------
// fp16 MMA GEMM core (128x128 tile): 3-stage cp.async pipeline.
// ----------------------------------------------------------------------------
constexpr int A_TILE_U32 = 128 * 32;
constexpr int B_TILE_U32 = 32 * 136;
constexpr int STAGE_U32  = A_TILE_U32 + B_TILE_U32;            // 8448
constexpr int GEMM_SMEM  = 3 * STAGE_U32 * 4;                  // 101376 bytes

__device__ __forceinline__ void gemm_accum_f16(const uint32_t* __restrict__ A,
                                               const uint32_t* __restrict__ Bw,
                                               int Nn, int Kpairs,
                                               float acc[2][8][4])
{
    extern __shared__ uint32_t sm[];

    const int tid  = threadIdx.x;
    const int lane = tid & 31;
    const int warp = tid >> 5;
    const int gid  = lane >> 2;
    const int tig  = lane & 3;
    const int wm   = warp & 3;
    const int wn   = warp >> 2;

    const int rowBase = blockIdx.y * 128;
    const int colBase = blockIdx.x * 128;

    int aR[4], aS[4], bR[4], bS[4], aC4[4], bC4[4];
#pragma unroll
    for (int i = 0; i < 4; i++) {
        int idx = tid + i * 256;
        int r  = idx >> 3;
        int c4 = (idx & 7) << 2;
        aR[i] = r; aS[i] = r * 32 + (c4 ^ ((r & 7) << 2)); aC4[i] = c4;
        int rb  = idx >> 5;
        int cb4 = (idx & 31) << 2;
        bR[i] = rb; bS[i] = rb * 136 + cb4; bC4[i] = cb4;
    }

    auto issue = [&](int t, int buf) {
        const int k0 = t * 32;                 // kpair units
        uint32_t* As = sm + buf * STAGE_U32;
        uint32_t* Bs = As + A_TILE_U32;
#pragma unroll
        for (int i = 0; i < 4; i++)
            cp16(smem_u32(&As[aS[i]]),
                 &A[(size_t)(rowBase + aR[i]) * Kpairs + k0 + aC4[i]]);
#pragma unroll
        for (int i = 0; i < 4; i++)
            cp16(smem_u32(&Bs[bS[i]]),
                 &Bw[(size_t)(k0 + bR[i]) * Nn + colBase + bC4[i]]);
        cp_commit();
    };

#pragma unroll
    for (int mt = 0; mt < 2; mt++)
#pragma unroll
        for (int nt = 0; nt < 8; nt++)
#pragma unroll
            for (int j = 0; j < 4; j++) acc[mt][nt][j] = 0.0f;

    const int T = Kpairs >> 5;
    issue(0, 0);
    issue(1, 1);

    int buf = 0;
    for (int t = 0; t < T; t++) {
        if (t + 1 < T) cp_wait<1>(); else cp_wait<0>();
        __syncthreads();

        const uint32_t* Ab = sm + buf * STAGE_U32;
        const uint32_t* Bb = Ab + A_TILE_U32;

#pragma unroll
        for (int kk = 0; kk < 32; kk += 8) {   // kpair units; 8 kpairs = k16
            uint32_t a[2][4];
#pragma unroll
            for (int mt = 0; mt < 2; mt++) {
                const int m  = wm * 32 + mt * 16 + gid;
                const int sw = (m & 7) << 2;
                const int b0 = m * 32;
                const int b1 = b0 + 8 * 32;
                a[mt][0] = Ab[b0 + (kk ^ sw) + tig];
                a[mt][1] = Ab[b1 + (kk ^ sw) + tig];
                a[mt][2] = Ab[b0 + ((kk + 4) ^ sw) + tig];
                a[mt][3] = Ab[b1 + ((kk + 4) ^ sw) + tig];
            }
            uint32_t b[8][2];
#pragma unroll
            for (int nt = 0; nt < 8; nt++) {
                const int n = wn * 64 + nt * 8 + gid;
                b[nt][0] = Bb[(kk + tig) * 136 + n];
                b[nt][1] = Bb[(kk + tig + 4) * 136 + n];
            }
#pragma unroll
            for (int mt = 0; mt < 2; mt++)
#pragma unroll
                for (int nt = 0; nt < 8; nt++)
                    mma_f16(acc[mt][nt], a[mt], b[nt]);
        }

        if (t + 2 < T) {
            int nbuf = buf + 2; if (nbuf >= 3) nbuf -= 3;
            issue(t + 2, nbuf);
        }
        if (++buf == 3) buf = 0;
    }
}

// ----------------------------------------------------------------------------
// QKV kernel (fp16). z=0: Q plain fp32. z=1: K -> Khaug (packed u32).
// z=2: V -> Vhaug (16-bit stores, key-parity selects half).
// ----------------------------------------------------------------------------
__global__ __launch_bounds__(256, 2)
void qkv_kernel(const uint32_t* __restrict__ Ah,
                const uint32_t* __restrict__ Wqh, const uint32_t* __restrict__ Wkh,
                const uint32_t* __restrict__ Wvh,
                const float* __restrict__ bq, const float* __restrict__ bk,
                const float* __restrict__ bv,
                float* __restrict__ Qo, uint32_t* __restrict__ Khaug,
                uint32_t* __restrict__ Vhaug)
{
    const uint32_t* Bw; const float* bias;
    if (blockIdx.z == 0)      { Bw = Wqh; bias = bq; }
    else if (blockIdx.z == 1) { Bw = Wkh; bias = bk; }
    else                      { Bw = Wvh; bias = bv; }

    float acc[2][8][4];
    gemm_accum_f16(Ah, Bw, D_, D_ / 2, acc);

    const int lane = threadIdx.x & 31;
    const int warp = threadIdx.x >> 5;
    const int gid  = lane >> 2;
    const int tig  = lane & 3;
    const int wm   = warp & 3;
    const int wn   = warp >> 2;
    const int rowBase = blockIdx.y * 128;
    const int colBase = blockIdx.x * 128;

    if (blockIdx.z == 0) {
#pragma unroll
        for (int mt = 0; mt < 2; mt++) {
            const int row0 = rowBase + wm * 32 + mt * 16 + gid;
            const int row1 = row0 + 8;
#pragma unroll
            for (int nt = 0; nt < 8; nt++) {
                const int col = colBase + wn * 64 + nt * 8 + 2 * tig;
                float2 bb = *reinterpret_cast<const float2*>(&bias[col]);
                *reinterpret_cast<float2*>(&Qo[(size_t)row0 * D_ + col]) =
                    make_float2(acc[mt][nt][0] + bb.x, acc[mt][nt][1] + bb.y);
                *reinterpret_cast<float2*>(&Qo[(size_t)row1 * D_ + col]) =
                    make_float2(acc[mt][nt][2] + bb.x, acc[mt][nt][3] + bb.y);
            }
        }
    } else if (blockIdx.z == 1) {
        // K: cols 2tig,2tig+1 are adjacent k -> free half2 pack.
#pragma unroll
        for (int mt = 0; mt < 2; mt++) {
            const int row0 = rowBase + wm * 32 + mt * 16 + gid;
            const int b    = row0 >> 10;
            const int n0   = row0 & 1023;
            const int kt   = n0 >> 7;
            const int key0 = n0 & 127;
            const int key1 = key0 + 8;
#pragma unroll
            for (int nt = 0; nt < 8; nt++) {
                const int col = colBase + wn * 64 + nt * 8 + 2 * tig;
                const int h   = col >> 5;
                const int kp  = (col & 31) >> 1;        // local kpair 0..15
                float2 bb = *reinterpret_cast<const float2*>(&bias[col]);
                const size_t base = (size_t)((b * 8 + h) * 8 + kt) * KT_U32;
                Khaug[base + (size_t)kp * 136 + key0] =
                    packh2(acc[mt][nt][0] + bb.x, acc[mt][nt][1] + bb.y);
                Khaug[base + (size_t)kp * 136 + key1] =
                    packh2(acc[mt][nt][2] + bb.x, acc[mt][nt][3] + bb.y);
            }
        }
    } else {
        // V: key-parity half stores into [keypair][dk(40)] layout.
        __half* Vh = reinterpret_cast<__half*>(Vhaug);
#pragma unroll
        for (int mt = 0; mt < 2; mt++) {
            const int row0 = rowBase + wm * 32 + mt * 16 + gid;
            const int b    = row0 >> 10;
            const int n0   = row0 & 1023;
            const int kt   = n0 >> 7;
            const int key0 = n0 & 127;
            const int key1 = key0 + 8;
#pragma unroll
            for (int nt = 0; nt < 8; nt++) {
                const int col = colBase + wn * 64 + nt * 8 + 2 * tig;
                const int h   = col >> 5;
                const int dk0 = col & 31;
                float2 bb = *reinterpret_cast<const float2*>(&bias[col]);
                const size_t hb = (size_t)((b * 8 + h) * 8 + kt) * (VT_U32 * 2);
#pragma unroll
                for (int e = 0; e < 4; e++) {
                    const int dk  = dk0 + (e & 1);
                    const int key = (e < 2) ? key0 : key1;
                    const float v = acc[mt][nt][e] + ((e & 1) ? bb.y : bb.x);
                    Vh[hb + (size_t)((key >> 1) * 40 + dk) * 2 + (key & 1)] =
                        __float2half_rn(v);
                }
            }
        }
    }
}

// ff1 (fp16): H = relu(X @ W1 + b1), output packed fp16 only.
__global__ __launch_bounds__(256, 2)
void ff1_kernel(const uint32_t* __restrict__ Ah, const uint32_t* __restrict__ Bw,
                const float* __restrict__ bias, uint32_t* __restrict__ Ch)
{
    float acc[2][8][4];
    gemm_accum_f16(Ah, Bw, FF_, D_ / 2, acc);

    const int lane = threadIdx.x & 31;
    const int warp = threadIdx.x >> 5;
    const int gid  = lane >> 2;
    const int tig  = lane & 3;
    const int wm   = warp & 3;
    const int wn   = warp >> 2;
    const int rowBase = blockIdx.y * 128;
    const int colBase = blockIdx.x * 128;

#pragma unroll
    for (int mt = 0; mt < 2; mt++) {
        const int row0 = rowBase + wm * 32 + mt * 16 + gid;
        const int row1 = row0 + 8;
#pragma unroll
        for (int nt = 0; nt < 8; nt++) {
            const int col = colBase + wn * 64 + nt * 8 + 2 * tig;
            float2 bb = *reinterpret_cast<const float2*>(&bias[col]);
            float v0 = fmaxf(acc[mt][nt][0] + bb.x, 0.0f);
            float v1 = fmaxf(acc[mt][nt][1] + bb.y, 0.0f);
            float v2 = fmaxf(acc[mt][nt][2] + bb.x, 0.0f);
            float v3 = fmaxf(acc[mt][nt][3] + bb.y, 0.0f);
            Ch[(size_t)row0 * (FF_ / 2) + (col >> 1)] = packh2(v0, v1);
            Ch[(size_t)row1 * (FF_ / 2) + (col >> 1)] = packh2(v2, v3);
        }
    }
}

// ----------------------------------------------------------------------------
// Fused ff2 + residual + LayerNorm (fp16 mma, fp32 epilogue).
// ----------------------------------------------------------------------------
constexpr int A2_TILE_U32 = 64 * 32;                            // 2048
constexpr int B2_TILE_U32 = 32 * 264;                           // 8448
constexpr int STAGE2_U32  = A2_TILE_U32 + B2_TILE_U32;          // 10496
constexpr int FF2_SMEM    = 3 * STAGE2_U32 * 4;                 // 125952 bytes

__global__ __launch_bounds__(256, 1)
void ff2_ln_kernel(const uint32_t* __restrict__ Hbh,
                   const uint32_t* __restrict__ W2h,
                   const float* __restrict__ b2,
                   const float* __restrict__ X,
                   const float* __restrict__ g,
                   const float* __restrict__ be,
                   float* __restrict__ out,
                   uint32_t* __restrict__ outh)
{
    extern __shared__ uint32_t sm[];

    const int tid  = threadIdx.x;
    const int lane = tid & 31;
    const int warp = tid >> 5;
    const int gid  = lane >> 2;
    const int tig  = lane & 3;
    const int wm   = warp & 1;
    const int wn   = warp >> 1;

    const int rowBase = blockIdx.x * 64;
    constexpr int KP = FF_ / 2;            // 512 kpairs

    int aR[2], aS[2], aC4[2];
#pragma unroll
    for (int i = 0; i < 2; i++) {
        int idx = tid + i * 256;
        int r  = idx >> 3;
        int c4 = (idx & 7) << 2;
        aR[i] = r; aS[i] = r * 32 + (c4 ^ ((r & 7) << 2)); aC4[i] = c4;
    }
    int bR[8], bS[8], bC4[8];
#pragma unroll
    for (int i = 0; i < 8; i++) {
        int idx = tid + i * 256;
        int rb  = idx >> 6;
        int cb4 = (idx & 63) << 2;
        bR[i] = rb; bS[i] = rb * 264 + cb4; bC4[i] = cb4;
    }

    auto issue = [&](int t, int buf) {
        const int k0 = t * 32;             // kpair units
        uint32_t* As = sm + buf * STAGE2_U32;
        uint32_t* Bs = As + A2_TILE_U32;
#pragma unroll
        for (int i = 0; i < 2; i++)
            cp16(smem_u32(&As[aS[i]]),
                 &Hbh[(size_t)(rowBase + aR[i]) * KP + k0 + aC4[i]]);
#pragma unroll
        for (int i = 0; i < 8; i++)
            cp16(smem_u32(&Bs[bS[i]]),
                 &W2h[(size_t)(k0 + bR[i]) * D_ + bC4[i]]);
        cp_commit();
    };

    float acc[2][8][4];
#pragma unroll
    for (int mt = 0; mt < 2; mt++)
#pragma unroll
        for (int nt = 0; nt < 8; nt++)
#pragma unroll
            for (int j = 0; j < 4; j++) acc[mt][nt][j] = 0.0f;

    const int T = KP >> 5;                 // 16
    issue(0, 0);
    issue(1, 1);

    int buf = 0;
    for (int t = 0; t < T; t++) {
        if (t + 1 < T) cp_wait<1>(); else cp_wait<0>();
        __syncthreads();

        const uint32_t* Ab = sm + buf * STAGE2_U32;
        const uint32_t* Bb = Ab + A2_TILE_U32;

#pragma unroll
        for (int kk = 0; kk < 32; kk += 8) {
            uint32_t a[2][4];
#pragma unroll
            for (int mt = 0; mt < 2; mt++) {
                const int m  = wm * 32 + mt * 16 + gid;
                const int sw = (m & 7) << 2;
                const int b0 = m * 32;
                const int b1 = b0 + 8 * 32;
                a[mt][0] = Ab[b0 + (kk ^ sw) + tig];
                a[mt][1] = Ab[b1 + (kk ^ sw) + tig];
                a[mt][2] = Ab[b0 + ((kk + 4) ^ sw) + tig];
                a[mt][3] = Ab[b1 + ((kk + 4) ^ sw) + tig];
            }
            uint32_t b[8][2];
#pragma unroll
            for (int nt = 0; nt < 8; nt++) {
                const int n = wn * 64 + nt * 8 + gid;
                b[nt][0] = Bb[(kk + tig) * 264 + n];
                b[nt][1] = Bb[(kk + tig + 4) * 264 + n];
            }
#pragma unroll
            for (int mt = 0; mt < 2; mt++)
#pragma unroll
                for (int nt = 0; nt < 8; nt++)
                    mma_f16(acc[mt][nt], a[mt], b[nt]);
        }

        if (t + 2 < T) {
            int nbuf = buf + 2; if (nbuf >= 3) nbuf -= 3;
            issue(t + 2, nbuf);
        }
        if (++buf == 3) buf = 0;
    }

    // ---- epilogue: bias + residual, per-row mean/var, LN, fp32 + fp16 out ----
    __syncthreads();
    float* red = reinterpret_cast<float*>(sm);

#pragma unroll
    for (int mt = 0; mt < 2; mt++) {
        const int rloc0 = wm * 32 + mt * 16 + gid;
        const int rloc1 = rloc0 + 8;
        float s0 = 0.0f, q0 = 0.0f, s1 = 0.0f, q1 = 0.0f;
#pragma unroll
        for (int nt = 0; nt < 8; nt++) {
            const int col = wn * 64 + nt * 8 + 2 * tig;
            float2 bb = *reinterpret_cast<const float2*>(&b2[col]);
            float2 x0 = *reinterpret_cast<const float2*>(
                &X[(size_t)(rowBase + rloc0) * D_ + col]);
            float2 x1 = *reinterpret_cast<const float2*>(
                &X[(size_t)(rowBase + rloc1) * D_ + col]);
            float v0 = acc[mt][nt][0] + bb.x + x0.x;
            float v1 = acc[mt][nt][1] + bb.y + x0.y;
            float v2 = acc[mt][nt][2] + bb.x + x1.x;
            float v3 = acc[mt][nt][3] + bb.y + x1.y;
            acc[mt][nt][0] = v0; acc[mt][nt][1] = v1;
            acc[mt][nt][2] = v2; acc[mt][nt][3] = v3;
            s0 += v0 + v1; q0 = fmaf(v0, v0, fmaf(v1, v1, q0));
            s1 += v2 + v3; q1 = fmaf(v2, v2, fmaf(v3, v3, q1));
        }
        s0 += __shfl_xor_sync(0xffffffffu, s0, 1);
        s0 += __shfl_xor_sync(0xffffffffu, s0, 2);
        q0 += __shfl_xor_sync(0xffffffffu, q0, 1);
        q0 += __shfl_xor_sync(0xffffffffu, q0, 2);
        s1 += __shfl_xor_sync(0xffffffffu, s1, 1);
        s1 += __shfl_xor_sync(0xffffffffu, s1, 2);
        q1 += __shfl_xor_sync(0xffffffffu, q1, 1);
        q1 += __shfl_xor_sync(0xffffffffu, q1, 2);
        if (tig == 0) {
            red[rloc0 * 8 + wn * 2 + 0] = s0;
            red[rloc0 * 8 + wn * 2 + 1] = q0;
            red[rloc1 * 8 + wn * 2 + 0] = s1;
            red[rloc1 * 8 + wn * 2 + 1] = q1;
        }
    }
    __syncthreads();

#pragma unroll
    for (int mt = 0; mt < 2; mt++) {
#pragma unroll
        for (int rr = 0; rr < 2; rr++) {
            const int rloc = wm * 32 + mt * 16 + gid + rr * 8;
            const float* rp = &red[rloc * 8];
            const float sum = rp[0] + rp[2] + rp[4] + rp[6];
            const float sq  = rp[1] + rp[3] + rp[5] + rp[7];
            const float mean = sum * (1.0f / 256.0f);
            const float var  = sq * (1.0f / 256.0f) - mean * mean;
            const float rs   = rsqrtf(var + 1e-5f);
            const int row = rowBase + rloc;
#pragma unroll
            for (int nt = 0; nt < 8; nt++) {
                const int col = wn * 64 + nt * 8 + 2 * tig;
                float2 gv = *reinterpret_cast<const float2*>(&g[col]);
                float2 ev = *reinterpret_cast<const float2*>(&be[col]);
                const float a0 = acc[mt][nt][rr * 2 + 0];
                const float a1 = acc[mt][nt][rr * 2 + 1];
                const float o0 = (a0 - mean) * rs * gv.x + ev.x;
                const float o1 = (a1 - mean) * rs * gv.y + ev.y;
                *reinterpret_cast<float2*>(&out[(size_t)row * D_ + col]) =
                    make_float2(o0, o1);
                outh[(size_t)row * (D_ / 2) + (col >> 1)] = packh2(o0, o1);
            }
        }
    }
}

// ----------------------------------------------------------------------------
// One-time prep kernels
// ----------------------------------------------------------------------------
__global__ __launch_bounds__(256)
void pack_w_kernel(const float* __restrict__ W, uint32_t* __restrict__ out, int Nn)
{
    const int idx = blockIdx.x * 256 + threadIdx.x;
    const int kp  = idx / Nn;
    const int n   = idx - kp * Nn;
    out[idx] = packh2(W[(size_t)(2 * kp) * Nn + n],
                      W[(size_t)(2 * kp + 1) * Nn + n]);
}

__global__ __launch_bounds__(256)
void conv_x_kernel(const float* __restrict__ x, uint32_t* __restrict__ Xh)
{
    const int idx = blockIdx.x * 256 + threadIdx.x;
    float2 v = reinterpret_cast<const float2*>(x)[idx];
    Xh[idx] = packh2(v.x, v.y);
}

// Fill Khaug coords rows (kpair 16..23): layer-invariant.
// Grid 512 = bh*8+kt; 1088 u32 per tile (8 rows x 136).
__global__ __launch_bounds__(256)
void fill_kcoords_kernel(const float* __restrict__ coords,
                         uint32_t* __restrict__ Khaug)
{
    const int t  = blockIdx.x;
    const int kt = t & 7;
    const int b  = (t >> 3) >> 3;
    uint32_t* base = Khaug + (size_t)t * KT_U32 + 16 * 136;
    for (int idx = threadIdx.x; idx < 8 * 136; idx += 256) {
        const int r   = idx / 136;      // 0..7 -> kpair 16+r
        const int key = idx - r * 136;
        uint32_t v = 0;
        if (key < 128) {
            const float* c = &coords[(size_t)(b * N_ + kt * 128 + key) * 3];
            if (r == 0)      v = packh2(c[0], c[1]);
            else if (r == 1) v = packh2(c[2], 0.0f);
        }
        base[idx] = v;
    }
}

// ----------------------------------------------------------------------------
// fp16 MMA flash attention. 2 CTAs/SM.
// S = Q'K'^T (DK'=48, 3 k16-steps), P packed C->A identity, O += P@V.
// ----------------------------------------------------------------------------
constexpr int TILE_U32A = KT_U32 + VT_U32;          // 5824
constexpr int ATTN_SMEM = 2 * TILE_U32A * 4;        // 46592

__global__ __launch_bounds__(256, 2)
void attn_f16_kernel(const float* __restrict__ Q,
                     const uint32_t* __restrict__ Khaug,
                     const uint32_t* __restrict__ Vhaug,
                     const float* __restrict__ coords,
                     const float* __restrict__ alpha,
                     int layer,
                     float* __restrict__ Out)
{
    extern __shared__ uint32_t smu[];

    const int tid  = threadIdx.x;
    const int lane = tid & 31;
    const int w    = tid >> 5;
    const int gid  = lane >> 2;
    const int tig  = lane & 3;

    const int bh = blockIdx.x;
    const int b  = bh >> 3;
    const int h  = bh & 7;
    const int q0 = blockIdx.y * 128;

    const float scale  = 0.17677669529663687f;
    const float alphav = alpha[layer];

    // Q' fragments: 3 k16-steps over DK'=48 (kk>=35 zero)
    uint32_t qf[3][4];
    {
        const int row0 = b * N_ + q0 + w * 16 + gid;
        auto qval = [&](int row, int kk) -> float {
            if (kk < 32)  return Q[(size_t)row * D_ + h * DK_ + kk] * scale;
            if (kk < 35)  return alphav * coords[(size_t)row * 3 + (kk - 32)];
            return 0.0f;
        };
#pragma unroll
        for (int ks = 0; ks < 3; ks++) {
#pragma unroll
            for (int r = 0; r < 4; r++) {
                const int row = row0 + (r & 1) * 8;
                const int kk  = ks * 16 + 2 * tig + ((r >> 1) << 3);
                qf[ks][r] = packh2(qval(row, kk), qval(row, kk + 1));
            }
        }
    }

    auto issue = [&](int t, int buf) {
        const uint32_t* srcK = Khaug + (size_t)(bh * 8 + t) * KT_U32;
        uint32_t* dst = smu + buf * TILE_U32A;
#pragma unroll
        for (int j = 0; j < 3; j++) {
            const int i16 = tid + j * 256;     // f4 units; KT = 816 f4
            cp16(smem_u32(dst + i16 * 4), srcK + i16 * 4);
        }
        if (tid < 48)
            cp16(smem_u32(dst + (768 + tid) * 4), srcK + (768 + tid) * 4);
        const uint32_t* srcV = Vhaug + (size_t)(bh * 8 + t) * VT_U32;
        uint32_t* dstV = dst + KT_U32;
#pragma unroll
        for (int j = 0; j < 2; j++) {
            const int i16 = tid + j * 256;     // VT = 640 f4
            cp16(smem_u32(dstV + i16 * 4), srcV + i16 * 4);
        }
        if (tid < 128)
            cp16(smem_u32(dstV + (512 + tid) * 4), srcV + (512 + tid) * 4);
        cp_commit();
    };

    float O[4][4];
#pragma unroll
    for (int i = 0; i < 4; i++)
#pragma unroll
        for (int j = 0; j < 4; j++) O[i][j] = 0.0f;
    float m0 = -1e30f, m1 = -1e30f, l0 = 0.0f, l1 = 0.0f;

    issue(0, 0);

    for (int t = 0; t < 8; t++) {
        if (t < 7) { issue(t + 1, (t + 1) & 1); cp_wait<1>(); }
        else       { cp_wait<0>(); }
        __syncthreads();

        const uint32_t* Kb = smu + (t & 1) * TILE_U32A;
        const uint32_t* Vb = Kb + KT_U32;

        // ---- S = Q' @ K'^T: 3 ksteps x 16 n-tiles ----
        float s[16][4];
#pragma unroll
        for (int nt = 0; nt < 16; nt++)
#pragma unroll
            for (int j = 0; j < 4; j++) s[nt][j] = 0.0f;

#pragma unroll
        for (int ks = 0; ks < 3; ks++) {
#pragma unroll
            for (int nt = 0; nt < 16; nt++) {
                uint32_t bfr[2];
                const int key = nt * 8 + gid;
                bfr[0] = Kb[(ks * 8 + tig) * 136 + key];
                bfr[1] = Kb[(ks * 8 + 4 + tig) * 136 + key];
                mma_f16(s[nt], qf[ks], bfr);
            }
        }

        // ---- online softmax ----
        float mx0 = -1e30f, mx1 = -1e30f;
#pragma unroll
        for (int nt = 0; nt < 16; nt++) {
            mx0 = fmaxf(mx0, fmaxf(s[nt][0], s[nt][1]));
            mx1 = fmaxf(mx1, fmaxf(s[nt][2], s[nt][3]));
        }
        mx0 = fmaxf(mx0, __shfl_xor_sync(0xffffffffu, mx0, 1));
        mx0 = fmaxf(mx0, __shfl_xor_sync(0xffffffffu, mx0, 2));
        mx1 = fmaxf(mx1, __shfl_xor_sync(0xffffffffu, mx1, 1));
        mx1 = fmaxf(mx1, __shfl_xor_sync(0xffffffffu, mx1, 2));

        const float mn0 = fmaxf(m0, mx0);
        const float mn1 = fmaxf(m1, mx1);
        const float c0  = __expf(m0 - mn0);
        const float c1  = __expf(m1 - mn1);
        m0 = mn0; m1 = mn1;

        float rs0 = 0.0f, rs1 = 0.0f;
#pragma unroll
        for (int nt = 0; nt < 16; nt++) {
            s[nt][0] = __expf(s[nt][0] - mn0);
            s[nt][1] = __expf(s[nt][1] - mn0);
            s[nt][2] = __expf(s[nt][2] - mn1);
            s[nt][3] = __expf(s[nt][3] - mn1);
            rs0 += s[nt][0] + s[nt][1];
            rs1 += s[nt][2] + s[nt][3];
        }
        rs0 += __shfl_xor_sync(0xffffffffu, rs0, 1);
        rs0 += __shfl_xor_sync(0xffffffffu, rs0, 2);
        rs1 += __shfl_xor_sync(0xffffffffu, rs1, 1);
        rs1 += __shfl_xor_sync(0xffffffffu, rs1, 2);
        l0 = l0 * c0 + rs0;
        l1 = l1 * c1 + rs1;

#pragma unroll
        for (int nt2 = 0; nt2 < 4; nt2++) {
            O[nt2][0] *= c0; O[nt2][1] *= c0;
            O[nt2][2] *= c1; O[nt2][3] *= c1;
        }

        // ---- O += P @ V: C->A fragment identity, no shuffles ----
#pragma unroll
        for (int ks = 0; ks < 8; ks++) {
            uint32_t a[4];
            a[0] = packh2(s[2 * ks][0],     s[2 * ks][1]);
            a[1] = packh2(s[2 * ks][2],     s[2 * ks][3]);
            a[2] = packh2(s[2 * ks + 1][0], s[2 * ks + 1][1]);
            a[3] = packh2(s[2 * ks + 1][2], s[2 * ks + 1][3]);
#pragma unroll
            for (int nt2 = 0; nt2 < 4; nt2++) {
                uint32_t bfr[2];
                const int dk = nt2 * 8 + gid;
                bfr[0] = Vb[(ks * 8 + tig) * 40 + dk];
                bfr[1] = Vb[(ks * 8 + 4 + tig) * 40 + dk];
                mma_f16(O[nt2], a, bfr);
            }
        }
        __syncthreads();
    }

    const float inv0 = 1.0f / l0;
    const float inv1 = 1.0f / l1;
    const int row0 = b * N_ + q0 + w * 16 + gid;
    const int row1 = row0 + 8;
#pragma unroll
    for (int nt2 = 0; nt2 < 4; nt2++) {
        const int col = h * DK_ + nt2 * 8 + 2 * tig;
        *reinterpret_cast<float2*>(&Out[(size_t)row0 * D_ + col]) =
            make_float2(O[nt2][0] * inv0, O[nt2][1] * inv0);
        *reinterpret_cast<float2*>(&Out[(size_t)row1 * D_ + col]) =
            make_float2(O[nt2][2] * inv1, O[nt2][3] * inv1);
    }
}

// ----------------------------------------------------------------------------
// Fused residual add + LayerNorm (LN1). Two rows per warp; emits fp32 + fp16.
// ----------------------------------------------------------------------------
__global__ __launch_bounds__(256, 6)
void add_ln_kernel(const float* __restrict__ x,
                   const float* __restrict__ delta,
                   const float* __restrict__ g,
                   const float* __restrict__ be,
                   float* __restrict__ out,
                   uint32_t* __restrict__ outh)
{
    const int warp = threadIdx.x >> 5;
    const int lane = threadIdx.x & 31;
    const int rowA = blockIdx.x * 16 + warp * 2;
    const int rowB = rowA + 1;
    const int col0 = lane * 8;

    const float4* xa = reinterpret_cast<const float4*>(&x[(size_t)rowA * D_ + col0]);
    const float4* da = reinterpret_cast<const float4*>(&delta[(size_t)rowA * D_ + col0]);
    const float4* xb = reinterpret_cast<const float4*>(&x[(size_t)rowB * D_ + col0]);
    const float4* db = reinterpret_cast<const float4*>(&delta[(size_t)rowB * D_ + col0]);

    float4 xa0 = xa[0], xa1 = xa[1], xb0 = xb[0], xb1 = xb[1];
    float4 da0 = da[0], da1 = da[1], db0 = db[0], db1 = db[1];

    float ra[8], rb[8];
    ra[0] = xa0.x + da0.x; ra[1] = xa0.y + da0.y; ra[2] = xa0.z + da0.z; ra[3] = xa0.w + da0.w;
    ra[4] = xa1.x + da1.x; ra[5] = xa1.y + da1.y; ra[6] = xa1.z + da1.z; ra[7] = xa1.w + da1.w;
    rb[0] = xb0.x + db0.x; rb[1] = xb0.y + db0.y; rb[2] = xb0.z + db0.z; rb[3] = xb0.w + db0.w;
    rb[4] = xb1.x + db1.x; rb[5] = xb1.y + db1.y; rb[6] = xb1.z + db1.z; rb[7] = xb1.w + db1.w;

    float sa = 0.0f, sb = 0.0f;
#pragma unroll
    for (int j = 0; j < 8; j++) { sa += ra[j]; sb += rb[j]; }
#pragma unroll
    for (int off = 16; off > 0; off >>= 1) {
        sa += __shfl_xor_sync(0xffffffffu, sa, off);
        sb += __shfl_xor_sync(0xffffffffu, sb, off);
    }
    const float meanA = sa * (1.0f / 256.0f);
    const float meanB = sb * (1.0f / 256.0f);

    float va = 0.0f, vb = 0.0f;
#pragma unroll
    for (int j = 0; j < 8; j++) {
        float ta = ra[j] - meanA; va = fmaf(ta, ta, va);
        float tb = rb[j] - meanB; vb = fmaf(tb, tb, vb);
    }
#pragma unroll
    for (int off = 16; off > 0; off >>= 1) {
        va += __shfl_xor_sync(0xffffffffu, va, off);
        vb += __shfl_xor_sync(0xffffffffu, vb, off);
    }
    const float rsA = rsqrtf(va * (1.0f / 256.0f) + 1e-5f);
    const float rsB = rsqrtf(vb * (1.0f / 256.0f) + 1e-5f);

    const float4* gg = reinterpret_cast<const float4*>(&g[col0]);
    const float4* bb = reinterpret_cast<const float4*>(&be[col0]);
    float4 g0 = gg[0], g1 = gg[1], e0 = bb[0], e1 = bb[1];
    const float gv[8] = {g0.x, g0.y, g0.z, g0.w, g1.x, g1.y, g1.z, g1.w};
    const float ev[8] = {e0.x, e0.y, e0.z, e0.w, e1.x, e1.y, e1.z, e1.w};

    float oa[8], ob[8];
#pragma unroll
    for (int j = 0; j < 8; j++) {
        oa[j] = (ra[j] - meanA) * rsA * gv[j] + ev[j];
        ob[j] = (rb[j] - meanB) * rsB * gv[j] + ev[j];
    }

    float4* outA = reinterpret_cast<float4*>(&out[(size_t)rowA * D_ + col0]);
    float4* outB = reinterpret_cast<float4*>(&out[(size_t)rowB * D_ + col0]);
    outA[0] = make_float4(oa[0], oa[1], oa[2], oa[3]);
    outA[1] = make_float4(oa[4], oa[5], oa[6], oa[7]);
    outB[0] = make_float4(ob[0], ob[1], ob[2], ob[3]);
    outB[1] = make_float4(ob[4], ob[5], ob[6], ob[7]);

    uint4 pa, pb;
    pa.x = packh2(oa[0], oa[1]); pa.y = packh2(oa[2], oa[3]);
    pa.z = packh2(oa[4], oa[5]); pa.w = packh2(oa[6], oa[7]);
    pb.x = packh2(ob[0], ob[1]); pb.y = packh2(ob[2], ob[3]);
    pb.z = packh2(ob[4], ob[5]); pb.w = packh2(ob[6], ob[7]);
    *reinterpret_cast<uint4*>(&outh[(size_t)rowA * (D_ / 2) + lane * 4]) = pa;
    *reinterpret_cast<uint4*>(&outh[(size_t)rowB * (D_ / 2) + lane * 4]) = pb;
}

// ----------------------------------------------------------------------------
// Host driver
// ----------------------------------------------------------------------------
extern "C" void kernel_launch(void* const* d_in, const int* in_sizes, int n_in,
                              void* d_out, int out_size)
{
    const float* x      = (const float*)d_in[0];
    const float* coords = (const float*)d_in[1];
    const float* Wq     = (const float*)d_in[2];
    const float* bq     = (const float*)d_in[3];
    const float* Wk     = (const float*)d_in[4];
    const float* bk     = (const float*)d_in[5];
    const float* Wv     = (const float*)d_in[6];
    const float* bv     = (const float*)d_in[7];
    const float* alpha  = (const float*)d_in[8];
    const float* W1     = (const float*)d_in[9];
    const float* b1     = (const float*)d_in[10];
    const float* W2     = (const float*)d_in[11];
    const float* b2     = (const float*)d_in[12];
    const float* g1     = (const float*)d_in[13];
    const float* be1    = (const float*)d_in[14];
    const float* g2     = (const float*)d_in[15];
    const float* be2    = (const float*)d_in[16];
    float* out = (float*)d_out;

    float *Qp, *Ap, *Xp;
    uint32_t *Xhp, *Hbhp, *Wqhp, *Wkhp, *Wvhp, *W1hp, *W2hp, *Khp, *Vhp;
    cudaGetSymbolAddress((void**)&Qp,   g_Q);
    cudaGetSymbolAddress((void**)&Ap,   g_ATT);
    cudaGetSymbolAddress((void**)&Xp,   g_X);
    cudaGetSymbolAddress((void**)&Xhp,  g_Xh);
    cudaGetSymbolAddress((void**)&Hbhp, g_Hbh);
    cudaGetSymbolAddress((void**)&Wqhp, g_Wqh);
    cudaGetSymbolAddress((void**)&Wkhp, g_Wkh);
    cudaGetSymbolAddress((void**)&Wvhp, g_Wvh);
    cudaGetSymbolAddress((void**)&W1hp, g_W1h);
    cudaGetSymbolAddress((void**)&W2hp, g_W2h);
    cudaGetSymbolAddress((void**)&Khp,  g_Khaug);
    cudaGetSymbolAddress((void**)&Vhp,  g_Vhaug);

    cudaFuncSetAttribute(qkv_kernel,
                         cudaFuncAttributeMaxDynamicSharedMemorySize, GEMM_SMEM);
    cudaFuncSetAttribute(ff1_kernel,
                         cudaFuncAttributeMaxDynamicSharedMemorySize, GEMM_SMEM);
    cudaFuncSetAttribute(ff2_ln_kernel,
                         cudaFuncAttributeMaxDynamicSharedMemorySize, FF2_SMEM);
    cudaFuncSetAttribute(attn_f16_kernel,
                         cudaFuncAttributeMaxDynamicSharedMemorySize, ATTN_SMEM);

    const dim3 gQKV(D_ / 128, ROWS / 128, 3);
    const dim3 gFF1(FF_ / 128, ROWS / 128);
    const dim3 gAttn(B_ * H_, N_ / 128);

    // one-time prep (per launch; deterministic)
    fill_kcoords_kernel<<<512, 256>>>(coords, Khp);
    conv_x_kernel<<<ROWS * D_ / 2 / 256, 256>>>(x, Xhp);
    pack_w_kernel<<<L_ * (D_ / 2) * D_ / 256, 256>>>(Wq, Wqhp, D_);
    pack_w_kernel<<<L_ * (D_ / 2) * D_ / 256, 256>>>(Wk, Wkhp, D_);
    pack_w_kernel<<<L_ * (D_ / 2) * D_ / 256, 256>>>(Wv, Wvhp, D_);
    pack_w_kernel<<<L_ * (D_ / 2) * FF_ / 256, 256>>>(W1, W1hp, FF_);
    pack_w_kernel<<<L_ * (FF_ / 2) * D_ / 256, 256>>>(W2, W2hp, D_);

    const float* cur = x;          // fp32 residual source
    const uint32_t* curh = Xhp;    // fp16 GEMM operand
    for (int i = 0; i < L_; i++) {
        qkv_kernel<<<gQKV, 256, GEMM_SMEM>>>(
            curh,
            Wqhp + (size_t)i * (D_ / 2) * D_,
            Wkhp + (size_t)i * (D_ / 2) * D_,
            Wvhp + (size_t)i * (D_ / 2) * D_,
            bq + i * D_, bk + i * D_, bv + i * D_,
            Qp, Khp, Vhp);

        attn_f16_kernel<<<gAttn, 256, ATTN_SMEM>>>(Qp, Khp, Vhp, coords, alpha, i, Ap);

        add_ln_kernel<<<ROWS / 16, 256>>>(cur, Ap, g1 + i * D_, be1 + i * D_,
                                          Xp, Xhp);

        ff1_kernel<<<gFF1, 256, GEMM_SMEM>>>(
            Xhp, W1hp + (size_t)i * (D_ / 2) * FF_, b1 + i * FF_, Hbhp);

        float* xo = (i == L_ - 1) ? out : Xp;
        ff2_ln_kernel<<<ROWS / 64, 256, FF2_SMEM>>>(
            Hbhp, W2hp + (size_t)i * (FF_ / 2) * D_, b2 + i * D_,
            Xp, g2 + i * D_, be2 + i * D_, xo, Xhp);

        cur = Xp;
        curh = Xhp;
    }
}

// round 16
// speedup vs baseline: 1.6701x; 1.0453x over previous
#include <cuda_runtime.h>
#include <cuda_fp16.h>
#include <cstdint>

// ----------------------------------------------------------------------------
// Problem constants
// ----------------------------------------------------------------------------
constexpr int B_  = 8;
constexpr int N_  = 1024;
constexpr int D_  = 256;
constexpr int H_  = 8;
constexpr int DK_ = 32;
constexpr int FF_ = 1024;
constexpr int L_  = 4;
constexpr int ROWS = B_ * N_;          // 8192 token rows

// ----------------------------------------------------------------------------
// Scratch (device globals: no allocation allowed)
// ----------------------------------------------------------------------------
__device__ float g_X  [ROWS * D_];
// fp16 packed activations (u32 = half2 along k)
__device__ __align__(16) uint32_t g_Xh  [ROWS * D_ / 2];
__device__ __align__(16) uint32_t g_Hbh [ROWS * FF_ / 2];
__device__ __align__(16) uint32_t g_Qh  [ROWS * D_ / 2];   // pre-scaled Q
__device__ __align__(16) uint32_t g_ATTh[ROWS * D_ / 2];   // attention out
// fp16 packed weights: [K/2][N] per layer
__device__ __align__(16) uint32_t g_Wqh[L_ * (D_ / 2) * D_];
__device__ __align__(16) uint32_t g_Wkh[L_ * (D_ / 2) * D_];
__device__ __align__(16) uint32_t g_Wvh[L_ * (D_ / 2) * D_];
__device__ __align__(16) uint32_t g_W1h[L_ * (D_ / 2) * FF_];
__device__ __align__(16) uint32_t g_W2h[L_ * (FF_ / 2) * D_];
// Attention fp16 staging:
// K' per (bh,kt): 24 kpairs x 136 keys(pad) u32; V: 64 keypairs x 40 dk(pad)
constexpr int KT_U32 = 24 * 136;       // 3264
constexpr int VT_U32 = 64 * 40;        // 2560
__device__ __align__(16) uint32_t g_Khaug[64 * 8 * KT_U32];
__device__ __align__(16) uint32_t g_Vhaug[64 * 8 * VT_U32];

// ----------------------------------------------------------------------------
// Helpers
// ----------------------------------------------------------------------------
__device__ __forceinline__ uint32_t smem_u32(const void* p) {
    return (uint32_t)__cvta_generic_to_shared(p);
}
__device__ __forceinline__ void cp16(uint32_t s, const void* g) {
    asm volatile("cp.async.cg.shared.global [%0], [%1], 16;" :: "r"(s), "l"(g));
}
__device__ __forceinline__ void cp_commit() {
    asm volatile("cp.async.commit_group;" ::: "memory");
}
template <int NN>
__device__ __forceinline__ void cp_wait() {
    asm volatile("cp.async.wait_group %0;" :: "n"(NN) : "memory");
}
__device__ __forceinline__ void mma_f16(float* c, const uint32_t* a, const uint32_t* b) {
    asm volatile(
        "mma.sync.aligned.m16n8k16.row.col.f32.f16.f16.f32 "
        "{%0,%1,%2,%3},{%4,%5,%6,%7},{%8,%9},{%0,%1,%2,%3};"
        : "+f"(c[0]), "+f"(c[1]), "+f"(c[2]), "+f"(c[3])
        : "r"(a[0]), "r"(a[1]), "r"(a[2]), "r"(a[3]), "r"(b[0]), "r"(b[1]));
}
__device__ __forceinline__ uint32_t packh2(float a, float b) {
    __half2 h = __floats2half2_rn(a, b);
    return *reinterpret_cast<uint32_t*>(&h);
}

// ----------------------------------------------------------------------------
// fp16 MMA GEMM core (128x128 tile): 3-stage cp.async pipeline.
// ----------------------------------------------------------------------------
constexpr int A_TILE_U32 = 128 * 32;
constexpr int B_TILE_U32 = 32 * 136;
constexpr int STAGE_U32  = A_TILE_U32 + B_TILE_U32;            // 8448
constexpr int GEMM_SMEM  = 3 * STAGE_U32 * 4;                  // 101376 bytes

__device__ __forceinline__ void gemm_accum_f16(const uint32_t* __restrict__ A,
                                               const uint32_t* __restrict__ Bw,
                                               int Nn, int Kpairs,
                                               float acc[2][8][4])
{
    extern __shared__ uint32_t sm[];

    const int tid  = threadIdx.x;
    const int lane = tid & 31;
    const int warp = tid >> 5;
    const int gid  = lane >> 2;
    const int tig  = lane & 3;
    const int wm   = warp & 3;
    const int wn   = warp >> 2;

    const int rowBase = blockIdx.y * 128;
    const int colBase = blockIdx.x * 128;

    int aR[4], aS[4], bR[4], bS[4], aC4[4], bC4[4];
#pragma unroll
    for (int i = 0; i < 4; i++) {
        int idx = tid + i * 256;
        int r  = idx >> 3;
        int c4 = (idx & 7) << 2;
        aR[i] = r; aS[i] = r * 32 + (c4 ^ ((r & 7) << 2)); aC4[i] = c4;
        int rb  = idx >> 5;
        int cb4 = (idx & 31) << 2;
        bR[i] = rb; bS[i] = rb * 136 + cb4; bC4[i] = cb4;
    }

    auto issue = [&](int t, int buf) {
        const int k0 = t * 32;                 // kpair units
        uint32_t* As = sm + buf * STAGE_U32;
        uint32_t* Bs = As + A_TILE_U32;
#pragma unroll
        for (int i = 0; i < 4; i++)
            cp16(smem_u32(&As[aS[i]]),
                 &A[(size_t)(rowBase + aR[i]) * Kpairs + k0 + aC4[i]]);
#pragma unroll
        for (int i = 0; i < 4; i++)
            cp16(smem_u32(&Bs[bS[i]]),
                 &Bw[(size_t)(k0 + bR[i]) * Nn + colBase + bC4[i]]);
        cp_commit();
    };

#pragma unroll
    for (int mt = 0; mt < 2; mt++)
#pragma unroll
        for (int nt = 0; nt < 8; nt++)
#pragma unroll
            for (int j = 0; j < 4; j++) acc[mt][nt][j] = 0.0f;

    const int T = Kpairs >> 5;
    issue(0, 0);
    issue(1, 1);

    int buf = 0;
    for (int t = 0; t < T; t++) {
        if (t + 1 < T) cp_wait<1>(); else cp_wait<0>();
        __syncthreads();

        const uint32_t* Ab = sm + buf * STAGE_U32;
        const uint32_t* Bb = Ab + A_TILE_U32;

#pragma unroll
        for (int kk = 0; kk < 32; kk += 8) {
            uint32_t a[2][4];
#pragma unroll
            for (int mt = 0; mt < 2; mt++) {
                const int m  = wm * 32 + mt * 16 + gid;
                const int sw = (m & 7) << 2;
                const int b0 = m * 32;
                const int b1 = b0 + 8 * 32;
                a[mt][0] = Ab[b0 + (kk ^ sw) + tig];
                a[mt][1] = Ab[b1 + (kk ^ sw) + tig];
                a[mt][2] = Ab[b0 + ((kk + 4) ^ sw) + tig];
                a[mt][3] = Ab[b1 + ((kk + 4) ^ sw) + tig];
            }
            uint32_t b[8][2];
#pragma unroll
            for (int nt = 0; nt < 8; nt++) {
                const int n = wn * 64 + nt * 8 + gid;
                b[nt][0] = Bb[(kk + tig) * 136 + n];
                b[nt][1] = Bb[(kk + tig + 4) * 136 + n];
            }
#pragma unroll
            for (int mt = 0; mt < 2; mt++)
#pragma unroll
                for (int nt = 0; nt < 8; nt++)
                    mma_f16(acc[mt][nt], a[mt], b[nt]);
        }

        if (t + 2 < T) {
            int nbuf = buf + 2; if (nbuf >= 3) nbuf -= 3;
            issue(t + 2, nbuf);
        }
        if (++buf == 3) buf = 0;
    }
}

// ----------------------------------------------------------------------------
// QKV kernel. z=0: Q -> packed fp16, pre-scaled by 1/sqrt(DK).
// z=1: K -> Khaug (packed u32). z=2: V -> Vhaug (16-bit stores).
// ----------------------------------------------------------------------------
__global__ __launch_bounds__(256, 2)
void qkv_kernel(const uint32_t* __restrict__ Ah,
                const uint32_t* __restrict__ Wqh, const uint32_t* __restrict__ Wkh,
                const uint32_t* __restrict__ Wvh,
                const float* __restrict__ bq, const float* __restrict__ bk,
                const float* __restrict__ bv,
                uint32_t* __restrict__ Qh, uint32_t* __restrict__ Khaug,
                uint32_t* __restrict__ Vhaug)
{
    const uint32_t* Bw; const float* bias;
    if (blockIdx.z == 0)      { Bw = Wqh; bias = bq; }
    else if (blockIdx.z == 1) { Bw = Wkh; bias = bk; }
    else                      { Bw = Wvh; bias = bv; }

    float acc[2][8][4];
    gemm_accum_f16(Ah, Bw, D_, D_ / 2, acc);

    const int lane = threadIdx.x & 31;
    const int warp = threadIdx.x >> 5;
    const int gid  = lane >> 2;
    const int tig  = lane & 3;
    const int wm   = warp & 3;
    const int wn   = warp >> 2;
    const int rowBase = blockIdx.y * 128;
    const int colBase = blockIdx.x * 128;

    if (blockIdx.z == 0) {
        const float scale = 0.17677669529663687f;   // 1/sqrt(32)
#pragma unroll
        for (int mt = 0; mt < 2; mt++) {
            const int row0 = rowBase + wm * 32 + mt * 16 + gid;
            const int row1 = row0 + 8;
#pragma unroll
            for (int nt = 0; nt < 8; nt++) {
                const int col = colBase + wn * 64 + nt * 8 + 2 * tig;
                float2 bb = *reinterpret_cast<const float2*>(&bias[col]);
                Qh[(size_t)row0 * (D_ / 2) + (col >> 1)] =
                    packh2((acc[mt][nt][0] + bb.x) * scale,
                           (acc[mt][nt][1] + bb.y) * scale);
                Qh[(size_t)row1 * (D_ / 2) + (col >> 1)] =
                    packh2((acc[mt][nt][2] + bb.x) * scale,
                           (acc[mt][nt][3] + bb.y) * scale);
            }
        }
    } else if (blockIdx.z == 1) {
#pragma unroll
        for (int mt = 0; mt < 2; mt++) {
            const int row0 = rowBase + wm * 32 + mt * 16 + gid;
            const int b    = row0 >> 10;
            const int n0   = row0 & 1023;
            const int kt   = n0 >> 7;
            const int key0 = n0 & 127;
            const int key1 = key0 + 8;
#pragma unroll
            for (int nt = 0; nt < 8; nt++) {
                const int col = colBase + wn * 64 + nt * 8 + 2 * tig;
                const int h   = col >> 5;
                const int kp  = (col & 31) >> 1;
                float2 bb = *reinterpret_cast<const float2*>(&bias[col]);
                const size_t base = (size_t)((b * 8 + h) * 8 + kt) * KT_U32;
                Khaug[base + (size_t)kp * 136 + key0] =
                    packh2(acc[mt][nt][0] + bb.x, acc[mt][nt][1] + bb.y);
                Khaug[base + (size_t)kp * 136 + key1] =
                    packh2(acc[mt][nt][2] + bb.x, acc[mt][nt][3] + bb.y);
            }
        }
    } else {
        __half* Vh = reinterpret_cast<__half*>(Vhaug);
#pragma unroll
        for (int mt = 0; mt < 2; mt++) {
            const int row0 = rowBase + wm * 32 + mt * 16 + gid;
            const int b    = row0 >> 10;
            const int n0   = row0 & 1023;
            const int kt   = n0 >> 7;
            const int key0 = n0 & 127;
            const int key1 = key0 + 8;
#pragma unroll
            for (int nt = 0; nt < 8; nt++) {
                const int col = colBase + wn * 64 + nt * 8 + 2 * tig;
                const int h   = col >> 5;
                const int dk0 = col & 31;
                float2 bb = *reinterpret_cast<const float2*>(&bias[col]);
                const size_t hb = (size_t)((b * 8 + h) * 8 + kt) * (VT_U32 * 2);
#pragma unroll
                for (int e = 0; e < 4; e++) {
                    const int dk  = dk0 + (e & 1);
                    const int key = (e < 2) ? key0 : key1;
                    const float v = acc[mt][nt][e] + ((e & 1) ? bb.y : bb.x);
                    Vh[hb + (size_t)((key >> 1) * 40 + dk) * 2 + (key & 1)] =
                        __float2half_rn(v);
                }
            }
        }
    }
}

// ff1 (fp16): H = relu(X @ W1 + b1), output packed fp16 only.
__global__ __launch_bounds__(256, 2)
void ff1_kernel(const uint32_t* __restrict__ Ah, const uint32_t* __restrict__ Bw,
                const float* __restrict__ bias, uint32_t* __restrict__ Ch)
{
    float acc[2][8][4];
    gemm_accum_f16(Ah, Bw, FF_, D_ / 2, acc);

    const int lane = threadIdx.x & 31;
    const int warp = threadIdx.x >> 5;
    const int gid  = lane >> 2;
    const int tig  = lane & 3;
    const int wm   = warp & 3;
    const int wn   = warp >> 2;
    const int rowBase = blockIdx.y * 128;
    const int colBase = blockIdx.x * 128;

#pragma unroll
    for (int mt = 0; mt < 2; mt++) {
        const int row0 = rowBase + wm * 32 + mt * 16 + gid;
        const int row1 = row0 + 8;
#pragma unroll
        for (int nt = 0; nt < 8; nt++) {
            const int col = colBase + wn * 64 + nt * 8 + 2 * tig;
            float2 bb = *reinterpret_cast<const float2*>(&bias[col]);
            float v0 = fmaxf(acc[mt][nt][0] + bb.x, 0.0f);
            float v1 = fmaxf(acc[mt][nt][1] + bb.y, 0.0f);
            float v2 = fmaxf(acc[mt][nt][2] + bb.x, 0.0f);
            float v3 = fmaxf(acc[mt][nt][3] + bb.y, 0.0f);
            Ch[(size_t)row0 * (FF_ / 2) + (col >> 1)] = packh2(v0, v1);
            Ch[(size_t)row1 * (FF_ / 2) + (col >> 1)] = packh2(v2, v3);
        }
    }
}

// ----------------------------------------------------------------------------
// Fused ff2 + residual + LayerNorm (fp16 mma, fp32 epilogue).
// ----------------------------------------------------------------------------
constexpr int A2_TILE_U32 = 64 * 32;
constexpr int B2_TILE_U32 = 32 * 264;
constexpr int STAGE2_U32  = A2_TILE_U32 + B2_TILE_U32;          // 10496
constexpr int FF2_SMEM    = 3 * STAGE2_U32 * 4;                 // 125952

__global__ __launch_bounds__(256, 1)
void ff2_ln_kernel(const uint32_t* __restrict__ Hbh,
                   const uint32_t* __restrict__ W2h,
                   const float* __restrict__ b2,
                   const float* __restrict__ X,
                   const float* __restrict__ g,
                   const float* __restrict__ be,
                   float* __restrict__ out,
                   uint32_t* __restrict__ outh)
{
    extern __shared__ uint32_t sm[];

    const int tid  = threadIdx.x;
    const int lane = tid & 31;
    const int warp = tid >> 5;
    const int gid  = lane >> 2;
    const int tig  = lane & 3;
    const int wm   = warp & 1;
    const int wn   = warp >> 1;

    const int rowBase = blockIdx.x * 64;
    constexpr int KP = FF_ / 2;

    int aR[2], aS[2], aC4[2];
#pragma unroll
    for (int i = 0; i < 2; i++) {
        int idx = tid + i * 256;
        int r  = idx >> 3;
        int c4 = (idx & 7) << 2;
        aR[i] = r; aS[i] = r * 32 + (c4 ^ ((r & 7) << 2)); aC4[i] = c4;
    }
    int bR[8], bS[8], bC4[8];
#pragma unroll
    for (int i = 0; i < 8; i++) {
        int idx = tid + i * 256;
        int rb  = idx >> 6;
        int cb4 = (idx & 63) << 2;
        bR[i] = rb; bS[i] = rb * 264 + cb4; bC4[i] = cb4;
    }

    auto issue = [&](int t, int buf) {
        const int k0 = t * 32;
        uint32_t* As = sm + buf * STAGE2_U32;
        uint32_t* Bs = As + A2_TILE_U32;
#pragma unroll
        for (int i = 0; i < 2; i++)
            cp16(smem_u32(&As[aS[i]]),
                 &Hbh[(size_t)(rowBase + aR[i]) * KP + k0 + aC4[i]]);
#pragma unroll
        for (int i = 0; i < 8; i++)
            cp16(smem_u32(&Bs[bS[i]]),
                 &W2h[(size_t)(k0 + bR[i]) * D_ + bC4[i]]);
        cp_commit();
    };

    float acc[2][8][4];
#pragma unroll
    for (int mt = 0; mt < 2; mt++)
#pragma unroll
        for (int nt = 0; nt < 8; nt++)
#pragma unroll
            for (int j = 0; j < 4; j++) acc[mt][nt][j] = 0.0f;

    const int T = KP >> 5;                 // 16
    issue(0, 0);
    issue(1, 1);

    int buf = 0;
    for (int t = 0; t < T; t++) {
        if (t + 1 < T) cp_wait<1>(); else cp_wait<0>();
        __syncthreads();

        const uint32_t* Ab = sm + buf * STAGE2_U32;
        const uint32_t* Bb = Ab + A2_TILE_U32;

#pragma unroll
        for (int kk = 0; kk < 32; kk += 8) {
            uint32_t a[2][4];
#pragma unroll
            for (int mt = 0; mt < 2; mt++) {
                const int m  = wm * 32 + mt * 16 + gid;
                const int sw = (m & 7) << 2;
                const int b0 = m * 32;
                const int b1 = b0 + 8 * 32;
                a[mt][0] = Ab[b0 + (kk ^ sw) + tig];
                a[mt][1] = Ab[b1 + (kk ^ sw) + tig];
                a[mt][2] = Ab[b0 + ((kk + 4) ^ sw) + tig];
                a[mt][3] = Ab[b1 + ((kk + 4) ^ sw) + tig];
            }
            uint32_t b[8][2];
#pragma unroll
            for (int nt = 0; nt < 8; nt++) {
                const int n = wn * 64 + nt * 8 + gid;
                b[nt][0] = Bb[(kk + tig) * 264 + n];
                b[nt][1] = Bb[(kk + tig + 4) * 264 + n];
            }
#pragma unroll
            for (int mt = 0; mt < 2; mt++)
#pragma unroll
                for (int nt = 0; nt < 8; nt++)
                    mma_f16(acc[mt][nt], a[mt], b[nt]);
        }

        if (t + 2 < T) {
            int nbuf = buf + 2; if (nbuf >= 3) nbuf -= 3;
            issue(t + 2, nbuf);
        }
        if (++buf == 3) buf = 0;
    }

    __syncthreads();
    float* red = reinterpret_cast<float*>(sm);

#pragma unroll
    for (int mt = 0; mt < 2; mt++) {
        const int rloc0 = wm * 32 + mt * 16 + gid;
        const int rloc1 = rloc0 + 8;
        float s0 = 0.0f, q0 = 0.0f, s1 = 0.0f, q1 = 0.0f;
#pragma unroll
        for (int nt = 0; nt < 8; nt++) {
            const int col = wn * 64 + nt * 8 + 2 * tig;
            float2 bb = *reinterpret_cast<const float2*>(&b2[col]);
            float2 x0 = *reinterpret_cast<const float2*>(
                &X[(size_t)(rowBase + rloc0) * D_ + col]);
            float2 x1 = *reinterpret_cast<const float2*>(
                &X[(size_t)(rowBase + rloc1) * D_ + col]);
            float v0 = acc[mt][nt][0] + bb.x + x0.x;
            float v1 = acc[mt][nt][1] + bb.y + x0.y;
            float v2 = acc[mt][nt][2] + bb.x + x1.x;
            float v3 = acc[mt][nt][3] + bb.y + x1.y;
            acc[mt][nt][0] = v0; acc[mt][nt][1] = v1;
            acc[mt][nt][2] = v2; acc[mt][nt][3] = v3;
            s0 += v0 + v1; q0 = fmaf(v0, v0, fmaf(v1, v1, q0));
            s1 += v2 + v3; q1 = fmaf(v2, v2, fmaf(v3, v3, q1));
        }
        s0 += __shfl_xor_sync(0xffffffffu, s0, 1);
        s0 += __shfl_xor_sync(0xffffffffu, s0, 2);
        q0 += __shfl_xor_sync(0xffffffffu, q0, 1);
        q0 += __shfl_xor_sync(0xffffffffu, q0, 2);
        s1 += __shfl_xor_sync(0xffffffffu, s1, 1);
        s1 += __shfl_xor_sync(0xffffffffu, s1, 2);
        q1 += __shfl_xor_sync(0xffffffffu, q1, 1);
        q1 += __shfl_xor_sync(0xffffffffu, q1, 2);
        if (tig == 0) {
            red[rloc0 * 8 + wn * 2 + 0] = s0;
            red[rloc0 * 8 + wn * 2 + 1] = q0;
            red[rloc1 * 8 + wn * 2 + 0] = s1;
            red[rloc1 * 8 + wn * 2 + 1] = q1;
        }
    }
    __syncthreads();

#pragma unroll
    for (int mt = 0; mt < 2; mt++) {
#pragma unroll
        for (int rr = 0; rr < 2; rr++) {
            const int rloc = wm * 32 + mt * 16 + gid + rr * 8;
            const float* rp = &red[rloc * 8];
            const float sum = rp[0] + rp[2] + rp[4] + rp[6];
            const float sq  = rp[1] + rp[3] + rp[5] + rp[7];
            const float mean = sum * (1.0f / 256.0f);
            const float var  = sq * (1.0f / 256.0f) - mean * mean;
            const float rs   = rsqrtf(var + 1e-5f);
            const int row = rowBase + rloc;
#pragma unroll
            for (int nt = 0; nt < 8; nt++) {
                const int col = wn * 64 + nt * 8 + 2 * tig;
                float2 gv = *reinterpret_cast<const float2*>(&g[col]);
                float2 ev = *reinterpret_cast<const float2*>(&be[col]);
                const float a0 = acc[mt][nt][rr * 2 + 0];
                const float a1 = acc[mt][nt][rr * 2 + 1];
                const float o0 = (a0 - mean) * rs * gv.x + ev.x;
                const float o1 = (a1 - mean) * rs * gv.y + ev.y;
                *reinterpret_cast<float2*>(&out[(size_t)row * D_ + col]) =
                    make_float2(o0, o1);
                outh[(size_t)row * (D_ / 2) + (col >> 1)] = packh2(o0, o1);
            }
        }
    }
}

// ----------------------------------------------------------------------------
// ONE fused prep kernel. Flat index dispatch over segments:
//   [0, XN)        : x -> packed fp16
//   [.., +WN)x3    : Wq, Wk, Wv pack (Nn = D)
//   [.., +W1N)     : W1 pack (Nn = FF)
//   [.., +W2N)     : W2 pack (Nn = D)
//   [.., +CN)      : Khaug coords rows fill
// ----------------------------------------------------------------------------
constexpr int XN  = ROWS * D_ / 2;               // 1048576
constexpr int WN  = L_ * (D_ / 2) * D_;          // 131072
constexpr int W1N = L_ * (D_ / 2) * FF_;         // 524288
constexpr int W2N = L_ * (FF_ / 2) * D_;         // 524288
constexpr int CN  = 512 * (8 * 136);             // 557056
constexpr int PREP_TOTAL = XN + 3 * WN + W1N + W2N + CN;   // 3047424
constexpr int PREP_GRID  = PREP_TOTAL / 256;               // 11904

__global__ __launch_bounds__(256)
void prep_kernel(const float* __restrict__ x,
                 const float* __restrict__ Wq, const float* __restrict__ Wk,
                 const float* __restrict__ Wv, const float* __restrict__ W1,
                 const float* __restrict__ W2, const float* __restrict__ coords,
                 uint32_t* __restrict__ Xh,
                 uint32_t* __restrict__ Wqh, uint32_t* __restrict__ Wkh,
                 uint32_t* __restrict__ Wvh, uint32_t* __restrict__ W1h,
                 uint32_t* __restrict__ W2h, uint32_t* __restrict__ Khaug)
{
    int idx = blockIdx.x * 256 + threadIdx.x;
    if (idx < XN) {
        float2 v = reinterpret_cast<const float2*>(x)[idx];
        Xh[idx] = packh2(v.x, v.y);
        return;
    }
    idx -= XN;
    if (idx < 3 * WN) {
        const float* W; uint32_t* O;
        if (idx < WN)            { W = Wq; O = Wqh; }
        else if (idx < 2 * WN)   { W = Wk; O = Wkh; idx -= WN; }
        else                     { W = Wv; O = Wvh; idx -= 2 * WN; }
        const int kp = idx >> 8;            // / D_
        const int n  = idx & 255;
        O[idx] = packh2(W[(size_t)(2 * kp) * D_ + n],
                        W[(size_t)(2 * kp + 1) * D_ + n]);
        return;
    }
    idx -= 3 * WN;
    if (idx < W1N) {
        const int kp = idx >> 10;           // / FF_
        const int n  = idx & 1023;
        W1h[idx] = packh2(W1[(size_t)(2 * kp) * FF_ + n],
                          W1[(size_t)(2 * kp + 1) * FF_ + n]);
        return;
    }
    idx -= W1N;
    if (idx < W2N) {
        const int kp = idx >> 8;            // / D_
        const int n  = idx & 255;
        W2h[idx] = packh2(W2[(size_t)(2 * kp) * D_ + n],
                          W2[(size_t)(2 * kp + 1) * D_ + n]);
        return;
    }
    idx -= W2N;
    {
        const int t   = idx / 1088;         // (bh*8+kt)
        const int rem = idx - t * 1088;
        const int r   = rem / 136;          // kpair 16+r
        const int key = rem - r * 136;
        const int kt  = t & 7;
        const int b   = t >> 6;
        uint32_t v = 0;
        if (key < 128) {
            const float* c = &coords[(size_t)(b * N_ + kt * 128 + key) * 3];
            if (r == 0)      v = packh2(c[0], c[1]);
            else if (r == 1) v = packh2(c[2], 0.0f);
        }
        Khaug[(size_t)t * KT_U32 + (16 + r) * 136 + key] = v;
    }
}

// ----------------------------------------------------------------------------
// fp16 MMA flash attention. 2 CTAs/SM. Q packed fp16 (pre-scaled), output fp16.
// ----------------------------------------------------------------------------
constexpr int TILE_U32A = KT_U32 + VT_U32;          // 5824
constexpr int ATTN_SMEM = 2 * TILE_U32A * 4;        // 46592

__global__ __launch_bounds__(256, 2)
void attn_f16_kernel(const uint32_t* __restrict__ Qh,
                     const uint32_t* __restrict__ Khaug,
                     const uint32_t* __restrict__ Vhaug,
                     const float* __restrict__ coords,
                     const float* __restrict__ alpha,
                     int layer,
                     uint32_t* __restrict__ Outh)
{
    extern __shared__ uint32_t smu[];

    const int tid  = threadIdx.x;
    const int lane = tid & 31;
    const int w    = tid >> 5;
    const int gid  = lane >> 2;
    const int tig  = lane & 3;

    const int bh = blockIdx.x;
    const int b  = bh >> 3;
    const int h  = bh & 7;
    const int q0 = blockIdx.y * 128;

    const float alphav = alpha[layer];

    // Q' fragments: ks 0,1 direct packed loads; ks 2 = alpha*coords rows.
    uint32_t qf[3][4];
    {
        const int row0 = b * N_ + q0 + w * 16 + gid;
#pragma unroll
        for (int ks = 0; ks < 2; ks++) {
#pragma unroll
            for (int r = 0; r < 4; r++) {
                const int row = row0 + (r & 1) * 8;
                const int kp  = h * 16 + ks * 8 + tig + ((r >> 1) << 2);
                qf[ks][r] = Qh[(size_t)row * (D_ / 2) + kp];
            }
        }
#pragma unroll
        for (int r = 0; r < 4; r++) {
            const int row = row0 + (r & 1) * 8;
            uint32_t v = 0;
            if ((r >> 1) == 0) {
                const float* c = &coords[(size_t)row * 3];
                if (tig == 0)      v = packh2(alphav * c[0], alphav * c[1]);
                else if (tig == 1) v = packh2(alphav * c[2], 0.0f);
            }
            qf[2][r] = v;
        }
    }

    auto issue = [&](int t, int buf) {
        const uint32_t* srcK = Khaug + (size_t)(bh * 8 + t) * KT_U32;
        uint32_t* dst = smu + buf * TILE_U32A;
#pragma unroll
        for (int j = 0; j < 3; j++) {
            const int i16 = tid + j * 256;
            cp16(smem_u32(dst + i16 * 4), srcK + i16 * 4);
        }
        if (tid < 48)
            cp16(smem_u32(dst + (768 + tid) * 4), srcK + (768 + tid) * 4);
        const uint32_t* srcV = Vhaug + (size_t)(bh * 8 + t) * VT_U32;
        uint32_t* dstV = dst + KT_U32;
#pragma unroll
        for (int j = 0; j < 2; j++) {
            const int i16 = tid + j * 256;
            cp16(smem_u32(dstV + i16 * 4), srcV + i16 * 4);
        }
        if (tid < 128)
            cp16(smem_u32(dstV + (512 + tid) * 4), srcV + (512 + tid) * 4);
        cp_commit();
    };

    float O[4][4];
#pragma unroll
    for (int i = 0; i < 4; i++)
#pragma unroll
        for (int j = 0; j < 4; j++) O[i][j] = 0.0f;
    float m0 = -1e30f, m1 = -1e30f, l0 = 0.0f, l1 = 0.0f;

    issue(0, 0);

    for (int t = 0; t < 8; t++) {
        if (t < 7) { issue(t + 1, (t + 1) & 1); cp_wait<1>(); }
        else       { cp_wait<0>(); }
        __syncthreads();

        const uint32_t* Kb = smu + (t & 1) * TILE_U32A;
        const uint32_t* Vb = Kb + KT_U32;

        float s[16][4];
#pragma unroll
        for (int nt = 0; nt < 16; nt++)
#pragma unroll
            for (int j = 0; j < 4; j++) s[nt][j] = 0.0f;

#pragma unroll
        for (int ks = 0; ks < 3; ks++) {
#pragma unroll
            for (int nt = 0; nt < 16; nt++) {
                uint32_t bfr[2];
                const int key = nt * 8 + gid;
                bfr[0] = Kb[(ks * 8 + tig) * 136 + key];
                bfr[1] = Kb[(ks * 8 + 4 + tig) * 136 + key];
                mma_f16(s[nt], qf[ks], bfr);
            }
        }

        float mx0 = -1e30f, mx1 = -1e30f;
#pragma unroll
        for (int nt = 0; nt < 16; nt++) {
            mx0 = fmaxf(mx0, fmaxf(s[nt][0], s[nt][1]));
            mx1 = fmaxf(mx1, fmaxf(s[nt][2], s[nt][3]));
        }
        mx0 = fmaxf(mx0, __shfl_xor_sync(0xffffffffu, mx0, 1));
        mx0 = fmaxf(mx0, __shfl_xor_sync(0xffffffffu, mx0, 2));
        mx1 = fmaxf(mx1, __shfl_xor_sync(0xffffffffu, mx1, 1));
        mx1 = fmaxf(mx1, __shfl_xor_sync(0xffffffffu, mx1, 2));

        const float mn0 = fmaxf(m0, mx0);
        const float mn1 = fmaxf(m1, mx1);
        const float c0  = __expf(m0 - mn0);
        const float c1  = __expf(m1 - mn1);
        m0 = mn0; m1 = mn1;

        float rs0 = 0.0f, rs1 = 0.0f;
#pragma unroll
        for (int nt = 0; nt < 16; nt++) {
            s[nt][0] = __expf(s[nt][0] - mn0);
            s[nt][1] = __expf(s[nt][1] - mn0);
            s[nt][2] = __expf(s[nt][2] - mn1);
            s[nt][3] = __expf(s[nt][3] - mn1);
            rs0 += s[nt][0] + s[nt][1];
            rs1 += s[nt][2] + s[nt][3];
        }
        rs0 += __shfl_xor_sync(0xffffffffu, rs0, 1);
        rs0 += __shfl_xor_sync(0xffffffffu, rs0, 2);
        rs1 += __shfl_xor_sync(0xffffffffu, rs1, 1);
        rs1 += __shfl_xor_sync(0xffffffffu, rs1, 2);
        l0 = l0 * c0 + rs0;
        l1 = l1 * c1 + rs1;

#pragma unroll
        for (int nt2 = 0; nt2 < 4; nt2++) {
            O[nt2][0] *= c0; O[nt2][1] *= c0;
            O[nt2][2] *= c1; O[nt2][3] *= c1;
        }

#pragma unroll
        for (int ks = 0; ks < 8; ks++) {
            uint32_t a[4];
            a[0] = packh2(s[2 * ks][0],     s[2 * ks][1]);
            a[1] = packh2(s[2 * ks][2],     s[2 * ks][3]);
            a[2] = packh2(s[2 * ks + 1][0], s[2 * ks + 1][1]);
            a[3] = packh2(s[2 * ks + 1][2], s[2 * ks + 1][3]);
#pragma unroll
            for (int nt2 = 0; nt2 < 4; nt2++) {
                uint32_t bfr[2];
                const int dk = nt2 * 8 + gid;
                bfr[0] = Vb[(ks * 8 + tig) * 40 + dk];
                bfr[1] = Vb[(ks * 8 + 4 + tig) * 40 + dk];
                mma_f16(O[nt2], a, bfr);
            }
        }
        __syncthreads();
    }

    const float inv0 = 1.0f / l0;
    const float inv1 = 1.0f / l1;
    const int row0 = b * N_ + q0 + w * 16 + gid;
    const int row1 = row0 + 8;
#pragma unroll
    for (int nt2 = 0; nt2 < 4; nt2++) {
        const int kp = h * 16 + nt2 * 4 + tig;    // (h*32 + nt2*8 + 2tig)/2
        Outh[(size_t)row0 * (D_ / 2) + kp] =
            packh2(O[nt2][0] * inv0, O[nt2][1] * inv0);
        Outh[(size_t)row1 * (D_ / 2) + kp] =
            packh2(O[nt2][2] * inv1, O[nt2][3] * inv1);
    }
}

// ----------------------------------------------------------------------------
// Fused residual add + LayerNorm (LN1). fp16 delta input; fp32 + fp16 out.
// ----------------------------------------------------------------------------
__global__ __launch_bounds__(256, 6)
void add_ln_kernel(const float* __restrict__ x,
                   const uint32_t* __restrict__ deltah,
                   const float* __restrict__ g,
                   const float* __restrict__ be,
                   float* __restrict__ out,
                   uint32_t* __restrict__ outh)
{
    const int warp = threadIdx.x >> 5;
    const int lane = threadIdx.x & 31;
    const int rowA = blockIdx.x * 16 + warp * 2;
    const int rowB = rowA + 1;
    const int col0 = lane * 8;

    const float4* xa = reinterpret_cast<const float4*>(&x[(size_t)rowA * D_ + col0]);
    const float4* xb = reinterpret_cast<const float4*>(&x[(size_t)rowB * D_ + col0]);
    uint4 dha = *reinterpret_cast<const uint4*>(&deltah[(size_t)rowA * (D_ / 2) + lane * 4]);
    uint4 dhb = *reinterpret_cast<const uint4*>(&deltah[(size_t)rowB * (D_ / 2) + lane * 4]);

    float4 xa0 = xa[0], xa1 = xa[1], xb0 = xb[0], xb1 = xb[1];
    float2 da0 = __half22float2(*reinterpret_cast<__half2*>(&dha.x));
    float2 da1 = __half22float2(*reinterpret_cast<__half2*>(&dha.y));
    float2 da2 = __half22float2(*reinterpret_cast<__half2*>(&dha.z));
    float2 da3 = __half22float2(*reinterpret_cast<__half2*>(&dha.w));
    float2 db0 = __half22float2(*reinterpret_cast<__half2*>(&dhb.x));
    float2 db1 = __half22float2(*reinterpret_cast<__half2*>(&dhb.y));
    float2 db2 = __half22float2(*reinterpret_cast<__half2*>(&dhb.z));
    float2 db3 = __half22float2(*reinterpret_cast<__half2*>(&dhb.w));

    float ra[8], rb[8];
    ra[0] = xa0.x + da0.x; ra[1] = xa0.y + da0.y; ra[2] = xa0.z + da1.x; ra[3] = xa0.w + da1.y;
    ra[4] = xa1.x + da2.x; ra[5] = xa1.y + da2.y; ra[6] = xa1.z + da3.x; ra[7] = xa1.w + da3.y;
    rb[0] = xb0.x + db0.x; rb[1] = xb0.y + db0.y; rb[2] = xb0.z + db1.x; rb[3] = xb0.w + db1.y;
    rb[4] = xb1.x + db2.x; rb[5] = xb1.y + db2.y; rb[6] = xb1.z + db3.x; rb[7] = xb1.w + db3.y;

    float sa = 0.0f, sb = 0.0f;
#pragma unroll
    for (int j = 0; j < 8; j++) { sa += ra[j]; sb += rb[j]; }
#pragma unroll
    for (int off = 16; off > 0; off >>= 1) {
        sa += __shfl_xor_sync(0xffffffffu, sa, off);
        sb += __shfl_xor_sync(0xffffffffu, sb, off);
    }
    const float meanA = sa * (1.0f / 256.0f);
    const float meanB = sb * (1.0f / 256.0f);

    float va = 0.0f, vb = 0.0f;
#pragma unroll
    for (int j = 0; j < 8; j++) {
        float ta = ra[j] - meanA; va = fmaf(ta, ta, va);
        float tb = rb[j] - meanB; vb = fmaf(tb, tb, vb);
    }
#pragma unroll
    for (int off = 16; off > 0; off >>= 1) {
        va += __shfl_xor_sync(0xffffffffu, va, off);
        vb += __shfl_xor_sync(0xffffffffu, vb, off);
    }
    const float rsA = rsqrtf(va * (1.0f / 256.0f) + 1e-5f);
    const float rsB = rsqrtf(vb * (1.0f / 256.0f) + 1e-5f);

    const float4* gg = reinterpret_cast<const float4*>(&g[col0]);
    const float4* bb = reinterpret_cast<const float4*>(&be[col0]);
    float4 g0 = gg[0], g1 = gg[1], e0 = bb[0], e1 = bb[1];
    const float gv[8] = {g0.x, g0.y, g0.z, g0.w, g1.x, g1.y, g1.z, g1.w};
    const float ev[8] = {e0.x, e0.y, e0.z, e0.w, e1.x, e1.y, e1.z, e1.w};

    float oa[8], ob[8];
#pragma unroll
    for (int j = 0; j < 8; j++) {
        oa[j] = (ra[j] - meanA) * rsA * gv[j] + ev[j];
        ob[j] = (rb[j] - meanB) * rsB * gv[j] + ev[j];
    }

    float4* outA = reinterpret_cast<float4*>(&out[(size_t)rowA * D_ + col0]);
    float4* outB = reinterpret_cast<float4*>(&out[(size_t)rowB * D_ + col0]);
    outA[0] = make_float4(oa[0], oa[1], oa[2], oa[3]);
    outA[1] = make_float4(oa[4], oa[5], oa[6], oa[7]);
    outB[0] = make_float4(ob[0], ob[1], ob[2], ob[3]);
    outB[1] = make_float4(ob[4], ob[5], ob[6], ob[7]);

    uint4 pa, pb;
    pa.x = packh2(oa[0], oa[1]); pa.y = packh2(oa[2], oa[3]);
    pa.z = packh2(oa[4], oa[5]); pa.w = packh2(oa[6], oa[7]);
    pb.x = packh2(ob[0], ob[1]); pb.y = packh2(ob[2], ob[3]);
    pb.z = packh2(ob[4], ob[5]); pb.w = packh2(ob[6], ob[7]);
    *reinterpret_cast<uint4*>(&outh[(size_t)rowA * (D_ / 2) + lane * 4]) = pa;
    *reinterpret_cast<uint4*>(&outh[(size_t)rowB * (D_ / 2) + lane * 4]) = pb;
}

// ----------------------------------------------------------------------------
// Host driver
// ----------------------------------------------------------------------------
extern "C" void kernel_launch(void* const* d_in, const int* in_sizes, int n_in,
                              void* d_out, int out_size)
{
    const float* x      = (const float*)d_in[0];
    const float* coords = (const float*)d_in[1];
    const float* Wq     = (const float*)d_in[2];
    const float* bq     = (const float*)d_in[3];
    const float* Wk     = (const float*)d_in[4];
    const float* bk     = (const float*)d_in[5];
    const float* Wv     = (const float*)d_in[6];
    const float* bv     = (const float*)d_in[7];
    const float* alpha  = (const float*)d_in[8];
    const float* W1     = (const float*)d_in[9];
    const float* b1     = (const float*)d_in[10];
    const float* W2     = (const float*)d_in[11];
    const float* b2     = (const float*)d_in[12];
    const float* g1     = (const float*)d_in[13];
    const float* be1    = (const float*)d_in[14];
    const float* g2     = (const float*)d_in[15];
    const float* be2    = (const float*)d_in[16];
    float* out = (float*)d_out;

    float *Xp;
    uint32_t *Xhp, *Hbhp, *Qhp, *ATThp, *Wqhp, *Wkhp, *Wvhp, *W1hp, *W2hp, *Khp, *Vhp;
    cudaGetSymbolAddress((void**)&Xp,    g_X);
    cudaGetSymbolAddress((void**)&Xhp,   g_Xh);
    cudaGetSymbolAddress((void**)&Hbhp,  g_Hbh);
    cudaGetSymbolAddress((void**)&Qhp,   g_Qh);
    cudaGetSymbolAddress((void**)&ATThp, g_ATTh);
    cudaGetSymbolAddress((void**)&Wqhp,  g_Wqh);
    cudaGetSymbolAddress((void**)&Wkhp,  g_Wkh);
    cudaGetSymbolAddress((void**)&Wvhp,  g_Wvh);
    cudaGetSymbolAddress((void**)&W1hp,  g_W1h);
    cudaGetSymbolAddress((void**)&W2hp,  g_W2h);
    cudaGetSymbolAddress((void**)&Khp,   g_Khaug);
    cudaGetSymbolAddress((void**)&Vhp,   g_Vhaug);

    cudaFuncSetAttribute(qkv_kernel,
                         cudaFuncAttributeMaxDynamicSharedMemorySize, GEMM_SMEM);
    cudaFuncSetAttribute(ff1_kernel,
                         cudaFuncAttributeMaxDynamicSharedMemorySize, GEMM_SMEM);
    cudaFuncSetAttribute(ff2_ln_kernel,
                         cudaFuncAttributeMaxDynamicSharedMemorySize, FF2_SMEM);
    cudaFuncSetAttribute(attn_f16_kernel,
                         cudaFuncAttributeMaxDynamicSharedMemorySize, ATTN_SMEM);

    const dim3 gQKV(D_ / 128, ROWS / 128, 3);
    const dim3 gFF1(FF_ / 128, ROWS / 128);
    const dim3 gAttn(B_ * H_, N_ / 128);

    prep_kernel<<<PREP_GRID, 256>>>(x, Wq, Wk, Wv, W1, W2, coords,
                                    Xhp, Wqhp, Wkhp, Wvhp, W1hp, W2hp, Khp);

    const float* cur = x;          // fp32 residual source
    const uint32_t* curh = Xhp;    // fp16 GEMM operand
    for (int i = 0; i < L_; i++) {
        qkv_kernel<<<gQKV, 256, GEMM_SMEM>>>(
            curh,
            Wqhp + (size_t)i * (D_ / 2) * D_,
            Wkhp + (size_t)i * (D_ / 2) * D_,
            Wvhp + (size_t)i * (D_ / 2) * D_,
            bq + i * D_, bk + i * D_, bv + i * D_,
            Qhp, Khp, Vhp);

        attn_f16_kernel<<<gAttn, 256, ATTN_SMEM>>>(Qhp, Khp, Vhp, coords,
                                                   alpha, i, ATThp);

        add_ln_kernel<<<ROWS / 16, 256>>>(cur, ATThp, g1 + i * D_, be1 + i * D_,
                                          Xp, Xhp);

        ff1_kernel<<<gFF1, 256, GEMM_SMEM>>>(
            Xhp, W1hp + (size_t)i * (D_ / 2) * FF_, b1 + i * FF_, Hbhp);

        float* xo = (i == L_ - 1) ? out : Xp;
        ff2_ln_kernel<<<ROWS / 64, 256, FF2_SMEM>>>(
            Hbhp, W2hp + (size_t)i * (FF_ / 2) * D_, b2 + i * D_,
            Xp, g2 + i * D_, be2 + i * D_, xo, Xhp);

        cur = Xp;
        curh = Xhp;
    }
}

// round 17
// speedup vs baseline: 1.7249x; 1.0328x over previous
#include <cuda_runtime.h>
#include <cuda_fp16.h>
#include <cstdint>

// ----------------------------------------------------------------------------
// Problem constants
// ----------------------------------------------------------------------------
constexpr int B_  = 8;
constexpr int N_  = 1024;
constexpr int D_  = 256;
constexpr int H_  = 8;
constexpr int DK_ = 32;
constexpr int FF_ = 1024;
constexpr int L_  = 4;
constexpr int ROWS = B_ * N_;          // 8192 token rows

// ----------------------------------------------------------------------------
// Scratch (device globals: no allocation allowed)
// ----------------------------------------------------------------------------
// fp16 packed activations (u32 = half2 along k)
__device__ __align__(16) uint32_t g_Xh  [ROWS * D_ / 2];   // residual stream
__device__ __align__(16) uint32_t g_Yh  [ROWS * D_ / 2];   // post-LN1 stream
__device__ __align__(16) uint32_t g_Hbh [ROWS * FF_ / 2];
__device__ __align__(16) uint32_t g_Qh  [ROWS * D_ / 2];   // pre-scaled Q
__device__ __align__(16) uint32_t g_ATTh[ROWS * D_ / 2];   // attention out
// fp16 packed weights: [K/2][N] per layer
__device__ __align__(16) uint32_t g_Wqh[L_ * (D_ / 2) * D_];
__device__ __align__(16) uint32_t g_Wkh[L_ * (D_ / 2) * D_];
__device__ __align__(16) uint32_t g_Wvh[L_ * (D_ / 2) * D_];
__device__ __align__(16) uint32_t g_W1h[L_ * (D_ / 2) * FF_];
__device__ __align__(16) uint32_t g_W2h[L_ * (FF_ / 2) * D_];
// Attention fp16 staging:
constexpr int KT_U32 = 24 * 136;       // 3264
constexpr int VT_U32 = 64 * 40;        // 2560
__device__ __align__(16) uint32_t g_Khaug[64 * 8 * KT_U32];
__device__ __align__(16) uint32_t g_Vhaug[64 * 8 * VT_U32];

// ----------------------------------------------------------------------------
// Helpers
// ----------------------------------------------------------------------------
__device__ __forceinline__ uint32_t smem_u32(const void* p) {
    return (uint32_t)__cvta_generic_to_shared(p);
}
__device__ __forceinline__ void cp16(uint32_t s, const void* g) {
    asm volatile("cp.async.cg.shared.global [%0], [%1], 16;" :: "r"(s), "l"(g));
}
__device__ __forceinline__ void cp_commit() {
    asm volatile("cp.async.commit_group;" ::: "memory");
}
template <int NN>
__device__ __forceinline__ void cp_wait() {
    asm volatile("cp.async.wait_group %0;" :: "n"(NN) : "memory");
}
__device__ __forceinline__ void mma_f16(float* c, const uint32_t* a, const uint32_t* b) {
    asm volatile(
        "mma.sync.aligned.m16n8k16.row.col.f32.f16.f16.f32 "
        "{%0,%1,%2,%3},{%4,%5,%6,%7},{%8,%9},{%0,%1,%2,%3};"
        : "+f"(c[0]), "+f"(c[1]), "+f"(c[2]), "+f"(c[3])
        : "r"(a[0]), "r"(a[1]), "r"(a[2]), "r"(a[3]), "r"(b[0]), "r"(b[1]));
}
__device__ __forceinline__ uint32_t packh2(float a, float b) {
    __half2 h = __floats2half2_rn(a, b);
    return *reinterpret_cast<uint32_t*>(&h);
}
__device__ __forceinline__ float2 unpackh2(uint32_t u) {
    return __half22float2(*reinterpret_cast<__half2*>(&u));
}

// ----------------------------------------------------------------------------
// fp16 MMA GEMM core (128x128 tile): 3-stage cp.async pipeline.
// ----------------------------------------------------------------------------
constexpr int A_TILE_U32 = 128 * 32;
constexpr int B_TILE_U32 = 32 * 136;
constexpr int STAGE_U32  = A_TILE_U32 + B_TILE_U32;            // 8448
constexpr int GEMM_SMEM  = 3 * STAGE_U32 * 4;                  // 101376 bytes

__device__ __forceinline__ void gemm_accum_f16(const uint32_t* __restrict__ A,
                                               const uint32_t* __restrict__ Bw,
                                               int Nn, int Kpairs,
                                               float acc[2][8][4])
{
    extern __shared__ uint32_t sm[];

    const int tid  = threadIdx.x;
    const int lane = tid & 31;
    const int warp = tid >> 5;
    const int gid  = lane >> 2;
    const int tig  = lane & 3;
    const int wm   = warp & 3;
    const int wn   = warp >> 2;

    const int rowBase = blockIdx.y * 128;
    const int colBase = blockIdx.x * 128;

    int aR[4], aS[4], bR[4], bS[4], aC4[4], bC4[4];
#pragma unroll
    for (int i = 0; i < 4; i++) {
        int idx = tid + i * 256;
        int r  = idx >> 3;
        int c4 = (idx & 7) << 2;
        aR[i] = r; aS[i] = r * 32 + (c4 ^ ((r & 7) << 2)); aC4[i] = c4;
        int rb  = idx >> 5;
        int cb4 = (idx & 31) << 2;
        bR[i] = rb; bS[i] = rb * 136 + cb4; bC4[i] = cb4;
    }

    auto issue = [&](int t, int buf) {
        const int k0 = t * 32;                 // kpair units
        uint32_t* As = sm + buf * STAGE_U32;
        uint32_t* Bs = As + A_TILE_U32;
#pragma unroll
        for (int i = 0; i < 4; i++)
            cp16(smem_u32(&As[aS[i]]),
                 &A[(size_t)(rowBase + aR[i]) * Kpairs + k0 + aC4[i]]);
#pragma unroll
        for (int i = 0; i < 4; i++)
            cp16(smem_u32(&Bs[bS[i]]),
                 &Bw[(size_t)(k0 + bR[i]) * Nn + colBase + bC4[i]]);
        cp_commit();
    };

#pragma unroll
    for (int mt = 0; mt < 2; mt++)
#pragma unroll
        for (int nt = 0; nt < 8; nt++)
#pragma unroll
            for (int j = 0; j < 4; j++) acc[mt][nt][j] = 0.0f;

    const int T = Kpairs >> 5;
    issue(0, 0);
    issue(1, 1);

    int buf = 0;
    for (int t = 0; t < T; t++) {
        if (t + 1 < T) cp_wait<1>(); else cp_wait<0>();
        __syncthreads();

        const uint32_t* Ab = sm + buf * STAGE_U32;
        const uint32_t* Bb = Ab + A_TILE_U32;

#pragma unroll
        for (int kk = 0; kk < 32; kk += 8) {
            uint32_t a[2][4];
#pragma unroll
            for (int mt = 0; mt < 2; mt++) {
                const int m  = wm * 32 + mt * 16 + gid;
                const int sw = (m & 7) << 2;
                const int b0 = m * 32;
                const int b1 = b0 + 8 * 32;
                a[mt][0] = Ab[b0 + (kk ^ sw) + tig];
                a[mt][1] = Ab[b1 + (kk ^ sw) + tig];
                a[mt][2] = Ab[b0 + ((kk + 4) ^ sw) + tig];
                a[mt][3] = Ab[b1 + ((kk + 4) ^ sw) + tig];
            }
            uint32_t b[8][2];
#pragma unroll
            for (int nt = 0; nt < 8; nt++) {
                const int n = wn * 64 + nt * 8 + gid;
                b[nt][0] = Bb[(kk + tig) * 136 + n];
                b[nt][1] = Bb[(kk + tig + 4) * 136 + n];
            }
#pragma unroll
            for (int mt = 0; mt < 2; mt++)
#pragma unroll
                for (int nt = 0; nt < 8; nt++)
                    mma_f16(acc[mt][nt], a[mt], b[nt]);
        }

        if (t + 2 < T) {
            int nbuf = buf + 2; if (nbuf >= 3) nbuf -= 3;
            issue(t + 2, nbuf);
        }
        if (++buf == 3) buf = 0;
    }
}

// ----------------------------------------------------------------------------
// QKV kernel. z=0: Q -> packed fp16 pre-scaled. z=1: K -> Khaug. z=2: V -> Vhaug.
// ----------------------------------------------------------------------------
__global__ __launch_bounds__(256, 2)
void qkv_kernel(const uint32_t* __restrict__ Ah,
                const uint32_t* __restrict__ Wqh, const uint32_t* __restrict__ Wkh,
                const uint32_t* __restrict__ Wvh,
                const float* __restrict__ bq, const float* __restrict__ bk,
                const float* __restrict__ bv,
                uint32_t* __restrict__ Qh, uint32_t* __restrict__ Khaug,
                uint32_t* __restrict__ Vhaug)
{
    const uint32_t* Bw; const float* bias;
    if (blockIdx.z == 0)      { Bw = Wqh; bias = bq; }
    else if (blockIdx.z == 1) { Bw = Wkh; bias = bk; }
    else                      { Bw = Wvh; bias = bv; }

    float acc[2][8][4];
    gemm_accum_f16(Ah, Bw, D_, D_ / 2, acc);

    const int lane = threadIdx.x & 31;
    const int warp = threadIdx.x >> 5;
    const int gid  = lane >> 2;
    const int tig  = lane & 3;
    const int wm   = warp & 3;
    const int wn   = warp >> 2;
    const int rowBase = blockIdx.y * 128;
    const int colBase = blockIdx.x * 128;

    if (blockIdx.z == 0) {
        const float scale = 0.17677669529663687f;
#pragma unroll
        for (int mt = 0; mt < 2; mt++) {
            const int row0 = rowBase + wm * 32 + mt * 16 + gid;
            const int row1 = row0 + 8;
#pragma unroll
            for (int nt = 0; nt < 8; nt++) {
                const int col = colBase + wn * 64 + nt * 8 + 2 * tig;
                float2 bb = *reinterpret_cast<const float2*>(&bias[col]);
                Qh[(size_t)row0 * (D_ / 2) + (col >> 1)] =
                    packh2((acc[mt][nt][0] + bb.x) * scale,
                           (acc[mt][nt][1] + bb.y) * scale);
                Qh[(size_t)row1 * (D_ / 2) + (col >> 1)] =
                    packh2((acc[mt][nt][2] + bb.x) * scale,
                           (acc[mt][nt][3] + bb.y) * scale);
            }
        }
    } else if (blockIdx.z == 1) {
#pragma unroll
        for (int mt = 0; mt < 2; mt++) {
            const int row0 = rowBase + wm * 32 + mt * 16 + gid;
            const int b    = row0 >> 10;
            const int n0   = row0 & 1023;
            const int kt   = n0 >> 7;
            const int key0 = n0 & 127;
            const int key1 = key0 + 8;
#pragma unroll
            for (int nt = 0; nt < 8; nt++) {
                const int col = colBase + wn * 64 + nt * 8 + 2 * tig;
                const int h   = col >> 5;
                const int kp  = (col & 31) >> 1;
                float2 bb = *reinterpret_cast<const float2*>(&bias[col]);
                const size_t base = (size_t)((b * 8 + h) * 8 + kt) * KT_U32;
                Khaug[base + (size_t)kp * 136 + key0] =
                    packh2(acc[mt][nt][0] + bb.x, acc[mt][nt][1] + bb.y);
                Khaug[base + (size_t)kp * 136 + key1] =
                    packh2(acc[mt][nt][2] + bb.x, acc[mt][nt][3] + bb.y);
            }
        }
    } else {
        __half* Vh = reinterpret_cast<__half*>(Vhaug);
#pragma unroll
        for (int mt = 0; mt < 2; mt++) {
            const int row0 = rowBase + wm * 32 + mt * 16 + gid;
            const int b    = row0 >> 10;
            const int n0   = row0 & 1023;
            const int kt   = n0 >> 7;
            const int key0 = n0 & 127;
            const int key1 = key0 + 8;
#pragma unroll
            for (int nt = 0; nt < 8; nt++) {
                const int col = colBase + wn * 64 + nt * 8 + 2 * tig;
                const int h   = col >> 5;
                const int dk0 = col & 31;
                float2 bb = *reinterpret_cast<const float2*>(&bias[col]);
                const size_t hb = (size_t)((b * 8 + h) * 8 + kt) * (VT_U32 * 2);
#pragma unroll
                for (int e = 0; e < 4; e++) {
                    const int dk  = dk0 + (e & 1);
                    const int key = (e < 2) ? key0 : key1;
                    const float v = acc[mt][nt][e] + ((e & 1) ? bb.y : bb.x);
                    Vh[hb + (size_t)((key >> 1) * 40 + dk) * 2 + (key & 1)] =
                        __float2half_rn(v);
                }
            }
        }
    }
}

// ff1 (fp16): H = relu(Y @ W1 + b1), output packed fp16 only.
__global__ __launch_bounds__(256, 2)
void ff1_kernel(const uint32_t* __restrict__ Ah, const uint32_t* __restrict__ Bw,
                const float* __restrict__ bias, uint32_t* __restrict__ Ch)
{
    float acc[2][8][4];
    gemm_accum_f16(Ah, Bw, FF_, D_ / 2, acc);

    const int lane = threadIdx.x & 31;
    const int warp = threadIdx.x >> 5;
    const int gid  = lane >> 2;
    const int tig  = lane & 3;
    const int wm   = warp & 3;
    const int wn   = warp >> 2;
    const int rowBase = blockIdx.y * 128;
    const int colBase = blockIdx.x * 128;

#pragma unroll
    for (int mt = 0; mt < 2; mt++) {
        const int row0 = rowBase + wm * 32 + mt * 16 + gid;
        const int row1 = row0 + 8;
#pragma unroll
        for (int nt = 0; nt < 8; nt++) {
            const int col = colBase + wn * 64 + nt * 8 + 2 * tig;
            float2 bb = *reinterpret_cast<const float2*>(&bias[col]);
            float v0 = fmaxf(acc[mt][nt][0] + bb.x, 0.0f);
            float v1 = fmaxf(acc[mt][nt][1] + bb.y, 0.0f);
            float v2 = fmaxf(acc[mt][nt][2] + bb.x, 0.0f);
            float v3 = fmaxf(acc[mt][nt][3] + bb.y, 0.0f);
            Ch[(size_t)row0 * (FF_ / 2) + (col >> 1)] = packh2(v0, v1);
            Ch[(size_t)row1 * (FF_ / 2) + (col >> 1)] = packh2(v2, v3);
        }
    }
}

// ----------------------------------------------------------------------------
// Fused ff2 + residual + LayerNorm. fp16 residual input; fp16 out (+fp32 on
// the last layer only).
// ----------------------------------------------------------------------------
constexpr int A2_TILE_U32 = 64 * 32;
constexpr int B2_TILE_U32 = 32 * 264;
constexpr int STAGE2_U32  = A2_TILE_U32 + B2_TILE_U32;          // 10496
constexpr int FF2_SMEM    = 3 * STAGE2_U32 * 4;                 // 125952

__global__ __launch_bounds__(256, 1)
void ff2_ln_kernel(const uint32_t* __restrict__ Hbh,
                   const uint32_t* __restrict__ W2h,
                   const float* __restrict__ b2,
                   const uint32_t* __restrict__ Yh,   // fp16 residual (post-LN1)
                   const float* __restrict__ g,
                   const float* __restrict__ be,
                   float* __restrict__ outF,          // fp32 out (nullptr unless last)
                   uint32_t* __restrict__ outh)
{
    extern __shared__ uint32_t sm[];

    const int tid  = threadIdx.x;
    const int lane = tid & 31;
    const int warp = tid >> 5;
    const int gid  = lane >> 2;
    const int tig  = lane & 3;
    const int wm   = warp & 1;
    const int wn   = warp >> 1;

    const int rowBase = blockIdx.x * 64;
    constexpr int KP = FF_ / 2;

    int aR[2], aS[2], aC4[2];
#pragma unroll
    for (int i = 0; i < 2; i++) {
        int idx = tid + i * 256;
        int r  = idx >> 3;
        int c4 = (idx & 7) << 2;
        aR[i] = r; aS[i] = r * 32 + (c4 ^ ((r & 7) << 2)); aC4[i] = c4;
    }
    int bR[8], bS[8], bC4[8];
#pragma unroll
    for (int i = 0; i < 8; i++) {
        int idx = tid + i * 256;
        int rb  = idx >> 6;
        int cb4 = (idx & 63) << 2;
        bR[i] = rb; bS[i] = rb * 264 + cb4; bC4[i] = cb4;
    }

    auto issue = [&](int t, int buf) {
        const int k0 = t * 32;
        uint32_t* As = sm + buf * STAGE2_U32;
        uint32_t* Bs = As + A2_TILE_U32;
#pragma unroll
        for (int i = 0; i < 2; i++)
            cp16(smem_u32(&As[aS[i]]),
                 &Hbh[(size_t)(rowBase + aR[i]) * KP + k0 + aC4[i]]);
#pragma unroll
        for (int i = 0; i < 8; i++)
            cp16(smem_u32(&Bs[bS[i]]),
                 &W2h[(size_t)(k0 + bR[i]) * D_ + bC4[i]]);
        cp_commit();
    };

    float acc[2][8][4];
#pragma unroll
    for (int mt = 0; mt < 2; mt++)
#pragma unroll
        for (int nt = 0; nt < 8; nt++)
#pragma unroll
            for (int j = 0; j < 4; j++) acc[mt][nt][j] = 0.0f;

    const int T = KP >> 5;                 // 16
    issue(0, 0);
    issue(1, 1);

    int buf = 0;
    for (int t = 0; t < T; t++) {
        if (t + 1 < T) cp_wait<1>(); else cp_wait<0>();
        __syncthreads();

        const uint32_t* Ab = sm + buf * STAGE2_U32;
        const uint32_t* Bb = Ab + A2_TILE_U32;

#pragma unroll
        for (int kk = 0; kk < 32; kk += 8) {
            uint32_t a[2][4];
#pragma unroll
            for (int mt = 0; mt < 2; mt++) {
                const int m  = wm * 32 + mt * 16 + gid;
                const int sw = (m & 7) << 2;
                const int b0 = m * 32;
                const int b1 = b0 + 8 * 32;
                a[mt][0] = Ab[b0 + (kk ^ sw) + tig];
                a[mt][1] = Ab[b1 + (kk ^ sw) + tig];
                a[mt][2] = Ab[b0 + ((kk + 4) ^ sw) + tig];
                a[mt][3] = Ab[b1 + ((kk + 4) ^ sw) + tig];
            }
            uint32_t b[8][2];
#pragma unroll
            for (int nt = 0; nt < 8; nt++) {
                const int n = wn * 64 + nt * 8 + gid;
                b[nt][0] = Bb[(kk + tig) * 264 + n];
                b[nt][1] = Bb[(kk + tig + 4) * 264 + n];
            }
#pragma unroll
            for (int mt = 0; mt < 2; mt++)
#pragma unroll
                for (int nt = 0; nt < 8; nt++)
                    mma_f16(acc[mt][nt], a[mt], b[nt]);
        }

        if (t + 2 < T) {
            int nbuf = buf + 2; if (nbuf >= 3) nbuf -= 3;
            issue(t + 2, nbuf);
        }
        if (++buf == 3) buf = 0;
    }

    __syncthreads();
    float* red = reinterpret_cast<float*>(sm);

#pragma unroll
    for (int mt = 0; mt < 2; mt++) {
        const int rloc0 = wm * 32 + mt * 16 + gid;
        const int rloc1 = rloc0 + 8;
        float s0 = 0.0f, q0 = 0.0f, s1 = 0.0f, q1 = 0.0f;
#pragma unroll
        for (int nt = 0; nt < 8; nt++) {
            const int col = wn * 64 + nt * 8 + 2 * tig;
            float2 bb = *reinterpret_cast<const float2*>(&b2[col]);
            float2 x0 = unpackh2(Yh[(size_t)(rowBase + rloc0) * (D_ / 2) + (col >> 1)]);
            float2 x1 = unpackh2(Yh[(size_t)(rowBase + rloc1) * (D_ / 2) + (col >> 1)]);
            float v0 = acc[mt][nt][0] + bb.x + x0.x;
            float v1 = acc[mt][nt][1] + bb.y + x0.y;
            float v2 = acc[mt][nt][2] + bb.x + x1.x;
            float v3 = acc[mt][nt][3] + bb.y + x1.y;
            acc[mt][nt][0] = v0; acc[mt][nt][1] = v1;
            acc[mt][nt][2] = v2; acc[mt][nt][3] = v3;
            s0 += v0 + v1; q0 = fmaf(v0, v0, fmaf(v1, v1, q0));
            s1 += v2 + v3; q1 = fmaf(v2, v2, fmaf(v3, v3, q1));
        }
        s0 += __shfl_xor_sync(0xffffffffu, s0, 1);
        s0 += __shfl_xor_sync(0xffffffffu, s0, 2);
        q0 += __shfl_xor_sync(0xffffffffu, q0, 1);
        q0 += __shfl_xor_sync(0xffffffffu, q0, 2);
        s1 += __shfl_xor_sync(0xffffffffu, s1, 1);
        s1 += __shfl_xor_sync(0xffffffffu, s1, 2);
        q1 += __shfl_xor_sync(0xffffffffu, q1, 1);
        q1 += __shfl_xor_sync(0xffffffffu, q1, 2);
        if (tig == 0) {
            red[rloc0 * 8 + wn * 2 + 0] = s0;
            red[rloc0 * 8 + wn * 2 + 1] = q0;
            red[rloc1 * 8 + wn * 2 + 0] = s1;
            red[rloc1 * 8 + wn * 2 + 1] = q1;
        }
    }
    __syncthreads();

#pragma unroll
    for (int mt = 0; mt < 2; mt++) {
#pragma unroll
        for (int rr = 0; rr < 2; rr++) {
            const int rloc = wm * 32 + mt * 16 + gid + rr * 8;
            const float* rp = &red[rloc * 8];
            const float sum = rp[0] + rp[2] + rp[4] + rp[6];
            const float sq  = rp[1] + rp[3] + rp[5] + rp[7];
            const float mean = sum * (1.0f / 256.0f);
            const float var  = sq * (1.0f / 256.0f) - mean * mean;
            const float rs   = rsqrtf(var + 1e-5f);
            const int row = rowBase + rloc;
#pragma unroll
            for (int nt = 0; nt < 8; nt++) {
                const int col = wn * 64 + nt * 8 + 2 * tig;
                float2 gv = *reinterpret_cast<const float2*>(&g[col]);
                float2 ev = *reinterpret_cast<const float2*>(&be[col]);
                const float a0 = acc[mt][nt][rr * 2 + 0];
                const float a1 = acc[mt][nt][rr * 2 + 1];
                const float o0 = (a0 - mean) * rs * gv.x + ev.x;
                const float o1 = (a1 - mean) * rs * gv.y + ev.y;
                if (outF)
                    *reinterpret_cast<float2*>(&outF[(size_t)row * D_ + col]) =
                        make_float2(o0, o1);
                outh[(size_t)row * (D_ / 2) + (col >> 1)] = packh2(o0, o1);
            }
        }
    }
}

// ----------------------------------------------------------------------------
// ONE fused prep kernel (unchanged segments).
// ----------------------------------------------------------------------------
constexpr int XN  = ROWS * D_ / 2;
constexpr int WN  = L_ * (D_ / 2) * D_;
constexpr int W1N = L_ * (D_ / 2) * FF_;
constexpr int W2N = L_ * (FF_ / 2) * D_;
constexpr int CN  = 512 * (8 * 136);
constexpr int PREP_TOTAL = XN + 3 * WN + W1N + W2N + CN;
constexpr int PREP_GRID  = PREP_TOTAL / 256;

__global__ __launch_bounds__(256)
void prep_kernel(const float* __restrict__ x,
                 const float* __restrict__ Wq, const float* __restrict__ Wk,
                 const float* __restrict__ Wv, const float* __restrict__ W1,
                 const float* __restrict__ W2, const float* __restrict__ coords,
                 uint32_t* __restrict__ Xh,
                 uint32_t* __restrict__ Wqh, uint32_t* __restrict__ Wkh,
                 uint32_t* __restrict__ Wvh, uint32_t* __restrict__ W1h,
                 uint32_t* __restrict__ W2h, uint32_t* __restrict__ Khaug)
{
    int idx = blockIdx.x * 256 + threadIdx.x;
    if (idx < XN) {
        float2 v = reinterpret_cast<const float2*>(x)[idx];
        Xh[idx] = packh2(v.x, v.y);
        return;
    }
    idx -= XN;
    if (idx < 3 * WN) {
        const float* W; uint32_t* O;
        if (idx < WN)            { W = Wq; O = Wqh; }
        else if (idx < 2 * WN)   { W = Wk; O = Wkh; idx -= WN; }
        else                     { W = Wv; O = Wvh; idx -= 2 * WN; }
        const int kp = idx >> 8;
        const int n  = idx & 255;
        O[idx] = packh2(W[(size_t)(2 * kp) * D_ + n],
                        W[(size_t)(2 * kp + 1) * D_ + n]);
        return;
    }
    idx -= 3 * WN;
    if (idx < W1N) {
        const int kp = idx >> 10;
        const int n  = idx & 1023;
        W1h[idx] = packh2(W1[(size_t)(2 * kp) * FF_ + n],
                          W1[(size_t)(2 * kp + 1) * FF_ + n]);
        return;
    }
    idx -= W1N;
    if (idx < W2N) {
        const int kp = idx >> 8;
        const int n  = idx & 255;
        W2h[idx] = packh2(W2[(size_t)(2 * kp) * D_ + n],
                          W2[(size_t)(2 * kp + 1) * D_ + n]);
        return;
    }
    idx -= W2N;
    {
        const int t   = idx / 1088;
        const int rem = idx - t * 1088;
        const int r   = rem / 136;
        const int key = rem - r * 136;
        const int kt  = t & 7;
        const int b   = t >> 6;
        uint32_t v = 0;
        if (key < 128) {
            const float* c = &coords[(size_t)(b * N_ + kt * 128 + key) * 3];
            if (r == 0)      v = packh2(c[0], c[1]);
            else if (r == 1) v = packh2(c[2], 0.0f);
        }
        Khaug[(size_t)t * KT_U32 + (16 + r) * 136 + key] = v;
    }
}

// ----------------------------------------------------------------------------
// fp16 MMA flash attention. 2 CTAs/SM. (unchanged from R16)
// ----------------------------------------------------------------------------
constexpr int TILE_U32A = KT_U32 + VT_U32;          // 5824
constexpr int ATTN_SMEM = 2 * TILE_U32A * 4;        // 46592

__global__ __launch_bounds__(256, 2)
void attn_f16_kernel(const uint32_t* __restrict__ Qh,
                     const uint32_t* __restrict__ Khaug,
                     const uint32_t* __restrict__ Vhaug,
                     const float* __restrict__ coords,
                     const float* __restrict__ alpha,
                     int layer,
                     uint32_t* __restrict__ Outh)
{
    extern __shared__ uint32_t smu[];

    const int tid  = threadIdx.x;
    const int lane = tid & 31;
    const int w    = tid >> 5;
    const int gid  = lane >> 2;
    const int tig  = lane & 3;

    const int bh = blockIdx.x;
    const int b  = bh >> 3;
    const int h  = bh & 7;
    const int q0 = blockIdx.y * 128;

    const float alphav = alpha[layer];

    uint32_t qf[3][4];
    {
        const int row0 = b * N_ + q0 + w * 16 + gid;
#pragma unroll
        for (int ks = 0; ks < 2; ks++) {
#pragma unroll
            for (int r = 0; r < 4; r++) {
                const int row = row0 + (r & 1) * 8;
                const int kp  = h * 16 + ks * 8 + tig + ((r >> 1) << 2);
                qf[ks][r] = Qh[(size_t)row * (D_ / 2) + kp];
            }
        }
#pragma unroll
        for (int r = 0; r < 4; r++) {
            const int row = row0 + (r & 1) * 8;
            uint32_t v = 0;
            if ((r >> 1) == 0) {
                const float* c = &coords[(size_t)row * 3];
                if (tig == 0)      v = packh2(alphav * c[0], alphav * c[1]);
                else if (tig == 1) v = packh2(alphav * c[2], 0.0f);
            }
            qf[2][r] = v;
        }
    }

    auto issue = [&](int t, int buf) {
        const uint32_t* srcK = Khaug + (size_t)(bh * 8 + t) * KT_U32;
        uint32_t* dst = smu + buf * TILE_U32A;
#pragma unroll
        for (int j = 0; j < 3; j++) {
            const int i16 = tid + j * 256;
            cp16(smem_u32(dst + i16 * 4), srcK + i16 * 4);
        }
        if (tid < 48)
            cp16(smem_u32(dst + (768 + tid) * 4), srcK + (768 + tid) * 4);
        const uint32_t* srcV = Vhaug + (size_t)(bh * 8 + t) * VT_U32;
        uint32_t* dstV = dst + KT_U32;
#pragma unroll
        for (int j = 0; j < 2; j++) {
            const int i16 = tid + j * 256;
            cp16(smem_u32(dstV + i16 * 4), srcV + i16 * 4);
        }
        if (tid < 128)
            cp16(smem_u32(dstV + (512 + tid) * 4), srcV + (512 + tid) * 4);
        cp_commit();
    };

    float O[4][4];
#pragma unroll
    for (int i = 0; i < 4; i++)
#pragma unroll
        for (int j = 0; j < 4; j++) O[i][j] = 0.0f;
    float m0 = -1e30f, m1 = -1e30f, l0 = 0.0f, l1 = 0.0f;

    issue(0, 0);

    for (int t = 0; t < 8; t++) {
        if (t < 7) { issue(t + 1, (t + 1) & 1); cp_wait<1>(); }
        else       { cp_wait<0>(); }
        __syncthreads();

        const uint32_t* Kb = smu + (t & 1) * TILE_U32A;
        const uint32_t* Vb = Kb + KT_U32;

        float s[16][4];
#pragma unroll
        for (int nt = 0; nt < 16; nt++)
#pragma unroll
            for (int j = 0; j < 4; j++) s[nt][j] = 0.0f;

#pragma unroll
        for (int ks = 0; ks < 3; ks++) {
#pragma unroll
            for (int nt = 0; nt < 16; nt++) {
                uint32_t bfr[2];
                const int key = nt * 8 + gid;
                bfr[0] = Kb[(ks * 8 + tig) * 136 + key];
                bfr[1] = Kb[(ks * 8 + 4 + tig) * 136 + key];
                mma_f16(s[nt], qf[ks], bfr);
            }
        }

        float mx0 = -1e30f, mx1 = -1e30f;
#pragma unroll
        for (int nt = 0; nt < 16; nt++) {
            mx0 = fmaxf(mx0, fmaxf(s[nt][0], s[nt][1]));
            mx1 = fmaxf(mx1, fmaxf(s[nt][2], s[nt][3]));
        }
        mx0 = fmaxf(mx0, __shfl_xor_sync(0xffffffffu, mx0, 1));
        mx0 = fmaxf(mx0, __shfl_xor_sync(0xffffffffu, mx0, 2));
        mx1 = fmaxf(mx1, __shfl_xor_sync(0xffffffffu, mx1, 1));
        mx1 = fmaxf(mx1, __shfl_xor_sync(0xffffffffu, mx1, 2));

        const float mn0 = fmaxf(m0, mx0);
        const float mn1 = fmaxf(m1, mx1);
        const float c0  = __expf(m0 - mn0);
        const float c1  = __expf(m1 - mn1);
        m0 = mn0; m1 = mn1;

        float rs0 = 0.0f, rs1 = 0.0f;
#pragma unroll
        for (int nt = 0; nt < 16; nt++) {
            s[nt][0] = __expf(s[nt][0] - mn0);
            s[nt][1] = __expf(s[nt][1] - mn0);
            s[nt][2] = __expf(s[nt][2] - mn1);
            s[nt][3] = __expf(s[nt][3] - mn1);
            rs0 += s[nt][0] + s[nt][1];
            rs1 += s[nt][2] + s[nt][3];
        }
        rs0 += __shfl_xor_sync(0xffffffffu, rs0, 1);
        rs0 += __shfl_xor_sync(0xffffffffu, rs0, 2);
        rs1 += __shfl_xor_sync(0xffffffffu, rs1, 1);
        rs1 += __shfl_xor_sync(0xffffffffu, rs1, 2);
        l0 = l0 * c0 + rs0;
        l1 = l1 * c1 + rs1;

#pragma unroll
        for (int nt2 = 0; nt2 < 4; nt2++) {
            O[nt2][0] *= c0; O[nt2][1] *= c0;
            O[nt2][2] *= c1; O[nt2][3] *= c1;
        }

#pragma unroll
        for (int ks = 0; ks < 8; ks++) {
            uint32_t a[4];
            a[0] = packh2(s[2 * ks][0],     s[2 * ks][1]);
            a[1] = packh2(s[2 * ks][2],     s[2 * ks][3]);
            a[2] = packh2(s[2 * ks + 1][0], s[2 * ks + 1][1]);
            a[3] = packh2(s[2 * ks + 1][2], s[2 * ks + 1][3]);
#pragma unroll
            for (int nt2 = 0; nt2 < 4; nt2++) {
                uint32_t bfr[2];
                const int dk = nt2 * 8 + gid;
                bfr[0] = Vb[(ks * 8 + tig) * 40 + dk];
                bfr[1] = Vb[(ks * 8 + 4 + tig) * 40 + dk];
                mma_f16(O[nt2], a, bfr);
            }
        }
        __syncthreads();
    }

    const float inv0 = 1.0f / l0;
    const float inv1 = 1.0f / l1;
    const int row0 = b * N_ + q0 + w * 16 + gid;
    const int row1 = row0 + 8;
#pragma unroll
    for (int nt2 = 0; nt2 < 4; nt2++) {
        const int kp = h * 16 + nt2 * 4 + tig;
        Outh[(size_t)row0 * (D_ / 2) + kp] =
            packh2(O[nt2][0] * inv0, O[nt2][1] * inv0);
        Outh[(size_t)row1 * (D_ / 2) + kp] =
            packh2(O[nt2][2] * inv1, O[nt2][3] * inv1);
    }
}

// ----------------------------------------------------------------------------
// Fused residual add + LayerNorm (LN1). All-fp16 I/O.
// ----------------------------------------------------------------------------
__global__ __launch_bounds__(256, 6)
void add_ln_kernel(const uint32_t* __restrict__ xh,
                   const uint32_t* __restrict__ deltah,
                   const float* __restrict__ g,
                   const float* __restrict__ be,
                   uint32_t* __restrict__ outh)
{
    const int warp = threadIdx.x >> 5;
    const int lane = threadIdx.x & 31;
    const int rowA = blockIdx.x * 16 + warp * 2;
    const int rowB = rowA + 1;
    const int col0 = lane * 8;

    uint4 xha = *reinterpret_cast<const uint4*>(&xh[(size_t)rowA * (D_ / 2) + lane * 4]);
    uint4 xhb = *reinterpret_cast<const uint4*>(&xh[(size_t)rowB * (D_ / 2) + lane * 4]);
    uint4 dha = *reinterpret_cast<const uint4*>(&deltah[(size_t)rowA * (D_ / 2) + lane * 4]);
    uint4 dhb = *reinterpret_cast<const uint4*>(&deltah[(size_t)rowB * (D_ / 2) + lane * 4]);

    float2 x0 = unpackh2(xha.x), x1 = unpackh2(xha.y),
           x2 = unpackh2(xha.z), x3 = unpackh2(xha.w);
    float2 y0 = unpackh2(xhb.x), y1 = unpackh2(xhb.y),
           y2 = unpackh2(xhb.z), y3 = unpackh2(xhb.w);
    float2 d0 = unpackh2(dha.x), d1 = unpackh2(dha.y),
           d2 = unpackh2(dha.z), d3 = unpackh2(dha.w);
    float2 e0 = unpackh2(dhb.x), e1 = unpackh2(dhb.y),
           e2 = unpackh2(dhb.z), e3 = unpackh2(dhb.w);

    float ra[8], rb[8];
    ra[0] = x0.x + d0.x; ra[1] = x0.y + d0.y; ra[2] = x1.x + d1.x; ra[3] = x1.y + d1.y;
    ra[4] = x2.x + d2.x; ra[5] = x2.y + d2.y; ra[6] = x3.x + d3.x; ra[7] = x3.y + d3.y;
    rb[0] = y0.x + e0.x; rb[1] = y0.y + e0.y; rb[2] = y1.x + e1.x; rb[3] = y1.y + e1.y;
    rb[4] = y2.x + e2.x; rb[5] = y2.y + e2.y; rb[6] = y3.x + e3.x; rb[7] = y3.y + e3.y;

    float sa = 0.0f, sb = 0.0f;
#pragma unroll
    for (int j = 0; j < 8; j++) { sa += ra[j]; sb += rb[j]; }
#pragma unroll
    for (int off = 16; off > 0; off >>= 1) {
        sa += __shfl_xor_sync(0xffffffffu, sa, off);
        sb += __shfl_xor_sync(0xffffffffu, sb, off);
    }
    const float meanA = sa * (1.0f / 256.0f);
    const float meanB = sb * (1.0f / 256.0f);

    float va = 0.0f, vb = 0.0f;
#pragma unroll
    for (int j = 0; j < 8; j++) {
        float ta = ra[j] - meanA; va = fmaf(ta, ta, va);
        float tb = rb[j] - meanB; vb = fmaf(tb, tb, vb);
    }
#pragma unroll
    for (int off = 16; off > 0; off >>= 1) {
        va += __shfl_xor_sync(0xffffffffu, va, off);
        vb += __shfl_xor_sync(0xffffffffu, vb, off);
    }
    const float rsA = rsqrtf(va * (1.0f / 256.0f) + 1e-5f);
    const float rsB = rsqrtf(vb * (1.0f / 256.0f) + 1e-5f);

    const float4* gg = reinterpret_cast<const float4*>(&g[col0]);
    const float4* bb = reinterpret_cast<const float4*>(&be[col0]);
    float4 g0 = gg[0], g1 = gg[1], f0 = bb[0], f1 = bb[1];
    const float gv[8] = {g0.x, g0.y, g0.z, g0.w, g1.x, g1.y, g1.z, g1.w};
    const float ev[8] = {f0.x, f0.y, f0.z, f0.w, f1.x, f1.y, f1.z, f1.w};

    float oa[8], ob[8];
#pragma unroll
    for (int j = 0; j < 8; j++) {
        oa[j] = (ra[j] - meanA) * rsA * gv[j] + ev[j];
        ob[j] = (rb[j] - meanB) * rsB * gv[j] + ev[j];
    }

    uint4 pa, pb;
    pa.x = packh2(oa[0], oa[1]); pa.y = packh2(oa[2], oa[3]);
    pa.z = packh2(oa[4], oa[5]); pa.w = packh2(oa[6], oa[7]);
    pb.x = packh2(ob[0], ob[1]); pb.y = packh2(ob[2], ob[3]);
    pb.z = packh2(ob[4], ob[5]); pb.w = packh2(ob[6], ob[7]);
    *reinterpret_cast<uint4*>(&outh[(size_t)rowA * (D_ / 2) + lane * 4]) = pa;
    *reinterpret_cast<uint4*>(&outh[(size_t)rowB * (D_ / 2) + lane * 4]) = pb;
}

// ----------------------------------------------------------------------------
// Host driver
// ----------------------------------------------------------------------------
extern "C" void kernel_launch(void* const* d_in, const int* in_sizes, int n_in,
                              void* d_out, int out_size)
{
    const float* x      = (const float*)d_in[0];
    const float* coords = (const float*)d_in[1];
    const float* Wq     = (const float*)d_in[2];
    const float* bq     = (const float*)d_in[3];
    const float* Wk     = (const float*)d_in[4];
    const float* bk     = (const float*)d_in[5];
    const float* Wv     = (const float*)d_in[6];
    const float* bv     = (const float*)d_in[7];
    const float* alpha  = (const float*)d_in[8];
    const float* W1     = (const float*)d_in[9];
    const float* b1     = (const float*)d_in[10];
    const float* W2     = (const float*)d_in[11];
    const float* b2     = (const float*)d_in[12];
    const float* g1     = (const float*)d_in[13];
    const float* be1    = (const float*)d_in[14];
    const float* g2     = (const float*)d_in[15];
    const float* be2    = (const float*)d_in[16];
    float* out = (float*)d_out;

    uint32_t *Xhp, *Yhp, *Hbhp, *Qhp, *ATThp, *Wqhp, *Wkhp, *Wvhp, *W1hp, *W2hp, *Khp, *Vhp;
    cudaGetSymbolAddress((void**)&Xhp,   g_Xh);
    cudaGetSymbolAddress((void**)&Yhp,   g_Yh);
    cudaGetSymbolAddress((void**)&Hbhp,  g_Hbh);
    cudaGetSymbolAddress((void**)&Qhp,   g_Qh);
    cudaGetSymbolAddress((void**)&ATThp, g_ATTh);
    cudaGetSymbolAddress((void**)&Wqhp,  g_Wqh);
    cudaGetSymbolAddress((void**)&Wkhp,  g_Wkh);
    cudaGetSymbolAddress((void**)&Wvhp,  g_Wvh);
    cudaGetSymbolAddress((void**)&W1hp,  g_W1h);
    cudaGetSymbolAddress((void**)&W2hp,  g_W2h);
    cudaGetSymbolAddress((void**)&Khp,   g_Khaug);
    cudaGetSymbolAddress((void**)&Vhp,   g_Vhaug);

    cudaFuncSetAttribute(qkv_kernel,
                         cudaFuncAttributeMaxDynamicSharedMemorySize, GEMM_SMEM);
    cudaFuncSetAttribute(ff1_kernel,
                         cudaFuncAttributeMaxDynamicSharedMemorySize, GEMM_SMEM);
    cudaFuncSetAttribute(ff2_ln_kernel,
                         cudaFuncAttributeMaxDynamicSharedMemorySize, FF2_SMEM);
    cudaFuncSetAttribute(attn_f16_kernel,
                         cudaFuncAttributeMaxDynamicSharedMemorySize, ATTN_SMEM);

    const dim3 gQKV(D_ / 128, ROWS / 128, 3);
    const dim3 gFF1(FF_ / 128, ROWS / 128);
    const dim3 gAttn(B_ * H_, N_ / 128);

    prep_kernel<<<PREP_GRID, 256>>>(x, Wq, Wk, Wv, W1, W2, coords,
                                    Xhp, Wqhp, Wkhp, Wvhp, W1hp, W2hp, Khp);

    // Residual stream lives in g_Xh (fp16). Post-LN1 stream in g_Yh.
    for (int i = 0; i < L_; i++) {
        qkv_kernel<<<gQKV, 256, GEMM_SMEM>>>(
            Xhp,
            Wqhp + (size_t)i * (D_ / 2) * D_,
            Wkhp + (size_t)i * (D_ / 2) * D_,
            Wvhp + (size_t)i * (D_ / 2) * D_,
            bq + i * D_, bk + i * D_, bv + i * D_,
            Qhp, Khp, Vhp);

        attn_f16_kernel<<<gAttn, 256, ATTN_SMEM>>>(Qhp, Khp, Vhp, coords,
                                                   alpha, i, ATThp);

        // Yh = LN1(Xh + ATTh)
        add_ln_kernel<<<ROWS / 16, 256>>>(Xhp, ATThp, g1 + i * D_, be1 + i * D_,
                                          Yhp);

        ff1_kernel<<<gFF1, 256, GEMM_SMEM>>>(
            Yhp, W1hp + (size_t)i * (D_ / 2) * FF_, b1 + i * FF_, Hbhp);

        // Xh = LN2(Yh + ff2) ; fp32 out only on the last layer
        float* outF = (i == L_ - 1) ? out : nullptr;
        ff2_ln_kernel<<<ROWS / 64, 256, FF2_SMEM>>>(
            Hbhp, W2hp + (size_t)i * (FF_ / 2) * D_, b2 + i * D_,
            Yhp, g2 + i * D_, be2 + i * D_, outF, Xhp);
    }
}